// round 4
// baseline (speedup 1.0000x reference)
#include <cuda_runtime.h>
#include <cuda_bf16.h>
#include <cstdint>
#include <cstddef>

typedef unsigned long long ull;

__device__ __forceinline__ void ffma2(ull& d, ull a, ull b){
    asm("fma.rn.f32x2 %0, %1, %2, %0;" : "+l"(d) : "l"(a), "l"(b));
}
__device__ __forceinline__ ull pk2(float x, float y){
    ull r; asm("mov.b64 %0, {%1, %2};" : "=l"(r) : "f"(x), "f"(y)); return r;
}
__device__ __forceinline__ float2 upk(ull a){
    float2 r; asm("mov.b64 {%0, %1}, %2;" : "=f"(r.x), "=f"(r.y) : "l"(a)); return r;
}

// ---------------- fixed shapes ----------------
#define BB 4
#define HF 128
#define WF 128
#define CF 256
#define HC 64
#define WC 64
#define CC 512
#define EE 64
#define FF 256
#define NP 384
#define NCOARSE (BB*HC*WC)   // 16384
#define NFINE   (BB*HF*WF)   // 65536

// ---------------- scratch ----------------
__device__ float g_coarse_n[(size_t)NCOARSE*CC];
__device__ float g_gate[NCOARSE];
__device__ float g_proj[(size_t)NCOARSE*NP];   // fused k|qc|v
__device__ float g_query[(size_t)NFINE*EE];
__device__ float g_mean[NFINE];
__device__ float g_rstd[NFINE];
__device__ float g_wfold[(size_t)CF*EE];
__device__ float g_dvec[EE];
__device__ float g_cvec[EE];
__device__ float g_wcat[(size_t)CC*NP];
__device__ float g_bcat[NP];

// ================= kernel 1: LN(coarse) + gate =================
__global__ void __launch_bounds__(128) ln_coarse_gate(
    const float* __restrict__ x, const float* __restrict__ g, const float* __restrict__ b,
    const float* __restrict__ wg, const float* __restrict__ bg)
{
    int row = blockIdx.x; int t = threadIdx.x;
    const float4* xr = (const float4*)(x + (size_t)row*CC);
    float4 v = xr[t];
    float s  = v.x+v.y+v.z+v.w;
    float sq = v.x*v.x+v.y*v.y+v.z*v.z+v.w*v.w;
    #pragma unroll
    for (int o=16;o;o>>=1){ s += __shfl_xor_sync(0xffffffffu,s,o); sq += __shfl_xor_sync(0xffffffffu,sq,o); }
    __shared__ float red[8];
    int wid = t>>5, l = t&31;
    if (l==0){ red[wid]=s; red[4+wid]=sq; }
    __syncthreads();
    s  = red[0]+red[1]+red[2]+red[3];
    sq = red[4]+red[5]+red[6]+red[7];
    float mean = s*(1.f/512.f);
    float var  = sq*(1.f/512.f) - mean*mean;
    float rstd = rsqrtf(var + 1e-3f);
    float4 gv = ((const float4*)g)[t];
    float4 bv = ((const float4*)b)[t];
    float4 o;
    o.x = (v.x-mean)*rstd*gv.x + bv.x;
    o.y = (v.y-mean)*rstd*gv.y + bv.y;
    o.z = (v.z-mean)*rstd*gv.z + bv.z;
    o.w = (v.w-mean)*rstd*gv.w + bv.w;
    ((float4*)(g_coarse_n + (size_t)row*CC))[t] = o;
    float4 wv = ((const float4*)wg)[t];
    float gd = o.x*wv.x + o.y*wv.y + o.z*wv.z + o.w*wv.w;
    #pragma unroll
    for (int oo=16;oo;oo>>=1) gd += __shfl_xor_sync(0xffffffffu,gd,oo);
    __syncthreads();
    if (l==0) red[wid]=gd;
    __syncthreads();
    if (t==0){
        float tot = red[0]+red[1]+red[2]+red[3] + bg[0];
        g_gate[row] = 1.f/(1.f+__expf(-tot));
    }
}

// ================= kernel 2: fine LN stats =================
__global__ void __launch_bounds__(256) fine_stats(const float* __restrict__ x)
{
    int w = threadIdx.x>>5, l = threadIdx.x&31;
    int row = blockIdx.x*8 + w;
    const float4* xr = (const float4*)(x + (size_t)row*CF);
    float4 a = xr[l], c = xr[l+32];
    float s  = a.x+a.y+a.z+a.w + c.x+c.y+c.z+c.w;
    float sq = a.x*a.x+a.y*a.y+a.z*a.z+a.w*a.w + c.x*c.x+c.y*c.y+c.z*c.z+c.w*c.w;
    #pragma unroll
    for (int o=16;o;o>>=1){ s += __shfl_xor_sync(0xffffffffu,s,o); sq += __shfl_xor_sync(0xffffffffu,sq,o); }
    if (l==0){
        float m = s*(1.f/256.f);
        g_mean[row] = m;
        g_rstd[row] = rsqrtf(sq*(1.f/256.f) - m*m + 1e-3f);
    }
}

// ================= pack weights =================
__global__ void __launch_bounds__(384) pack_w(
    const float* __restrict__ wk, const float* __restrict__ wqc, const float* __restrict__ wv,
    const float* __restrict__ bk, const float* __restrict__ bqc, const float* __restrict__ bv)
{
    int k = blockIdx.x; int n = threadIdx.x;
    float v;
    if (n < 64)       v = wk [k*64  + n];
    else if (n < 128) v = wqc[k*64  + (n-64)];
    else              v = wv [k*256 + (n-128)];
    g_wcat[(size_t)k*NP + n] = v;
    if (k == 0){
        float bvv = (n<64) ? bk[n] : (n<128) ? bqc[n-64] : bv[n-128];
        g_bcat[n] = bvv;
    }
}

// ================= fold LN(fine) params into w_qf: block per n, threads over k =================
__global__ void __launch_bounds__(256) fold_qf(
    const float* __restrict__ wqf, const float* __restrict__ bqf,
    const float* __restrict__ g, const float* __restrict__ bb)
{
    int n = blockIdx.x; int t = threadIdx.x;   // t = k in [0,256)
    float wv = wqf[t*EE + n];
    float wf = g[t]*wv;
    g_wfold[t*EE + n] = wf;
    float cv = bb[t]*wv;
    #pragma unroll
    for (int o=16;o;o>>=1){ wf += __shfl_xor_sync(0xffffffffu,wf,o); cv += __shfl_xor_sync(0xffffffffu,cv,o); }
    __shared__ float sd[8], sc[8];
    int wid = t>>5, l = t&31;
    if (l==0){ sd[wid]=wf; sc[wid]=cv; }
    __syncthreads();
    if (t==0){
        float dd=0.f, cc=0.f;
        #pragma unroll
        for (int i=0;i<8;i++){ dd+=sd[i]; cc+=sc[i]; }
        g_dvec[n]=dd; g_cvec[n]=cc + bqf[n];
    }
}

// ================= fused projection GEMM: proj = coarse_n @ wcat + bcat =================
// BM=128, BN=64, BK=32, 256 thr, double-buffered; grid (n-tiles fast, m slow) for L2 A-reuse
__global__ void __launch_bounds__(256,2) proj_gemm()
{
    __shared__ __align__(16) float As[2][32][128];
    __shared__ __align__(16) float Bs[2][32][64];
    int n0 = blockIdx.x*64, m0 = blockIdx.y*128;
    int t = threadIdx.x;
    int mA = t>>1, kq = (t&1)*16;
    int kB = t>>3, n8 = (t&7)*8;
    int ty = t>>4, tx = t&15;

    const float* Aload = g_coarse_n + (size_t)(m0+mA)*CC + kq;
    const float* Wload = g_wcat + (size_t)kB*NP + n0 + n8;

    ull acc[4][4];
    #pragma unroll
    for (int n=0;n<4;n++)
        #pragma unroll
        for (int mp=0;mp<4;mp++) acc[n][mp]=pk2(0.f,0.f);

    const int ITERS = CC/32;  // 16
    float4 ra0 = *(const float4*)(Aload);
    float4 ra1 = *(const float4*)(Aload+4);
    float4 ra2 = *(const float4*)(Aload+8);
    float4 ra3 = *(const float4*)(Aload+12);
    float4 rb0 = *(const float4*)(Wload);
    float4 rb1 = *(const float4*)(Wload+4);
    As[0][kq+ 0][mA]=ra0.x; As[0][kq+ 1][mA]=ra0.y; As[0][kq+ 2][mA]=ra0.z; As[0][kq+ 3][mA]=ra0.w;
    As[0][kq+ 4][mA]=ra1.x; As[0][kq+ 5][mA]=ra1.y; As[0][kq+ 6][mA]=ra1.z; As[0][kq+ 7][mA]=ra1.w;
    As[0][kq+ 8][mA]=ra2.x; As[0][kq+ 9][mA]=ra2.y; As[0][kq+10][mA]=ra2.z; As[0][kq+11][mA]=ra2.w;
    As[0][kq+12][mA]=ra3.x; As[0][kq+13][mA]=ra3.y; As[0][kq+14][mA]=ra3.z; As[0][kq+15][mA]=ra3.w;
    *(float4*)&Bs[0][kB][n8]   = rb0;
    *(float4*)&Bs[0][kB][n8+4] = rb1;
    __syncthreads();

    for (int it=0; it<ITERS; it++){
        int s = it&1;
        if (it+1<ITERS){
            const float* ap = Aload + (it+1)*32;
            ra0 = *(const float4*)(ap);
            ra1 = *(const float4*)(ap+4);
            ra2 = *(const float4*)(ap+8);
            ra3 = *(const float4*)(ap+12);
            const float* bp = Wload + (size_t)(it+1)*32*NP;
            rb0 = *(const float4*)(bp);
            rb1 = *(const float4*)(bp+4);
        }
        #pragma unroll
        for (int k=0;k<32;k++){
            ulonglong2 A01 = *(const ulonglong2*)&As[s][k][ty*8];
            ulonglong2 A23 = *(const ulonglong2*)&As[s][k][ty*8+4];
            float4 bf = *(const float4*)&Bs[s][k][tx*4];
            ull B0=pk2(bf.x,bf.x), B1=pk2(bf.y,bf.y), B2=pk2(bf.z,bf.z), B3=pk2(bf.w,bf.w);
            ffma2(acc[0][0],A01.x,B0); ffma2(acc[0][1],A01.y,B0); ffma2(acc[0][2],A23.x,B0); ffma2(acc[0][3],A23.y,B0);
            ffma2(acc[1][0],A01.x,B1); ffma2(acc[1][1],A01.y,B1); ffma2(acc[1][2],A23.x,B1); ffma2(acc[1][3],A23.y,B1);
            ffma2(acc[2][0],A01.x,B2); ffma2(acc[2][1],A01.y,B2); ffma2(acc[2][2],A23.x,B2); ffma2(acc[2][3],A23.y,B2);
            ffma2(acc[3][0],A01.x,B3); ffma2(acc[3][1],A01.y,B3); ffma2(acc[3][2],A23.x,B3); ffma2(acc[3][3],A23.y,B3);
        }
        if (it+1<ITERS){
            int d = s^1;
            As[d][kq+ 0][mA]=ra0.x; As[d][kq+ 1][mA]=ra0.y; As[d][kq+ 2][mA]=ra0.z; As[d][kq+ 3][mA]=ra0.w;
            As[d][kq+ 4][mA]=ra1.x; As[d][kq+ 5][mA]=ra1.y; As[d][kq+ 6][mA]=ra1.z; As[d][kq+ 7][mA]=ra1.w;
            As[d][kq+ 8][mA]=ra2.x; As[d][kq+ 9][mA]=ra2.y; As[d][kq+10][mA]=ra2.z; As[d][kq+11][mA]=ra2.w;
            As[d][kq+12][mA]=ra3.x; As[d][kq+13][mA]=ra3.y; As[d][kq+14][mA]=ra3.z; As[d][kq+15][mA]=ra3.w;
            *(float4*)&Bs[d][kB][n8]   = rb0;
            *(float4*)&Bs[d][kB][n8+4] = rb1;
        }
        __syncthreads();
    }

    float4 bb = *(const float4*)&g_bcat[n0 + tx*4];
    #pragma unroll
    for (int mp=0; mp<4; mp++){
        float2 c0=upk(acc[0][mp]), c1=upk(acc[1][mp]), c2=upk(acc[2][mp]), c3=upk(acc[3][mp]);
        int r0 = m0 + ty*8 + 2*mp;
        *(float4*)&g_proj[(size_t)r0*NP + n0 + tx*4] =
            make_float4(c0.x+bb.x, c1.x+bb.y, c2.x+bb.z, c3.x+bb.w);
        *(float4*)&g_proj[(size_t)(r0+1)*NP + n0 + tx*4] =
            make_float4(c0.y+bb.x, c1.y+bb.y, c2.y+bb.z, c3.y+bb.w);
    }
}

// ================= query GEMM with folded LN + gate blend =================
__global__ void __launch_bounds__(256,2) query_gemm(const float* __restrict__ fine)
{
    __shared__ __align__(16) float As[2][32][128];
    __shared__ __align__(16) float Bs[2][32][64];
    int m0 = blockIdx.x*128;
    int t = threadIdx.x;
    int mA = t>>1, kq = (t&1)*16;
    int kB = t>>3, n8 = (t&7)*8;
    int ty = t>>4, tx = t&15;

    const float* Aload = fine + (size_t)(m0+mA)*CF + kq;
    const float* Wload = g_wfold + (size_t)kB*EE + n8;

    ull acc[4][4];
    #pragma unroll
    for (int n=0;n<4;n++)
        #pragma unroll
        for (int mp=0;mp<4;mp++) acc[n][mp]=pk2(0.f,0.f);

    const int ITERS = CF/32;  // 8
    float4 ra0 = *(const float4*)(Aload);
    float4 ra1 = *(const float4*)(Aload+4);
    float4 ra2 = *(const float4*)(Aload+8);
    float4 ra3 = *(const float4*)(Aload+12);
    float4 rb0 = *(const float4*)(Wload);
    float4 rb1 = *(const float4*)(Wload+4);
    As[0][kq+ 0][mA]=ra0.x; As[0][kq+ 1][mA]=ra0.y; As[0][kq+ 2][mA]=ra0.z; As[0][kq+ 3][mA]=ra0.w;
    As[0][kq+ 4][mA]=ra1.x; As[0][kq+ 5][mA]=ra1.y; As[0][kq+ 6][mA]=ra1.z; As[0][kq+ 7][mA]=ra1.w;
    As[0][kq+ 8][mA]=ra2.x; As[0][kq+ 9][mA]=ra2.y; As[0][kq+10][mA]=ra2.z; As[0][kq+11][mA]=ra2.w;
    As[0][kq+12][mA]=ra3.x; As[0][kq+13][mA]=ra3.y; As[0][kq+14][mA]=ra3.z; As[0][kq+15][mA]=ra3.w;
    *(float4*)&Bs[0][kB][n8]   = rb0;
    *(float4*)&Bs[0][kB][n8+4] = rb1;
    __syncthreads();

    for (int it=0; it<ITERS; it++){
        int s = it&1;
        if (it+1<ITERS){
            const float* ap = Aload + (it+1)*32;
            ra0 = *(const float4*)(ap);
            ra1 = *(const float4*)(ap+4);
            ra2 = *(const float4*)(ap+8);
            ra3 = *(const float4*)(ap+12);
            const float* bp = Wload + (size_t)(it+1)*32*EE;
            rb0 = *(const float4*)(bp);
            rb1 = *(const float4*)(bp+4);
        }
        #pragma unroll
        for (int k=0;k<32;k++){
            ulonglong2 A01 = *(const ulonglong2*)&As[s][k][ty*8];
            ulonglong2 A23 = *(const ulonglong2*)&As[s][k][ty*8+4];
            float4 bf = *(const float4*)&Bs[s][k][tx*4];
            ull B0=pk2(bf.x,bf.x), B1=pk2(bf.y,bf.y), B2=pk2(bf.z,bf.z), B3=pk2(bf.w,bf.w);
            ffma2(acc[0][0],A01.x,B0); ffma2(acc[0][1],A01.y,B0); ffma2(acc[0][2],A23.x,B0); ffma2(acc[0][3],A23.y,B0);
            ffma2(acc[1][0],A01.x,B1); ffma2(acc[1][1],A01.y,B1); ffma2(acc[1][2],A23.x,B1); ffma2(acc[1][3],A23.y,B1);
            ffma2(acc[2][0],A01.x,B2); ffma2(acc[2][1],A01.y,B2); ffma2(acc[2][2],A23.x,B2); ffma2(acc[2][3],A23.y,B2);
            ffma2(acc[3][0],A01.x,B3); ffma2(acc[3][1],A01.y,B3); ffma2(acc[3][2],A23.x,B3); ffma2(acc[3][3],A23.y,B3);
        }
        if (it+1<ITERS){
            int d = s^1;
            As[d][kq+ 0][mA]=ra0.x; As[d][kq+ 1][mA]=ra0.y; As[d][kq+ 2][mA]=ra0.z; As[d][kq+ 3][mA]=ra0.w;
            As[d][kq+ 4][mA]=ra1.x; As[d][kq+ 5][mA]=ra1.y; As[d][kq+ 6][mA]=ra1.z; As[d][kq+ 7][mA]=ra1.w;
            As[d][kq+ 8][mA]=ra2.x; As[d][kq+ 9][mA]=ra2.y; As[d][kq+10][mA]=ra2.z; As[d][kq+11][mA]=ra2.w;
            As[d][kq+12][mA]=ra3.x; As[d][kq+13][mA]=ra3.y; As[d][kq+14][mA]=ra3.z; As[d][kq+15][mA]=ra3.w;
            *(float4*)&Bs[d][kB][n8]   = rb0;
            *(float4*)&Bs[d][kB][n8+4] = rb1;
        }
        __syncthreads();
    }

    float4 dv = *(const float4*)&g_dvec[tx*4];
    float4 cv = *(const float4*)&g_cvec[tx*4];
    #pragma unroll
    for (int mp=0; mp<4; mp++){
        float2 c0=upk(acc[0][mp]), c1=upk(acc[1][mp]), c2=upk(acc[2][mp]), c3=upk(acc[3][mp]);
        #pragma unroll
        for (int rr=0; rr<2; rr++){
            int m = m0 + ty*8 + 2*mp + rr;
            float4 u = rr ? make_float4(c0.y,c1.y,c2.y,c3.y)
                          : make_float4(c0.x,c1.x,c2.x,c3.x);
            float mean = g_mean[m], rstd = g_rstd[m];
            int b_ = m>>14, h = (m>>7)&127, w = m&127;
            int mc = (b_<<12) | ((h>>1)<<6) | (w>>1);
            float gt = g_gate[mc];
            float4 qc4 = *(const float4*)&g_proj[(size_t)mc*NP + 64 + tx*4];
            float4 q;
            q.x = rstd*(u.x - mean*dv.x) + cv.x;
            q.y = rstd*(u.y - mean*dv.y) + cv.y;
            q.z = rstd*(u.z - mean*dv.z) + cv.z;
            q.w = rstd*(u.w - mean*dv.w) + cv.w;
            float4 o;
            o.x = q.x*gt + qc4.x*(1.f-gt);
            o.y = q.y*gt + qc4.y*(1.f-gt);
            o.z = q.z*gt + qc4.z*(1.f-gt);
            o.w = q.w*gt + qc4.w*(1.f-gt);
            *(float4*)&g_query[(size_t)m*EE + tx*4] = o;
        }
    }
}

// ================= local attention (v-channel split: 2 blocks per tile) =================
#define SK_STRIDE 68
#define ATT_SMEM_BYTES ((6800 + 12800 + 4096 + 1792) * 4)
__global__ void __launch_bounds__(256) attn_kernel(float* __restrict__ out)
{
    extern __shared__ __align__(16) float sm[];
    float* sk = sm;                       // [5][20][68]
    float* sv = sm + 6800;                // [5][20][128]  (half of v channels)
    float* sq = sm + 6800 + 12800;        // [64][64]
    float* satt = sq + 4096;              // [64][28]

    int j0 = blockIdx.x * 16;
    int i  = blockIdx.y;
    int bz = blockIdx.z;
    int b  = bz >> 1, vz = bz & 1;
    int t = threadIdx.x;

    // stage keys: proj cols [0,64)
    for (int idx = t; idx < 1600; idx += 256){
        int c4 = idx & 15, cc = (idx>>4) % 20, r = idx/320;
        int ci = i - 2 + r, cj = j0 - 2 + cc;
        float4 v = make_float4(0.f,0.f,0.f,0.f);
        if (ci>=0 && ci<HC && cj>=0 && cj<WC)
            v = *(const float4*)&g_proj[(size_t)((b*HC+ci)*WC + cj)*NP + c4*4];
        *(float4*)&sk[(r*20+cc)*SK_STRIDE + c4*4] = v;
    }
    // stage this block's 128 v channels: proj cols [128 + vz*128, ...)
    for (int idx = t; idx < 3200; idx += 256){
        int c4 = idx & 31, cc = (idx>>5) % 20, r = idx/640;
        int ci = i - 2 + r, cj = j0 - 2 + cc;
        float4 v = make_float4(0.f,0.f,0.f,0.f);
        if (ci>=0 && ci<HC && cj>=0 && cj<WC)
            v = *(const float4*)&g_proj[(size_t)((b*HC+ci)*WC + cj)*NP + 128 + vz*128 + c4*4];
        *(float4*)&sv[(r*20+cc)*128 + c4*4] = v;
    }
    // stage queries
    for (int idx = t; idx < 1024; idx += 256){
        int c4 = idx & 15, fp = idx >> 4;
        int cp = fp>>2, q = fp&3, di = q>>1, dj = q&1;
        int h = 2*i + di, w = 2*(j0+cp) + dj;
        *(float4*)&sq[fp*64 + c4*4] =
            *(const float4*)&g_query[(((size_t)(b*HF+h)*WF + w)<<6) + c4*4];
    }
    __syncthreads();

    // scores + softmax (duplicated across vz; cheap)
    int wd = t>>5, l = t&31;
    int pr = l/5, pc = l - pr*5;
    for (int fi=0; fi<8; fi++){
        int fp = wd*8 + fi;
        int cp = fp>>2;
        float s = -1e30f;
        if (l < 25){
            s = 0.f;
            const float* kk = &sk[(pr*20 + cp + pc)*SK_STRIDE];
            const float* qq = &sq[fp*64];
            #pragma unroll
            for (int c4=0;c4<16;c4++){
                float4 qa = *(const float4*)(qq + c4*4);
                float4 ka = *(const float4*)(kk + c4*4);
                s += qa.x*ka.x + qa.y*ka.y + qa.z*ka.z + qa.w*ka.w;
            }
        }
        float mx = s;
        #pragma unroll
        for (int o=16;o;o>>=1) mx = fmaxf(mx, __shfl_xor_sync(0xffffffffu,mx,o));
        float e = (l<25) ? __expf(s - mx) : 0.f;
        float ssum = e;
        #pragma unroll
        for (int o=16;o;o>>=1) ssum += __shfl_xor_sync(0xffffffffu,ssum,o);
        if (l<25) satt[fp*28 + l] = e / ssum;
    }
    __syncthreads();

    // value pass: 16 threads per coarse pixel, 2 channel groups of 64
    int cp = t>>4, l16 = t&15;
    for (int cg=0; cg<2; cg++){
        int cl = cg*64 + l16*4;
        ull acc[4][2];
        #pragma unroll
        for (int q=0;q<4;q++){ acc[q][0]=pk2(0.f,0.f); acc[q][1]=pk2(0.f,0.f); }
        #pragma unroll
        for (int p=0;p<25;p++){
            int ppr = p/5, ppc = p - ppr*5;
            const ull* vp = (const ull*)&sv[(ppr*20 + cp + ppc)*128 + cl];
            ull v01 = vp[0], v23 = vp[1];
            #pragma unroll
            for (int q=0;q<4;q++){
                float a = satt[(cp*4+q)*28 + p];
                ull aP = pk2(a,a);
                ffma2(acc[q][0], aP, v01);
                ffma2(acc[q][1], aP, v23);
            }
        }
        #pragma unroll
        for (int q=0;q<4;q++){
            int di=q>>1, dj=q&1;
            int h = 2*i+di, w = 2*(j0+cp)+dj;
            float2 u0=upk(acc[q][0]), u1=upk(acc[q][1]);
            float4 o = make_float4(u0.x,u0.y,u1.x,u1.y);
            *(float4*)&out[(((size_t)(b*HF+h)*WF + w)<<8) + vz*128 + cl] = o;
        }
    }
}

// ================= launch =================
extern "C" void kernel_launch(void* const* d_in, const int* in_sizes, int n_in,
                              void* d_out, int out_size)
{
    (void)in_sizes; (void)n_in; (void)out_size;
    const float* fine   = (const float*)d_in[0];
    const float* coarse = (const float*)d_in[1];
    const float* ln_f_g = (const float*)d_in[2];
    const float* ln_f_b = (const float*)d_in[3];
    const float* ln_c_g = (const float*)d_in[4];
    const float* ln_c_b = (const float*)d_in[5];
    const float* w_gate = (const float*)d_in[6];
    const float* b_gate = (const float*)d_in[7];
    const float* w_qf   = (const float*)d_in[8];
    const float* b_qf   = (const float*)d_in[9];
    const float* w_qc   = (const float*)d_in[10];
    const float* b_qc   = (const float*)d_in[11];
    const float* w_k    = (const float*)d_in[12];
    const float* b_k    = (const float*)d_in[13];
    const float* w_v    = (const float*)d_in[14];
    const float* b_v    = (const float*)d_in[15];
    float* out = (float*)d_out;

    ln_coarse_gate<<<NCOARSE, 128>>>(coarse, ln_c_g, ln_c_b, w_gate, b_gate);
    pack_w<<<CC, NP>>>(w_k, w_qc, w_v, b_k, b_qc, b_v);
    fine_stats<<<NFINE/8, 256>>>(fine);
    fold_qf<<<EE, 256>>>(w_qf, b_qf, ln_f_g, ln_f_b);

    proj_gemm<<<dim3(NP/64, NCOARSE/128), 256>>>();
    query_gemm<<<NFINE/128, 256>>>(fine);

    cudaFuncSetAttribute(attn_kernel, cudaFuncAttributeMaxDynamicSharedMemorySize, ATT_SMEM_BYTES);
    attn_kernel<<<dim3(WC/16, HC, BB*2), 256, ATT_SMEM_BYTES>>>(out);
}

// round 5
// speedup vs baseline: 1.2698x; 1.2698x over previous
#include <cuda_runtime.h>
#include <cuda_bf16.h>
#include <cstdint>
#include <cstddef>

typedef unsigned long long ull;

__device__ __forceinline__ void ffma2(ull& d, ull a, ull b){
    asm("fma.rn.f32x2 %0, %1, %2, %0;" : "+l"(d) : "l"(a), "l"(b));
}
__device__ __forceinline__ ull pk2(float x, float y){
    ull r; asm("mov.b64 %0, {%1, %2};" : "=l"(r) : "f"(x), "f"(y)); return r;
}
__device__ __forceinline__ float2 upk(ull a){
    float2 r; asm("mov.b64 {%0, %1}, %2;" : "=f"(r.x), "=f"(r.y) : "l"(a)); return r;
}

// ---------------- fixed shapes ----------------
#define BB 4
#define HF 128
#define WF 128
#define CF 256
#define HC 64
#define WC 64
#define CC 512
#define EE 64
#define FF 256
#define NP 384
#define NCOARSE (BB*HC*WC)   // 16384
#define NFINE   (BB*HF*WF)   // 65536

// ---------------- scratch ----------------
__device__ float g_coarse_n[(size_t)NCOARSE*CC];
__device__ float g_gate[NCOARSE];
__device__ float g_proj[(size_t)NCOARSE*NP];   // fused k|qc|v
__device__ float g_query[(size_t)NFINE*EE];
__device__ float g_mean[NFINE];
__device__ float g_rstd[NFINE];
__device__ float g_wfold[(size_t)CF*EE];
__device__ float g_dvec[EE];
__device__ float g_cvec[EE];
__device__ float g_wcat[(size_t)CC*NP];
__device__ float g_bcat[NP];

// ================= kernel 1: LN(coarse) + gate =================
__global__ void __launch_bounds__(128) ln_coarse_gate(
    const float* __restrict__ x, const float* __restrict__ g, const float* __restrict__ b,
    const float* __restrict__ wg, const float* __restrict__ bg)
{
    int row = blockIdx.x; int t = threadIdx.x;
    const float4* xr = (const float4*)(x + (size_t)row*CC);
    float4 v = xr[t];
    float s  = v.x+v.y+v.z+v.w;
    float sq = v.x*v.x+v.y*v.y+v.z*v.z+v.w*v.w;
    #pragma unroll
    for (int o=16;o;o>>=1){ s += __shfl_xor_sync(0xffffffffu,s,o); sq += __shfl_xor_sync(0xffffffffu,sq,o); }
    __shared__ float red[8];
    int wid = t>>5, l = t&31;
    if (l==0){ red[wid]=s; red[4+wid]=sq; }
    __syncthreads();
    s  = red[0]+red[1]+red[2]+red[3];
    sq = red[4]+red[5]+red[6]+red[7];
    float mean = s*(1.f/512.f);
    float var  = sq*(1.f/512.f) - mean*mean;
    float rstd = rsqrtf(var + 1e-3f);
    float4 gv = ((const float4*)g)[t];
    float4 bv = ((const float4*)b)[t];
    float4 o;
    o.x = (v.x-mean)*rstd*gv.x + bv.x;
    o.y = (v.y-mean)*rstd*gv.y + bv.y;
    o.z = (v.z-mean)*rstd*gv.z + bv.z;
    o.w = (v.w-mean)*rstd*gv.w + bv.w;
    ((float4*)(g_coarse_n + (size_t)row*CC))[t] = o;
    float4 wv = ((const float4*)wg)[t];
    float gd = o.x*wv.x + o.y*wv.y + o.z*wv.z + o.w*wv.w;
    #pragma unroll
    for (int oo=16;oo;oo>>=1) gd += __shfl_xor_sync(0xffffffffu,gd,oo);
    __syncthreads();
    if (l==0) red[wid]=gd;
    __syncthreads();
    if (t==0){
        float tot = red[0]+red[1]+red[2]+red[3] + bg[0];
        g_gate[row] = 1.f/(1.f+__expf(-tot));
    }
}

// ================= kernel 2: fine LN stats =================
__global__ void __launch_bounds__(256) fine_stats(const float* __restrict__ x)
{
    int w = threadIdx.x>>5, l = threadIdx.x&31;
    int row = blockIdx.x*8 + w;
    const float4* xr = (const float4*)(x + (size_t)row*CF);
    float4 a = xr[l], c = xr[l+32];
    float s  = a.x+a.y+a.z+a.w + c.x+c.y+c.z+c.w;
    float sq = a.x*a.x+a.y*a.y+a.z*a.z+a.w*a.w + c.x*c.x+c.y*c.y+c.z*c.z+c.w*c.w;
    #pragma unroll
    for (int o=16;o;o>>=1){ s += __shfl_xor_sync(0xffffffffu,s,o); sq += __shfl_xor_sync(0xffffffffu,sq,o); }
    if (l==0){
        float m = s*(1.f/256.f);
        g_mean[row] = m;
        g_rstd[row] = rsqrtf(sq*(1.f/256.f) - m*m + 1e-3f);
    }
}

// ================= pack weights =================
__global__ void __launch_bounds__(384) pack_w(
    const float* __restrict__ wk, const float* __restrict__ wqc, const float* __restrict__ wv,
    const float* __restrict__ bk, const float* __restrict__ bqc, const float* __restrict__ bv)
{
    int k = blockIdx.x; int n = threadIdx.x;
    float v;
    if (n < 64)       v = wk [k*64  + n];
    else if (n < 128) v = wqc[k*64  + (n-64)];
    else              v = wv [k*256 + (n-128)];
    g_wcat[(size_t)k*NP + n] = v;
    if (k == 0){
        float bvv = (n<64) ? bk[n] : (n<128) ? bqc[n-64] : bv[n-128];
        g_bcat[n] = bvv;
    }
}

// ================= fold LN(fine) params into w_qf: block per n, threads over k =================
__global__ void __launch_bounds__(256) fold_qf(
    const float* __restrict__ wqf, const float* __restrict__ bqf,
    const float* __restrict__ g, const float* __restrict__ bb)
{
    int n = blockIdx.x; int t = threadIdx.x;   // t = k in [0,256)
    float wv = wqf[t*EE + n];
    float wf = g[t]*wv;
    g_wfold[t*EE + n] = wf;
    float cv = bb[t]*wv;
    #pragma unroll
    for (int o=16;o;o>>=1){ wf += __shfl_xor_sync(0xffffffffu,wf,o); cv += __shfl_xor_sync(0xffffffffu,cv,o); }
    __shared__ float sd[8], sc[8];
    int wid = t>>5, l = t&31;
    if (l==0){ sd[wid]=wf; sc[wid]=cv; }
    __syncthreads();
    if (t==0){
        float dd=0.f, cc=0.f;
        #pragma unroll
        for (int i=0;i<8;i++){ dd+=sd[i]; cc+=sc[i]; }
        g_dvec[n]=dd; g_cvec[n]=cc + bqf[n];
    }
}

// ================= fused projection GEMM: proj = coarse_n @ wcat + bcat =================
// R3 structure: BM=128 BN=64 BK=16, 256 thr, single buffer; B read as LDS.128
__global__ void __launch_bounds__(256) proj_gemm()
{
    __shared__ __align__(16) float As[16][128];
    __shared__ __align__(16) float Bs[16][64];
    int m0 = blockIdx.x*128, n0 = blockIdx.y*64;
    int t = threadIdx.x;
    int mA = t>>1, kq = (t&1)*8;
    int kB = t>>4, n4 = (t&15)*4;
    int ty = t>>4, tx = t&15;

    const float* Aload = g_coarse_n + (size_t)(m0+mA)*CC + kq;
    const float* Wload = g_wcat + (size_t)kB*NP + n0 + n4;

    ull acc[4][4];   // [n][m-pair]
    #pragma unroll
    for (int n=0;n<4;n++)
        #pragma unroll
        for (int mp=0;mp<4;mp++) acc[n][mp]=pk2(0.f,0.f);

    const int KB = CC/16;
    float4 ra0 = *(const float4*)(Aload);
    float4 ra1 = *(const float4*)(Aload+4);
    float4 rb  = *(const float4*)(Wload);
    for (int kb=0; kb<KB; kb++){
        As[kq+0][mA]=ra0.x; As[kq+1][mA]=ra0.y; As[kq+2][mA]=ra0.z; As[kq+3][mA]=ra0.w;
        As[kq+4][mA]=ra1.x; As[kq+5][mA]=ra1.y; As[kq+6][mA]=ra1.z; As[kq+7][mA]=ra1.w;
        *(float4*)&Bs[kB][n4] = rb;
        __syncthreads();
        if (kb+1<KB){
            ra0 = *(const float4*)(Aload + (kb+1)*16);
            ra1 = *(const float4*)(Aload + (kb+1)*16 + 4);
            rb  = *(const float4*)(Wload + (size_t)(kb+1)*16*NP);
        }
        #pragma unroll
        for (int k=0;k<16;k++){
            ulonglong2 A01 = *(const ulonglong2*)&As[k][ty*8];
            ulonglong2 A23 = *(const ulonglong2*)&As[k][ty*8+4];
            float4 bf = *(const float4*)&Bs[k][tx*4];
            ull B0=pk2(bf.x,bf.x), B1=pk2(bf.y,bf.y), B2=pk2(bf.z,bf.z), B3=pk2(bf.w,bf.w);
            ffma2(acc[0][0],A01.x,B0); ffma2(acc[0][1],A01.y,B0); ffma2(acc[0][2],A23.x,B0); ffma2(acc[0][3],A23.y,B0);
            ffma2(acc[1][0],A01.x,B1); ffma2(acc[1][1],A01.y,B1); ffma2(acc[1][2],A23.x,B1); ffma2(acc[1][3],A23.y,B1);
            ffma2(acc[2][0],A01.x,B2); ffma2(acc[2][1],A01.y,B2); ffma2(acc[2][2],A23.x,B2); ffma2(acc[2][3],A23.y,B2);
            ffma2(acc[3][0],A01.x,B3); ffma2(acc[3][1],A01.y,B3); ffma2(acc[3][2],A23.x,B3); ffma2(acc[3][3],A23.y,B3);
        }
        __syncthreads();
    }
    float4 bb = *(const float4*)&g_bcat[n0 + tx*4];
    #pragma unroll
    for (int mp=0; mp<4; mp++){
        float2 c0=upk(acc[0][mp]), c1=upk(acc[1][mp]), c2=upk(acc[2][mp]), c3=upk(acc[3][mp]);
        int r0 = m0 + ty*8 + 2*mp;
        *(float4*)&g_proj[(size_t)r0*NP + n0 + tx*4] =
            make_float4(c0.x+bb.x, c1.x+bb.y, c2.x+bb.z, c3.x+bb.w);
        *(float4*)&g_proj[(size_t)(r0+1)*NP + n0 + tx*4] =
            make_float4(c0.y+bb.x, c1.y+bb.y, c2.y+bb.z, c3.y+bb.w);
    }
}

// ================= query GEMM with folded LN + gate blend =================
__global__ void __launch_bounds__(256) query_gemm(const float* __restrict__ fine)
{
    __shared__ __align__(16) float As[16][128];
    __shared__ __align__(16) float Bs[16][64];
    int m0 = blockIdx.x*128;
    int t = threadIdx.x;
    int mA = t>>1, kq = (t&1)*8;
    int kB = t>>4, n4 = (t&15)*4;
    int ty = t>>4, tx = t&15;

    const float* Aload = fine + (size_t)(m0+mA)*CF + kq;
    const float* Wload = g_wfold + (size_t)kB*EE + n4;

    ull acc[4][4];
    #pragma unroll
    for (int n=0;n<4;n++)
        #pragma unroll
        for (int mp=0;mp<4;mp++) acc[n][mp]=pk2(0.f,0.f);

    const int KB = CF/16;
    float4 ra0 = *(const float4*)(Aload);
    float4 ra1 = *(const float4*)(Aload+4);
    float4 rb  = *(const float4*)(Wload);
    for (int kb=0; kb<KB; kb++){
        As[kq+0][mA]=ra0.x; As[kq+1][mA]=ra0.y; As[kq+2][mA]=ra0.z; As[kq+3][mA]=ra0.w;
        As[kq+4][mA]=ra1.x; As[kq+5][mA]=ra1.y; As[kq+6][mA]=ra1.z; As[kq+7][mA]=ra1.w;
        *(float4*)&Bs[kB][n4] = rb;
        __syncthreads();
        if (kb+1<KB){
            ra0 = *(const float4*)(Aload + (kb+1)*16);
            ra1 = *(const float4*)(Aload + (kb+1)*16 + 4);
            rb  = *(const float4*)(Wload + (size_t)(kb+1)*16*EE);
        }
        #pragma unroll
        for (int k=0;k<16;k++){
            ulonglong2 A01 = *(const ulonglong2*)&As[k][ty*8];
            ulonglong2 A23 = *(const ulonglong2*)&As[k][ty*8+4];
            float4 bf = *(const float4*)&Bs[k][tx*4];
            ull B0=pk2(bf.x,bf.x), B1=pk2(bf.y,bf.y), B2=pk2(bf.z,bf.z), B3=pk2(bf.w,bf.w);
            ffma2(acc[0][0],A01.x,B0); ffma2(acc[0][1],A01.y,B0); ffma2(acc[0][2],A23.x,B0); ffma2(acc[0][3],A23.y,B0);
            ffma2(acc[1][0],A01.x,B1); ffma2(acc[1][1],A01.y,B1); ffma2(acc[1][2],A23.x,B1); ffma2(acc[1][3],A23.y,B1);
            ffma2(acc[2][0],A01.x,B2); ffma2(acc[2][1],A01.y,B2); ffma2(acc[2][2],A23.x,B2); ffma2(acc[2][3],A23.y,B2);
            ffma2(acc[3][0],A01.x,B3); ffma2(acc[3][1],A01.y,B3); ffma2(acc[3][2],A23.x,B3); ffma2(acc[3][3],A23.y,B3);
        }
        __syncthreads();
    }
    float4 dv = *(const float4*)&g_dvec[tx*4];
    float4 cv = *(const float4*)&g_cvec[tx*4];
    #pragma unroll
    for (int mp=0; mp<4; mp++){
        float2 c0=upk(acc[0][mp]), c1=upk(acc[1][mp]), c2=upk(acc[2][mp]), c3=upk(acc[3][mp]);
        #pragma unroll
        for (int rr=0; rr<2; rr++){
            int m = m0 + ty*8 + 2*mp + rr;
            float4 u = rr ? make_float4(c0.y,c1.y,c2.y,c3.y)
                          : make_float4(c0.x,c1.x,c2.x,c3.x);
            float mean = g_mean[m], rstd = g_rstd[m];
            int b_ = m>>14, h = (m>>7)&127, w = m&127;
            int mc = (b_<<12) | ((h>>1)<<6) | (w>>1);
            float gt = g_gate[mc];
            float4 qc4 = *(const float4*)&g_proj[(size_t)mc*NP + 64 + tx*4];
            float4 q;
            q.x = rstd*(u.x - mean*dv.x) + cv.x;
            q.y = rstd*(u.y - mean*dv.y) + cv.y;
            q.z = rstd*(u.z - mean*dv.z) + cv.z;
            q.w = rstd*(u.w - mean*dv.w) + cv.w;
            float4 o;
            o.x = q.x*gt + qc4.x*(1.f-gt);
            o.y = q.y*gt + qc4.y*(1.f-gt);
            o.z = q.z*gt + qc4.z*(1.f-gt);
            o.w = q.w*gt + qc4.w*(1.f-gt);
            *(float4*)&g_query[(size_t)m*EE + tx*4] = o;
        }
    }
}

// ================= local attention (R3 unsplit form) =================
#define SK_STRIDE 68
#define ATT_SMEM_BYTES ((6800 + 25600 + 4096 + 64*28) * 4)
__global__ void __launch_bounds__(256) attn_kernel(float* __restrict__ out)
{
    extern __shared__ __align__(16) float sm[];
    float* sk = sm;                       // [5][20][68]
    float* sv = sm + 6800;                // [5][20][256]
    float* sq = sm + 6800 + 25600;        // [64][64]
    float* satt = sq + 4096;              // [64][28]

    int j0 = blockIdx.x * 16;
    int i  = blockIdx.y;
    int b  = blockIdx.z;
    int t = threadIdx.x;

    // stage keys: proj cols [0,64)
    for (int idx = t; idx < 1600; idx += 256){
        int c4 = idx & 15, cc = (idx>>4) % 20, r = idx/320;
        int ci = i - 2 + r, cj = j0 - 2 + cc;
        float4 v = make_float4(0.f,0.f,0.f,0.f);
        if (ci>=0 && ci<HC && cj>=0 && cj<WC)
            v = *(const float4*)&g_proj[(size_t)((b*HC+ci)*WC + cj)*NP + c4*4];
        *(float4*)&sk[(r*20+cc)*SK_STRIDE + c4*4] = v;
    }
    // stage values: proj cols [128,384)
    for (int idx = t; idx < 6400; idx += 256){
        int c4 = idx & 63, cc = (idx>>6) % 20, r = idx/1280;
        int ci = i - 2 + r, cj = j0 - 2 + cc;
        float4 v = make_float4(0.f,0.f,0.f,0.f);
        if (ci>=0 && ci<HC && cj>=0 && cj<WC)
            v = *(const float4*)&g_proj[(size_t)((b*HC+ci)*WC + cj)*NP + 128 + c4*4];
        *(float4*)&sv[(r*20+cc)*256 + c4*4] = v;
    }
    // stage queries
    for (int idx = t; idx < 1024; idx += 256){
        int c4 = idx & 15, fp = idx >> 4;
        int cp = fp>>2, q = fp&3, di = q>>1, dj = q&1;
        int h = 2*i + di, w = 2*(j0+cp) + dj;
        *(float4*)&sq[fp*64 + c4*4] =
            *(const float4*)&g_query[(((size_t)(b*HF+h)*WF + w)<<6) + c4*4];
    }
    __syncthreads();

    // scores + softmax: warp per 8 fine pixels, lane per patch
    int wd = t>>5, l = t&31;
    int pr = l/5, pc = l - pr*5;
    for (int fi=0; fi<8; fi++){
        int fp = wd*8 + fi;
        int cp = fp>>2;
        float s = -1e30f;
        if (l < 25){
            s = 0.f;
            const float* kk = &sk[(pr*20 + cp + pc)*SK_STRIDE];
            const float* qq = &sq[fp*64];
            #pragma unroll
            for (int c4=0;c4<16;c4++){
                float4 qa = *(const float4*)(qq + c4*4);
                float4 ka = *(const float4*)(kk + c4*4);
                s += qa.x*ka.x + qa.y*ka.y + qa.z*ka.z + qa.w*ka.w;
            }
        }
        float mx = s;
        #pragma unroll
        for (int o=16;o;o>>=1) mx = fmaxf(mx, __shfl_xor_sync(0xffffffffu,mx,o));
        float e = (l<25) ? __expf(s - mx) : 0.f;
        float ssum = e;
        #pragma unroll
        for (int o=16;o;o>>=1) ssum += __shfl_xor_sync(0xffffffffu,ssum,o);
        if (l<25) satt[fp*28 + l] = e / ssum;
    }
    __syncthreads();

    // value pass: 16 threads per coarse pixel
    int cp = t>>4, l16 = t&15;
    for (int cg=0; cg<4; cg++){
        int c = cg*64 + l16*4;
        ull acc[4][2];
        #pragma unroll
        for (int q=0;q<4;q++){ acc[q][0]=pk2(0.f,0.f); acc[q][1]=pk2(0.f,0.f); }
        #pragma unroll
        for (int p=0;p<25;p++){
            int ppr = p/5, ppc = p - ppr*5;
            const ull* vp = (const ull*)&sv[(ppr*20 + cp + ppc)*256 + c];
            ull v01 = vp[0], v23 = vp[1];
            #pragma unroll
            for (int q=0;q<4;q++){
                float a = satt[(cp*4+q)*28 + p];
                ull aP = pk2(a,a);
                ffma2(acc[q][0], aP, v01);
                ffma2(acc[q][1], aP, v23);
            }
        }
        #pragma unroll
        for (int q=0;q<4;q++){
            int di=q>>1, dj=q&1;
            int h = 2*i+di, w = 2*(j0+cp)+dj;
            float2 u0=upk(acc[q][0]), u1=upk(acc[q][1]);
            float4 o = make_float4(u0.x,u0.y,u1.x,u1.y);
            *(float4*)&out[(((size_t)(b*HF+h)*WF + w)<<8) + c] = o;
        }
    }
}

// ================= launch =================
// Order puts proj_gemm in the profiled 4th slot.
extern "C" void kernel_launch(void* const* d_in, const int* in_sizes, int n_in,
                              void* d_out, int out_size)
{
    (void)in_sizes; (void)n_in; (void)out_size;
    const float* fine   = (const float*)d_in[0];
    const float* coarse = (const float*)d_in[1];
    const float* ln_f_g = (const float*)d_in[2];
    const float* ln_f_b = (const float*)d_in[3];
    const float* ln_c_g = (const float*)d_in[4];
    const float* ln_c_b = (const float*)d_in[5];
    const float* w_gate = (const float*)d_in[6];
    const float* b_gate = (const float*)d_in[7];
    const float* w_qf   = (const float*)d_in[8];
    const float* b_qf   = (const float*)d_in[9];
    const float* w_qc   = (const float*)d_in[10];
    const float* b_qc   = (const float*)d_in[11];
    const float* w_k    = (const float*)d_in[12];
    const float* b_k    = (const float*)d_in[13];
    const float* w_v    = (const float*)d_in[14];
    const float* b_v    = (const float*)d_in[15];
    float* out = (float*)d_out;

    ln_coarse_gate<<<NCOARSE, 128>>>(coarse, ln_c_g, ln_c_b, w_gate, b_gate);   // 1
    pack_w<<<CC, NP>>>(w_k, w_qc, w_v, b_k, b_qc, b_v);                          // 2
    fine_stats<<<NFINE/8, 256>>>(fine);                                          // 3
    proj_gemm<<<dim3(NCOARSE/128, NP/64), 256>>>();                              // 4  <- profiled slot
    fold_qf<<<EE, 256>>>(w_qf, b_qf, ln_f_g, ln_f_b);                            // 5
    query_gemm<<<NFINE/128, 256>>>(fine);                                        // 6
    cudaFuncSetAttribute(attn_kernel, cudaFuncAttributeMaxDynamicSharedMemorySize, ATT_SMEM_BYTES);
    attn_kernel<<<dim3(WC/16, HC, BB), 256, ATT_SMEM_BYTES>>>(out);              // 7
}

// round 6
// speedup vs baseline: 1.2972x; 1.0216x over previous
#include <cuda_runtime.h>
#include <cuda_bf16.h>
#include <cstdint>
#include <cstddef>

typedef unsigned long long ull;

__device__ __forceinline__ void ffma2(ull& d, ull a, ull b){
    asm("fma.rn.f32x2 %0, %1, %2, %0;" : "+l"(d) : "l"(a), "l"(b));
}
__device__ __forceinline__ ull pk2(float x, float y){
    ull r; asm("mov.b64 %0, {%1, %2};" : "=l"(r) : "f"(x), "f"(y)); return r;
}
__device__ __forceinline__ float2 upk(ull a){
    float2 r; asm("mov.b64 {%0, %1}, %2;" : "=f"(r.x), "=f"(r.y) : "l"(a)); return r;
}

// ---------------- fixed shapes ----------------
#define BB 4
#define HF 128
#define WF 128
#define CF 256
#define HC 64
#define WC 64
#define CC 512
#define EE 64
#define FF 256
#define NP 384
#define NCOARSE (BB*HC*WC)   // 16384
#define NFINE   (BB*HF*WF)   // 65536

// ---------------- scratch ----------------
__device__ float g_coarse_n[(size_t)NCOARSE*CC];
__device__ float g_gate[NCOARSE];
__device__ float g_proj[(size_t)NCOARSE*NP];   // fused k|qc|v
__device__ float g_query[(size_t)NFINE*EE];
__device__ float g_mean[NFINE];
__device__ float g_rstd[NFINE];
__device__ float g_wfold[(size_t)CF*EE];
__device__ float g_dvec[EE];
__device__ float g_cvec[EE];
__device__ float g_wcat[(size_t)CC*NP];
__device__ float g_bcat[NP];

// ================= kernel 1: LN(coarse) + gate =================
__global__ void __launch_bounds__(128) ln_coarse_gate(
    const float* __restrict__ x, const float* __restrict__ g, const float* __restrict__ b,
    const float* __restrict__ wg, const float* __restrict__ bg)
{
    int row = blockIdx.x; int t = threadIdx.x;
    const float4* xr = (const float4*)(x + (size_t)row*CC);
    float4 v = xr[t];
    float s  = v.x+v.y+v.z+v.w;
    float sq = v.x*v.x+v.y*v.y+v.z*v.z+v.w*v.w;
    #pragma unroll
    for (int o=16;o;o>>=1){ s += __shfl_xor_sync(0xffffffffu,s,o); sq += __shfl_xor_sync(0xffffffffu,sq,o); }
    __shared__ float red[8];
    int wid = t>>5, l = t&31;
    if (l==0){ red[wid]=s; red[4+wid]=sq; }
    __syncthreads();
    s  = red[0]+red[1]+red[2]+red[3];
    sq = red[4]+red[5]+red[6]+red[7];
    float mean = s*(1.f/512.f);
    float var  = sq*(1.f/512.f) - mean*mean;
    float rstd = rsqrtf(var + 1e-3f);
    float4 gv = ((const float4*)g)[t];
    float4 bv = ((const float4*)b)[t];
    float4 o;
    o.x = (v.x-mean)*rstd*gv.x + bv.x;
    o.y = (v.y-mean)*rstd*gv.y + bv.y;
    o.z = (v.z-mean)*rstd*gv.z + bv.z;
    o.w = (v.w-mean)*rstd*gv.w + bv.w;
    ((float4*)(g_coarse_n + (size_t)row*CC))[t] = o;
    float4 wv = ((const float4*)wg)[t];
    float gd = o.x*wv.x + o.y*wv.y + o.z*wv.z + o.w*wv.w;
    #pragma unroll
    for (int oo=16;oo;oo>>=1) gd += __shfl_xor_sync(0xffffffffu,gd,oo);
    __syncthreads();
    if (l==0) red[wid]=gd;
    __syncthreads();
    if (t==0){
        float tot = red[0]+red[1]+red[2]+red[3] + bg[0];
        g_gate[row] = 1.f/(1.f+__expf(-tot));
    }
}

// ================= kernel 2: fine LN stats =================
__global__ void __launch_bounds__(256) fine_stats(const float* __restrict__ x)
{
    int w = threadIdx.x>>5, l = threadIdx.x&31;
    int row = blockIdx.x*8 + w;
    const float4* xr = (const float4*)(x + (size_t)row*CF);
    float4 a = xr[l], c = xr[l+32];
    float s  = a.x+a.y+a.z+a.w + c.x+c.y+c.z+c.w;
    float sq = a.x*a.x+a.y*a.y+a.z*a.z+a.w*a.w + c.x*c.x+c.y*c.y+c.z*c.z+c.w*c.w;
    #pragma unroll
    for (int o=16;o;o>>=1){ s += __shfl_xor_sync(0xffffffffu,s,o); sq += __shfl_xor_sync(0xffffffffu,sq,o); }
    if (l==0){
        float m = s*(1.f/256.f);
        g_mean[row] = m;
        g_rstd[row] = rsqrtf(sq*(1.f/256.f) - m*m + 1e-3f);
    }
}

// ================= pack weights =================
__global__ void __launch_bounds__(384) pack_w(
    const float* __restrict__ wk, const float* __restrict__ wqc, const float* __restrict__ wv,
    const float* __restrict__ bk, const float* __restrict__ bqc, const float* __restrict__ bv)
{
    int k = blockIdx.x; int n = threadIdx.x;
    float v;
    if (n < 64)       v = wk [k*64  + n];
    else if (n < 128) v = wqc[k*64  + (n-64)];
    else              v = wv [k*256 + (n-128)];
    g_wcat[(size_t)k*NP + n] = v;
    if (k == 0){
        float bvv = (n<64) ? bk[n] : (n<128) ? bqc[n-64] : bv[n-128];
        g_bcat[n] = bvv;
    }
}

// ================= fold LN(fine) params into w_qf =================
__global__ void __launch_bounds__(256) fold_qf(
    const float* __restrict__ wqf, const float* __restrict__ bqf,
    const float* __restrict__ g, const float* __restrict__ bb)
{
    int n = blockIdx.x; int t = threadIdx.x;
    float wv = wqf[t*EE + n];
    float wf = g[t]*wv;
    g_wfold[t*EE + n] = wf;
    float cv = bb[t]*wv;
    #pragma unroll
    for (int o=16;o;o>>=1){ wf += __shfl_xor_sync(0xffffffffu,wf,o); cv += __shfl_xor_sync(0xffffffffu,cv,o); }
    __shared__ float sd[8], sc[8];
    int wid = t>>5, l = t&31;
    if (l==0){ sd[wid]=wf; sc[wid]=cv; }
    __syncthreads();
    if (t==0){
        float dd=0.f, cc=0.f;
        #pragma unroll
        for (int i=0;i<8;i++){ dd+=sd[i]; cc+=sc[i]; }
        g_dvec[n]=dd; g_cvec[n]=cc + bqf[n];
    }
}

// ================= fused projection GEMM: proj = coarse_n @ wcat + bcat =================
// BM=128 BN=128 BK=16, 256 thr, 8x8 thread tile, acc packed along n
__global__ void __launch_bounds__(256) proj_gemm()
{
    __shared__ __align__(16) float As[16][128];
    __shared__ __align__(16) float Bs[16][128];
    int n0 = blockIdx.x*128, m0 = blockIdx.y*128;
    int t = threadIdx.x;
    int mA = t>>1, kq = (t&1)*8;     // A staging
    int kB = t>>4, n8 = (t&15)*8;    // B staging
    int ty = t>>4, tx = t&15;        // compute: rows ty*8..+8, cols tx*4 & 64+tx*4

    const float* Aload = g_coarse_n + (size_t)(m0+mA)*CC + kq;
    const float* Wload = g_wcat + (size_t)kB*NP + n0 + n8;

    ull acc[8][4];
    #pragma unroll
    for (int i=0;i<8;i++)
        #pragma unroll
        for (int j=0;j<4;j++) acc[i][j]=pk2(0.f,0.f);

    const int KB = CC/16;  // 32
    float4 ra0 = *(const float4*)(Aload);
    float4 ra1 = *(const float4*)(Aload+4);
    float4 rb0 = *(const float4*)(Wload);
    float4 rb1 = *(const float4*)(Wload+4);
    for (int kb=0; kb<KB; kb++){
        As[kq+0][mA]=ra0.x; As[kq+1][mA]=ra0.y; As[kq+2][mA]=ra0.z; As[kq+3][mA]=ra0.w;
        As[kq+4][mA]=ra1.x; As[kq+5][mA]=ra1.y; As[kq+6][mA]=ra1.z; As[kq+7][mA]=ra1.w;
        *(float4*)&Bs[kB][n8]   = rb0;
        *(float4*)&Bs[kB][n8+4] = rb1;
        __syncthreads();
        if (kb+1<KB){
            const float* ap = Aload + (kb+1)*16;
            ra0 = *(const float4*)(ap);
            ra1 = *(const float4*)(ap+4);
            const float* bp = Wload + (size_t)(kb+1)*16*NP;
            rb0 = *(const float4*)(bp);
            rb1 = *(const float4*)(bp+4);
        }
        #pragma unroll
        for (int k=0;k<16;k++){
            ulonglong2 A01 = *(const ulonglong2*)&As[k][ty*8];
            ulonglong2 A23 = *(const ulonglong2*)&As[k][ty*8+4];
            ulonglong2 B0  = *(const ulonglong2*)&Bs[k][tx*4];
            ulonglong2 B1  = *(const ulonglong2*)&Bs[k][64+tx*4];
            float2 f0=upk(A01.x), f1=upk(A01.y), f2=upk(A23.x), f3=upk(A23.y);
            ull AP0=pk2(f0.x,f0.x), AP1=pk2(f0.y,f0.y), AP2=pk2(f1.x,f1.x), AP3=pk2(f1.y,f1.y);
            ull AP4=pk2(f2.x,f2.x), AP5=pk2(f2.y,f2.y), AP6=pk2(f3.x,f3.x), AP7=pk2(f3.y,f3.y);
            ffma2(acc[0][0],AP0,B0.x); ffma2(acc[0][1],AP0,B0.y); ffma2(acc[0][2],AP0,B1.x); ffma2(acc[0][3],AP0,B1.y);
            ffma2(acc[1][0],AP1,B0.x); ffma2(acc[1][1],AP1,B0.y); ffma2(acc[1][2],AP1,B1.x); ffma2(acc[1][3],AP1,B1.y);
            ffma2(acc[2][0],AP2,B0.x); ffma2(acc[2][1],AP2,B0.y); ffma2(acc[2][2],AP2,B1.x); ffma2(acc[2][3],AP2,B1.y);
            ffma2(acc[3][0],AP3,B0.x); ffma2(acc[3][1],AP3,B0.y); ffma2(acc[3][2],AP3,B1.x); ffma2(acc[3][3],AP3,B1.y);
            ffma2(acc[4][0],AP4,B0.x); ffma2(acc[4][1],AP4,B0.y); ffma2(acc[4][2],AP4,B1.x); ffma2(acc[4][3],AP4,B1.y);
            ffma2(acc[5][0],AP5,B0.x); ffma2(acc[5][1],AP5,B0.y); ffma2(acc[5][2],AP5,B1.x); ffma2(acc[5][3],AP5,B1.y);
            ffma2(acc[6][0],AP6,B0.x); ffma2(acc[6][1],AP6,B0.y); ffma2(acc[6][2],AP6,B1.x); ffma2(acc[6][3],AP6,B1.y);
            ffma2(acc[7][0],AP7,B0.x); ffma2(acc[7][1],AP7,B0.y); ffma2(acc[7][2],AP7,B1.x); ffma2(acc[7][3],AP7,B1.y);
        }
        __syncthreads();
    }
    float4 bb0 = *(const float4*)&g_bcat[n0 + tx*4];
    float4 bb1 = *(const float4*)&g_bcat[n0 + 64 + tx*4];
    #pragma unroll
    for (int i=0;i<8;i++){
        int m = m0 + ty*8 + i;
        float2 p0=upk(acc[i][0]), p1=upk(acc[i][1]), p2=upk(acc[i][2]), p3=upk(acc[i][3]);
        *(float4*)&g_proj[(size_t)m*NP + n0 + tx*4] =
            make_float4(p0.x+bb0.x, p0.y+bb0.y, p1.x+bb0.z, p1.y+bb0.w);
        *(float4*)&g_proj[(size_t)m*NP + n0 + 64 + tx*4] =
            make_float4(p2.x+bb1.x, p2.y+bb1.y, p3.x+bb1.z, p3.y+bb1.w);
    }
}

// ================= query GEMM with folded LN + gate blend =================
// BM=256 BN=64 BK=16, 256 thr, 8x8 thread tile
__global__ void __launch_bounds__(256) query_gemm(const float* __restrict__ fine)
{
    __shared__ __align__(16) float As[16][256];
    __shared__ __align__(16) float Bs[16][64];
    int m0 = blockIdx.x*256;
    int t = threadIdx.x;
    int kB = t>>4, n4 = (t&15)*4;
    int ty = t>>3, tx = t&7;     // rows ty*8..+8 (ty 0..31), cols tx*4 & 32+tx*4

    const float* Aload = fine + (size_t)(m0+t)*CF;
    const float* Wload = g_wfold + (size_t)kB*EE + n4;

    ull acc[8][4];
    #pragma unroll
    for (int i=0;i<8;i++)
        #pragma unroll
        for (int j=0;j<4;j++) acc[i][j]=pk2(0.f,0.f);

    const int KB = CF/16;  // 16
    float4 ra0 = *(const float4*)(Aload);
    float4 ra1 = *(const float4*)(Aload+4);
    float4 ra2 = *(const float4*)(Aload+8);
    float4 ra3 = *(const float4*)(Aload+12);
    float4 rb  = *(const float4*)(Wload);
    for (int kb=0; kb<KB; kb++){
        As[ 0][t]=ra0.x; As[ 1][t]=ra0.y; As[ 2][t]=ra0.z; As[ 3][t]=ra0.w;
        As[ 4][t]=ra1.x; As[ 5][t]=ra1.y; As[ 6][t]=ra1.z; As[ 7][t]=ra1.w;
        As[ 8][t]=ra2.x; As[ 9][t]=ra2.y; As[10][t]=ra2.z; As[11][t]=ra2.w;
        As[12][t]=ra3.x; As[13][t]=ra3.y; As[14][t]=ra3.z; As[15][t]=ra3.w;
        *(float4*)&Bs[kB][n4] = rb;
        __syncthreads();
        if (kb+1<KB){
            const float* ap = Aload + (kb+1)*16;
            ra0 = *(const float4*)(ap);
            ra1 = *(const float4*)(ap+4);
            ra2 = *(const float4*)(ap+8);
            ra3 = *(const float4*)(ap+12);
            rb  = *(const float4*)(Wload + (size_t)(kb+1)*16*EE);
        }
        #pragma unroll
        for (int k=0;k<16;k++){
            ulonglong2 A01 = *(const ulonglong2*)&As[k][ty*8];
            ulonglong2 A23 = *(const ulonglong2*)&As[k][ty*8+4];
            ulonglong2 B0  = *(const ulonglong2*)&Bs[k][tx*4];
            ulonglong2 B1  = *(const ulonglong2*)&Bs[k][32+tx*4];
            float2 f0=upk(A01.x), f1=upk(A01.y), f2=upk(A23.x), f3=upk(A23.y);
            ull AP0=pk2(f0.x,f0.x), AP1=pk2(f0.y,f0.y), AP2=pk2(f1.x,f1.x), AP3=pk2(f1.y,f1.y);
            ull AP4=pk2(f2.x,f2.x), AP5=pk2(f2.y,f2.y), AP6=pk2(f3.x,f3.x), AP7=pk2(f3.y,f3.y);
            ffma2(acc[0][0],AP0,B0.x); ffma2(acc[0][1],AP0,B0.y); ffma2(acc[0][2],AP0,B1.x); ffma2(acc[0][3],AP0,B1.y);
            ffma2(acc[1][0],AP1,B0.x); ffma2(acc[1][1],AP1,B0.y); ffma2(acc[1][2],AP1,B1.x); ffma2(acc[1][3],AP1,B1.y);
            ffma2(acc[2][0],AP2,B0.x); ffma2(acc[2][1],AP2,B0.y); ffma2(acc[2][2],AP2,B1.x); ffma2(acc[2][3],AP2,B1.y);
            ffma2(acc[3][0],AP3,B0.x); ffma2(acc[3][1],AP3,B0.y); ffma2(acc[3][2],AP3,B1.x); ffma2(acc[3][3],AP3,B1.y);
            ffma2(acc[4][0],AP4,B0.x); ffma2(acc[4][1],AP4,B0.y); ffma2(acc[4][2],AP4,B1.x); ffma2(acc[4][3],AP4,B1.y);
            ffma2(acc[5][0],AP5,B0.x); ffma2(acc[5][1],AP5,B0.y); ffma2(acc[5][2],AP5,B1.x); ffma2(acc[5][3],AP5,B1.y);
            ffma2(acc[6][0],AP6,B0.x); ffma2(acc[6][1],AP6,B0.y); ffma2(acc[6][2],AP6,B1.x); ffma2(acc[6][3],AP6,B1.y);
            ffma2(acc[7][0],AP7,B0.x); ffma2(acc[7][1],AP7,B0.y); ffma2(acc[7][2],AP7,B1.x); ffma2(acc[7][3],AP7,B1.y);
        }
        __syncthreads();
    }

    float4 dv0 = *(const float4*)&g_dvec[tx*4];
    float4 cv0 = *(const float4*)&g_cvec[tx*4];
    float4 dv1 = *(const float4*)&g_dvec[32+tx*4];
    float4 cv1 = *(const float4*)&g_cvec[32+tx*4];
    #pragma unroll
    for (int i=0;i<8;i++){
        int m = m0 + ty*8 + i;
        float mean = g_mean[m], rstd = g_rstd[m];
        int b_ = m>>14, h = (m>>7)&127, w = m&127;
        int mc = (b_<<12) | ((h>>1)<<6) | (w>>1);
        float gt = g_gate[mc];
        float2 p0=upk(acc[i][0]), p1=upk(acc[i][1]), p2=upk(acc[i][2]), p3=upk(acc[i][3]);
        float4 u0 = make_float4(p0.x,p0.y,p1.x,p1.y);
        float4 u1 = make_float4(p2.x,p2.y,p3.x,p3.y);
        float4 qc0 = *(const float4*)&g_proj[(size_t)mc*NP + 64 + tx*4];
        float4 qc1 = *(const float4*)&g_proj[(size_t)mc*NP + 64 + 32 + tx*4];
        float4 q0, q1, o0, o1;
        q0.x = rstd*(u0.x - mean*dv0.x) + cv0.x;
        q0.y = rstd*(u0.y - mean*dv0.y) + cv0.y;
        q0.z = rstd*(u0.z - mean*dv0.z) + cv0.z;
        q0.w = rstd*(u0.w - mean*dv0.w) + cv0.w;
        q1.x = rstd*(u1.x - mean*dv1.x) + cv1.x;
        q1.y = rstd*(u1.y - mean*dv1.y) + cv1.y;
        q1.z = rstd*(u1.z - mean*dv1.z) + cv1.z;
        q1.w = rstd*(u1.w - mean*dv1.w) + cv1.w;
        o0.x = q0.x*gt + qc0.x*(1.f-gt);
        o0.y = q0.y*gt + qc0.y*(1.f-gt);
        o0.z = q0.z*gt + qc0.z*(1.f-gt);
        o0.w = q0.w*gt + qc0.w*(1.f-gt);
        o1.x = q1.x*gt + qc1.x*(1.f-gt);
        o1.y = q1.y*gt + qc1.y*(1.f-gt);
        o1.z = q1.z*gt + qc1.z*(1.f-gt);
        o1.w = q1.w*gt + qc1.w*(1.f-gt);
        *(float4*)&g_query[(size_t)m*EE + tx*4]      = o0;
        *(float4*)&g_query[(size_t)m*EE + 32 + tx*4] = o1;
    }
}

// ================= local attention =================
#define SK_STRIDE 68
#define ATT_SMEM_BYTES ((6800 + 25600 + 4096 + 64*28) * 4)
__global__ void __launch_bounds__(256) attn_kernel(float* __restrict__ out)
{
    extern __shared__ __align__(16) float sm[];
    float* sk = sm;                       // [5][20][68]
    float* sv = sm + 6800;                // [5][20][256]
    float* sq = sm + 6800 + 25600;        // [64][64]
    float* satt = sq + 4096;              // [64][28]

    int j0 = blockIdx.x * 16;
    int i  = blockIdx.y;
    int b  = blockIdx.z;
    int t = threadIdx.x;

    for (int idx = t; idx < 1600; idx += 256){
        int c4 = idx & 15, cc = (idx>>4) % 20, r = idx/320;
        int ci = i - 2 + r, cj = j0 - 2 + cc;
        float4 v = make_float4(0.f,0.f,0.f,0.f);
        if (ci>=0 && ci<HC && cj>=0 && cj<WC)
            v = *(const float4*)&g_proj[(size_t)((b*HC+ci)*WC + cj)*NP + c4*4];
        *(float4*)&sk[(r*20+cc)*SK_STRIDE + c4*4] = v;
    }
    for (int idx = t; idx < 6400; idx += 256){
        int c4 = idx & 63, cc = (idx>>6) % 20, r = idx/1280;
        int ci = i - 2 + r, cj = j0 - 2 + cc;
        float4 v = make_float4(0.f,0.f,0.f,0.f);
        if (ci>=0 && ci<HC && cj>=0 && cj<WC)
            v = *(const float4*)&g_proj[(size_t)((b*HC+ci)*WC + cj)*NP + 128 + c4*4];
        *(float4*)&sv[(r*20+cc)*256 + c4*4] = v;
    }
    for (int idx = t; idx < 1024; idx += 256){
        int c4 = idx & 15, fp = idx >> 4;
        int cp = fp>>2, q = fp&3, di = q>>1, dj = q&1;
        int h = 2*i + di, w = 2*(j0+cp) + dj;
        *(float4*)&sq[fp*64 + c4*4] =
            *(const float4*)&g_query[(((size_t)(b*HF+h)*WF + w)<<6) + c4*4];
    }
    __syncthreads();

    int wd = t>>5, l = t&31;
    int pr = l/5, pc = l - pr*5;
    for (int fi=0; fi<8; fi++){
        int fp = wd*8 + fi;
        int cp = fp>>2;
        float s = -1e30f;
        if (l < 25){
            s = 0.f;
            const float* kk = &sk[(pr*20 + cp + pc)*SK_STRIDE];
            const float* qq = &sq[fp*64];
            #pragma unroll
            for (int c4=0;c4<16;c4++){
                float4 qa = *(const float4*)(qq + c4*4);
                float4 ka = *(const float4*)(kk + c4*4);
                s += qa.x*ka.x + qa.y*ka.y + qa.z*ka.z + qa.w*ka.w;
            }
        }
        float mx = s;
        #pragma unroll
        for (int o=16;o;o>>=1) mx = fmaxf(mx, __shfl_xor_sync(0xffffffffu,mx,o));
        float e = (l<25) ? __expf(s - mx) : 0.f;
        float ssum = e;
        #pragma unroll
        for (int o=16;o;o>>=1) ssum += __shfl_xor_sync(0xffffffffu,ssum,o);
        if (l<25) satt[fp*28 + l] = e / ssum;
    }
    __syncthreads();

    int cp = t>>4, l16 = t&15;
    for (int cg=0; cg<4; cg++){
        int c = cg*64 + l16*4;
        ull acc[4][2];
        #pragma unroll
        for (int q=0;q<4;q++){ acc[q][0]=pk2(0.f,0.f); acc[q][1]=pk2(0.f,0.f); }
        #pragma unroll
        for (int p=0;p<25;p++){
            int ppr = p/5, ppc = p - ppr*5;
            const ull* vp = (const ull*)&sv[(ppr*20 + cp + ppc)*256 + c];
            ull v01 = vp[0], v23 = vp[1];
            #pragma unroll
            for (int q=0;q<4;q++){
                float a = satt[(cp*4+q)*28 + p];
                ull aP = pk2(a,a);
                ffma2(acc[q][0], aP, v01);
                ffma2(acc[q][1], aP, v23);
            }
        }
        #pragma unroll
        for (int q=0;q<4;q++){
            int di=q>>1, dj=q&1;
            int h = 2*i+di, w = 2*(j0+cp)+dj;
            float2 u0=upk(acc[q][0]), u1=upk(acc[q][1]);
            float4 o = make_float4(u0.x,u0.y,u1.x,u1.y);
            *(float4*)&out[(((size_t)(b*HF+h)*WF + w)<<8) + c] = o;
        }
    }
}

// ================= launch =================
extern "C" void kernel_launch(void* const* d_in, const int* in_sizes, int n_in,
                              void* d_out, int out_size)
{
    (void)in_sizes; (void)n_in; (void)out_size;
    const float* fine   = (const float*)d_in[0];
    const float* coarse = (const float*)d_in[1];
    const float* ln_f_g = (const float*)d_in[2];
    const float* ln_f_b = (const float*)d_in[3];
    const float* ln_c_g = (const float*)d_in[4];
    const float* ln_c_b = (const float*)d_in[5];
    const float* w_gate = (const float*)d_in[6];
    const float* b_gate = (const float*)d_in[7];
    const float* w_qf   = (const float*)d_in[8];
    const float* b_qf   = (const float*)d_in[9];
    const float* w_qc   = (const float*)d_in[10];
    const float* b_qc   = (const float*)d_in[11];
    const float* w_k    = (const float*)d_in[12];
    const float* b_k    = (const float*)d_in[13];
    const float* w_v    = (const float*)d_in[14];
    const float* b_v    = (const float*)d_in[15];
    float* out = (float*)d_out;

    ln_coarse_gate<<<NCOARSE, 128>>>(coarse, ln_c_g, ln_c_b, w_gate, b_gate);   // 1
    pack_w<<<CC, NP>>>(w_k, w_qc, w_v, b_k, b_qc, b_v);                          // 2
    fine_stats<<<NFINE/8, 256>>>(fine);                                          // 3
    proj_gemm<<<dim3(NP/128, NCOARSE/128), 256>>>();                             // 4  <- profiled slot
    fold_qf<<<EE, 256>>>(w_qf, b_qf, ln_f_g, ln_f_b);                            // 5
    query_gemm<<<NFINE/256, 256>>>(fine);                                        // 6
    cudaFuncSetAttribute(attn_kernel, cudaFuncAttributeMaxDynamicSharedMemorySize, ATT_SMEM_BYTES);
    attn_kernel<<<dim3(WC/16, HC, BB), 256, ATT_SMEM_BYTES>>>(out);              // 7
}

// round 8
// speedup vs baseline: 1.4033x; 1.0818x over previous
#include <cuda_runtime.h>
#include <cuda_bf16.h>
#include <cstdint>
#include <cstddef>

typedef unsigned long long ull;

__device__ __forceinline__ void ffma2(ull& d, ull a, ull b){
    asm("fma.rn.f32x2 %0, %1, %2, %0;" : "+l"(d) : "l"(a), "l"(b));
}
__device__ __forceinline__ ull pk2(float x, float y){
    ull r; asm("mov.b64 %0, {%1, %2};" : "=l"(r) : "f"(x), "f"(y)); return r;
}
__device__ __forceinline__ float2 upk(ull a){
    float2 r; asm("mov.b64 {%0, %1}, %2;" : "=f"(r.x), "=f"(r.y) : "l"(a)); return r;
}

#define LDSM4(r, addr) asm volatile( \
    "ldmatrix.sync.aligned.m8n8.x4.shared.b16 {%0,%1,%2,%3}, [%4];" \
    : "=r"((r)[0]),"=r"((r)[1]),"=r"((r)[2]),"=r"((r)[3]) : "r"(addr))

#define MMA16816(c, a, b) asm volatile( \
    "mma.sync.aligned.m16n8k16.row.col.f32.bf16.bf16.f32 " \
    "{%0,%1,%2,%3}, {%4,%5,%6,%7}, {%8,%9}, {%0,%1,%2,%3};" \
    : "+f"((c)[0]),"+f"((c)[1]),"+f"((c)[2]),"+f"((c)[3]) \
    : "r"((a)[0]),"r"((a)[1]),"r"((a)[2]),"r"((a)[3]), "r"((b)[0]),"r"((b)[1]))

// ---------------- fixed shapes ----------------
#define BB 4
#define HF 128
#define WF 128
#define CF 256
#define HC 64
#define WC 64
#define CC 512
#define EE 64
#define FF 256
#define NP 384
#define NCOARSE (BB*HC*WC)   // 16384
#define NFINE   (BB*HF*WF)   // 65536

// ---------------- scratch ----------------
__device__ __nv_bfloat16 g_cnh[(size_t)NCOARSE*CC];  // LN(coarse) hi  [m][k]
__device__ __nv_bfloat16 g_cnl[(size_t)NCOARSE*CC];  // LN(coarse) lo
__device__ __nv_bfloat16 g_wth[(size_t)NP*CC];       // W^T hi  [n][k]
__device__ __nv_bfloat16 g_wtl[(size_t)NP*CC];       // W^T lo
__device__ float g_gate[NCOARSE];
__device__ float g_proj[(size_t)NCOARSE*NP];   // fused k|qc|v
__device__ float g_query[(size_t)NFINE*EE];
__device__ float g_mean[NFINE];
__device__ float g_rstd[NFINE];
__device__ float g_wfold[(size_t)CF*EE];
__device__ float g_dvec[EE];
__device__ float g_cvec[EE];
__device__ float g_bcat[NP];

// ================= kernel 1: LN(coarse) + gate, emit bf16 hi/lo =================
__global__ void __launch_bounds__(128) ln_coarse_gate(
    const float* __restrict__ x, const float* __restrict__ g, const float* __restrict__ b,
    const float* __restrict__ wg, const float* __restrict__ bg)
{
    int row = blockIdx.x; int t = threadIdx.x;
    const float4* xr = (const float4*)(x + (size_t)row*CC);
    float4 v = xr[t];
    float s  = v.x+v.y+v.z+v.w;
    float sq = v.x*v.x+v.y*v.y+v.z*v.z+v.w*v.w;
    #pragma unroll
    for (int o=16;o;o>>=1){ s += __shfl_xor_sync(0xffffffffu,s,o); sq += __shfl_xor_sync(0xffffffffu,sq,o); }
    __shared__ float red[8];
    int wid = t>>5, l = t&31;
    if (l==0){ red[wid]=s; red[4+wid]=sq; }
    __syncthreads();
    s  = red[0]+red[1]+red[2]+red[3];
    sq = red[4]+red[5]+red[6]+red[7];
    float mean = s*(1.f/512.f);
    float var  = sq*(1.f/512.f) - mean*mean;
    float rstd = rsqrtf(var + 1e-3f);
    float4 gv = ((const float4*)g)[t];
    float4 bv = ((const float4*)b)[t];
    float4 o;
    o.x = (v.x-mean)*rstd*gv.x + bv.x;
    o.y = (v.y-mean)*rstd*gv.y + bv.y;
    o.z = (v.z-mean)*rstd*gv.z + bv.z;
    o.w = (v.w-mean)*rstd*gv.w + bv.w;
    __nv_bfloat16 hx = __float2bfloat16_rn(o.x), hy = __float2bfloat16_rn(o.y);
    __nv_bfloat16 hz = __float2bfloat16_rn(o.z), hw = __float2bfloat16_rn(o.w);
    __nv_bfloat16 lx = __float2bfloat16_rn(o.x - __bfloat162float(hx));
    __nv_bfloat16 ly = __float2bfloat16_rn(o.y - __bfloat162float(hy));
    __nv_bfloat16 lz = __float2bfloat16_rn(o.z - __bfloat162float(hz));
    __nv_bfloat16 lw = __float2bfloat16_rn(o.w - __bfloat162float(hw));
    size_t off = (size_t)row*CC + t*4;
    __nv_bfloat162 h01; h01.x=hx; h01.y=hy;
    __nv_bfloat162 h23; h23.x=hz; h23.y=hw;
    __nv_bfloat162 l01; l01.x=lx; l01.y=ly;
    __nv_bfloat162 l23; l23.x=lz; l23.y=lw;
    uint2 uh, ulo;
    uh.x = *(unsigned*)&h01; uh.y = *(unsigned*)&h23;
    ulo.x = *(unsigned*)&l01; ulo.y = *(unsigned*)&l23;
    *(uint2*)&g_cnh[off] = uh;
    *(uint2*)&g_cnl[off] = ulo;

    float4 wv = ((const float4*)wg)[t];
    float gd = o.x*wv.x + o.y*wv.y + o.z*wv.z + o.w*wv.w;
    #pragma unroll
    for (int oo=16;oo;oo>>=1) gd += __shfl_xor_sync(0xffffffffu,gd,oo);
    __syncthreads();
    if (l==0) red[wid]=gd;
    __syncthreads();
    if (t==0){
        float tot = red[0]+red[1]+red[2]+red[3] + bg[0];
        g_gate[row] = 1.f/(1.f+__expf(-tot));
    }
}

// ================= kernel 2: fine LN stats =================
__global__ void __launch_bounds__(256) fine_stats(const float* __restrict__ x)
{
    int w = threadIdx.x>>5, l = threadIdx.x&31;
    int row = blockIdx.x*8 + w;
    const float4* xr = (const float4*)(x + (size_t)row*CF);
    float4 a = xr[l], c = xr[l+32];
    float s  = a.x+a.y+a.z+a.w + c.x+c.y+c.z+c.w;
    float sq = a.x*a.x+a.y*a.y+a.z*a.z+a.w*a.w + c.x*c.x+c.y*c.y+c.z*c.z+c.w*c.w;
    #pragma unroll
    for (int o=16;o;o>>=1){ s += __shfl_xor_sync(0xffffffffu,s,o); sq += __shfl_xor_sync(0xffffffffu,sq,o); }
    if (l==0){
        float m = s*(1.f/256.f);
        g_mean[row] = m;
        g_rstd[row] = rsqrtf(sq*(1.f/256.f) - m*m + 1e-3f);
    }
}

// ================= pack weights: W^T hi/lo bf16 + bias =================
__global__ void __launch_bounds__(384) pack_w(
    const float* __restrict__ wk, const float* __restrict__ wqc, const float* __restrict__ wv,
    const float* __restrict__ bk, const float* __restrict__ bqc, const float* __restrict__ bv)
{
    int k = blockIdx.x; int n = threadIdx.x;
    float v;
    if (n < 64)       v = wk [k*64  + n];
    else if (n < 128) v = wqc[k*64  + (n-64)];
    else              v = wv [k*256 + (n-128)];
    __nv_bfloat16 hi = __float2bfloat16_rn(v);
    __nv_bfloat16 lo = __float2bfloat16_rn(v - __bfloat162float(hi));
    g_wth[(size_t)n*CC + k] = hi;
    g_wtl[(size_t)n*CC + k] = lo;
    if (k == 0){
        float bvv = (n<64) ? bk[n] : (n<128) ? bqc[n-64] : bv[n-128];
        g_bcat[n] = bvv;
    }
}

// ================= fold LN(fine) params into w_qf =================
__global__ void __launch_bounds__(256) fold_qf(
    const float* __restrict__ wqf, const float* __restrict__ bqf,
    const float* __restrict__ g, const float* __restrict__ bb)
{
    int n = blockIdx.x; int t = threadIdx.x;
    float wv = wqf[t*EE + n];
    float wf = g[t]*wv;
    g_wfold[t*EE + n] = wf;
    float cv = bb[t]*wv;
    #pragma unroll
    for (int o=16;o;o>>=1){ wf += __shfl_xor_sync(0xffffffffu,wf,o); cv += __shfl_xor_sync(0xffffffffu,cv,o); }
    __shared__ float sd[8], sc[8];
    int wid = t>>5, l = t&31;
    if (l==0){ sd[wid]=wf; sc[wid]=cv; }
    __syncthreads();
    if (t==0){
        float dd=0.f, cc=0.f;
        #pragma unroll
        for (int i=0;i<8;i++){ dd+=sd[i]; cc+=sc[i]; }
        g_dvec[n]=dd; g_cvec[n]=cc + bqf[n];
    }
}

// ================= projection GEMM via mma.sync bf16 (hi/lo split) =================
// BM=128 BN=128 BK=32, 8 warps (4m x 2n), warp tile m32 x n64.
// Smem rows padded to 40 bf16 (80B) -> conflict-free ldmatrix.
#define SROW 40
__global__ void __launch_bounds__(256) proj_gemm()
{
    __shared__ __align__(16) __nv_bfloat16 sAh[128*SROW];
    __shared__ __align__(16) __nv_bfloat16 sAl[128*SROW];
    __shared__ __align__(16) __nv_bfloat16 sBh[128*SROW];
    __shared__ __align__(16) __nv_bfloat16 sBl[128*SROW];
    int t = threadIdx.x;
    int n0 = blockIdx.x*128, m0 = blockIdx.y*128;
    int w = t>>5, l = t&31;
    int wm = w>>1, wn = w&1;
    int m0w = wm*32, n0w = wn*64;

    // staging: thread -> (row sr, half skh)
    int sr = t>>1, skh = (t&1)*16;
    const __nv_bfloat16* gAh = g_cnh + (size_t)(m0+sr)*CC + skh;
    const __nv_bfloat16* gAl = g_cnl + (size_t)(m0+sr)*CC + skh;
    const __nv_bfloat16* gBh = g_wth + (size_t)(n0+sr)*CC + skh;
    const __nv_bfloat16* gBl = g_wtl + (size_t)(n0+sr)*CC + skh;
    __nv_bfloat16* dAh = sAh + sr*SROW + skh;
    __nv_bfloat16* dAl = sAl + sr*SROW + skh;
    __nv_bfloat16* dBh = sBh + sr*SROW + skh;
    __nv_bfloat16* dBl = sBl + sr*SROW + skh;

    uint32_t bAh = (uint32_t)__cvta_generic_to_shared(sAh);
    uint32_t bAl = (uint32_t)__cvta_generic_to_shared(sAl);
    uint32_t bBh = (uint32_t)__cvta_generic_to_shared(sBh);
    uint32_t bBl = (uint32_t)__cvta_generic_to_shared(sBl);

    float acc[2][8][4];
    #pragma unroll
    for (int mt=0;mt<2;mt++)
        #pragma unroll
        for (int nt=0;nt<8;nt++)
            #pragma unroll
            for (int i=0;i<4;i++) acc[mt][nt][i]=0.f;

    for (int c=0; c<16; c++){
        int koff = c*32;
        *(uint4*)(dAh)   = *(const uint4*)(gAh + koff);
        *(uint4*)(dAh+8) = *(const uint4*)(gAh + koff + 8);
        *(uint4*)(dAl)   = *(const uint4*)(gAl + koff);
        *(uint4*)(dAl+8) = *(const uint4*)(gAl + koff + 8);
        *(uint4*)(dBh)   = *(const uint4*)(gBh + koff);
        *(uint4*)(dBh+8) = *(const uint4*)(gBh + koff + 8);
        *(uint4*)(dBl)   = *(const uint4*)(gBl + koff);
        *(uint4*)(dBl+8) = *(const uint4*)(gBl + koff + 8);
        __syncthreads();

        #pragma unroll
        for (int ks=0; ks<2; ks++){
            int k0 = ks*16;
            // A fragments: ldmatrix x4, addr = row (m0w + l&15 [+16]) , col k0 + (l>>4)*8
            uint32_t aoff = ((m0w + (l&15))*SROW + k0 + (l>>4)*8)*2;
            uint32_t ah[2][4], al[2][4];
            LDSM4(ah[0], bAh + aoff);
            LDSM4(ah[1], bAh + aoff + 16*SROW*2);
            LDSM4(al[0], bAl + aoff);
            LDSM4(al[1], bAl + aoff + 16*SROW*2);
            // B hi fragments: x4 covers two n8 tiles (tile = l>>4, khalf = (l>>3)&1)
            uint32_t boff = ((n0w + (l>>4)*8 + (l&7))*SROW + k0 + ((l>>3)&1)*8)*2;
            uint32_t bh[8][2];
            #pragma unroll
            for (int np=0; np<4; np++){
                uint32_t r4[4];
                LDSM4(r4, bBh + boff + np*16*SROW*2);
                bh[np*2][0]=r4[0]; bh[np*2][1]=r4[1];
                bh[np*2+1][0]=r4[2]; bh[np*2+1][1]=r4[3];
            }
            #pragma unroll
            for (int mt=0; mt<2; mt++)
                #pragma unroll
                for (int nt=0; nt<8; nt++)
                    MMA16816(acc[mt][nt], ah[mt], bh[nt]);
            #pragma unroll
            for (int mt=0; mt<2; mt++)
                #pragma unroll
                for (int nt=0; nt<8; nt++)
                    MMA16816(acc[mt][nt], al[mt], bh[nt]);
            // B lo fragments (reuse regs)
            #pragma unroll
            for (int np=0; np<4; np++){
                uint32_t r4[4];
                LDSM4(r4, bBl + boff + np*16*SROW*2);
                bh[np*2][0]=r4[0]; bh[np*2][1]=r4[1];
                bh[np*2+1][0]=r4[2]; bh[np*2+1][1]=r4[3];
            }
            #pragma unroll
            for (int mt=0; mt<2; mt++)
                #pragma unroll
                for (int nt=0; nt<8; nt++)
                    MMA16816(acc[mt][nt], ah[mt], bh[nt]);
        }
        __syncthreads();
    }

    // epilogue: c0,c1 -> row g, cols 2q..; c2,c3 -> row g+8
    int g = l>>2, q = l&3;
    #pragma unroll
    for (int mt=0; mt<2; mt++){
        int row0 = m0 + m0w + mt*16 + g;
        #pragma unroll
        for (int nt=0; nt<8; nt++){
            int col = n0 + n0w + nt*8 + q*2;
            float2 b2 = *(const float2*)&g_bcat[col];
            *(float2*)&g_proj[(size_t)row0*NP + col] =
                make_float2(acc[mt][nt][0]+b2.x, acc[mt][nt][1]+b2.y);
            *(float2*)&g_proj[(size_t)(row0+8)*NP + col] =
                make_float2(acc[mt][nt][2]+b2.x, acc[mt][nt][3]+b2.y);
        }
    }
}

// ================= query GEMM with folded LN + gate blend (CUDA cores) =================
__global__ void __launch_bounds__(256) query_gemm(const float* __restrict__ fine)
{
    __shared__ __align__(16) float As[16][256];
    __shared__ __align__(16) float Bs[16][64];
    int m0 = blockIdx.x*256;
    int t = threadIdx.x;
    int kB = t>>4, n4 = (t&15)*4;
    int ty = t>>3, tx = t&7;

    const float* Aload = fine + (size_t)(m0+t)*CF;
    const float* Wload = g_wfold + (size_t)kB*EE + n4;

    ull acc[8][4];
    #pragma unroll
    for (int i=0;i<8;i++)
        #pragma unroll
        for (int j=0;j<4;j++) acc[i][j]=pk2(0.f,0.f);

    const int KB = CF/16;  // 16
    float4 ra0 = *(const float4*)(Aload);
    float4 ra1 = *(const float4*)(Aload+4);
    float4 ra2 = *(const float4*)(Aload+8);
    float4 ra3 = *(const float4*)(Aload+12);
    float4 rb  = *(const float4*)(Wload);
    for (int kb=0; kb<KB; kb++){
        As[ 0][t]=ra0.x; As[ 1][t]=ra0.y; As[ 2][t]=ra0.z; As[ 3][t]=ra0.w;
        As[ 4][t]=ra1.x; As[ 5][t]=ra1.y; As[ 6][t]=ra1.z; As[ 7][t]=ra1.w;
        As[ 8][t]=ra2.x; As[ 9][t]=ra2.y; As[10][t]=ra2.z; As[11][t]=ra2.w;
        As[12][t]=ra3.x; As[13][t]=ra3.y; As[14][t]=ra3.z; As[15][t]=ra3.w;
        *(float4*)&Bs[kB][n4] = rb;
        __syncthreads();
        if (kb+1<KB){
            const float* ap = Aload + (kb+1)*16;
            ra0 = *(const float4*)(ap);
            ra1 = *(const float4*)(ap+4);
            ra2 = *(const float4*)(ap+8);
            ra3 = *(const float4*)(ap+12);
            rb  = *(const float4*)(Wload + (size_t)(kb+1)*16*EE);
        }
        #pragma unroll
        for (int k=0;k<16;k++){
            ulonglong2 A01 = *(const ulonglong2*)&As[k][ty*8];
            ulonglong2 A23 = *(const ulonglong2*)&As[k][ty*8+4];
            ulonglong2 B0  = *(const ulonglong2*)&Bs[k][tx*4];
            ulonglong2 B1  = *(const ulonglong2*)&Bs[k][32+tx*4];
            float2 f0=upk(A01.x), f1=upk(A01.y), f2=upk(A23.x), f3=upk(A23.y);
            ull AP0=pk2(f0.x,f0.x), AP1=pk2(f0.y,f0.y), AP2=pk2(f1.x,f1.x), AP3=pk2(f1.y,f1.y);
            ull AP4=pk2(f2.x,f2.x), AP5=pk2(f2.y,f2.y), AP6=pk2(f3.x,f3.x), AP7=pk2(f3.y,f3.y);
            ffma2(acc[0][0],AP0,B0.x); ffma2(acc[0][1],AP0,B0.y); ffma2(acc[0][2],AP0,B1.x); ffma2(acc[0][3],AP0,B1.y);
            ffma2(acc[1][0],AP1,B0.x); ffma2(acc[1][1],AP1,B0.y); ffma2(acc[1][2],AP1,B1.x); ffma2(acc[1][3],AP1,B1.y);
            ffma2(acc[2][0],AP2,B0.x); ffma2(acc[2][1],AP2,B0.y); ffma2(acc[2][2],AP2,B1.x); ffma2(acc[2][3],AP2,B1.y);
            ffma2(acc[3][0],AP3,B0.x); ffma2(acc[3][1],AP3,B0.y); ffma2(acc[3][2],AP3,B1.x); ffma2(acc[3][3],AP3,B1.y);
            ffma2(acc[4][0],AP4,B0.x); ffma2(acc[4][1],AP4,B0.y); ffma2(acc[4][2],AP4,B1.x); ffma2(acc[4][3],AP4,B1.y);
            ffma2(acc[5][0],AP5,B0.x); ffma2(acc[5][1],AP5,B0.y); ffma2(acc[5][2],AP5,B1.x); ffma2(acc[5][3],AP5,B1.y);
            ffma2(acc[6][0],AP6,B0.x); ffma2(acc[6][1],AP6,B0.y); ffma2(acc[6][2],AP6,B1.x); ffma2(acc[6][3],AP6,B1.y);
            ffma2(acc[7][0],AP7,B0.x); ffma2(acc[7][1],AP7,B0.y); ffma2(acc[7][2],AP7,B1.x); ffma2(acc[7][3],AP7,B1.y);
        }
        __syncthreads();
    }

    float4 dv0 = *(const float4*)&g_dvec[tx*4];
    float4 cv0 = *(const float4*)&g_cvec[tx*4];
    float4 dv1 = *(const float4*)&g_dvec[32+tx*4];
    float4 cv1 = *(const float4*)&g_cvec[32+tx*4];
    #pragma unroll
    for (int i=0;i<8;i++){
        int m = m0 + ty*8 + i;
        float mean = g_mean[m], rstd = g_rstd[m];
        int b_ = m>>14, h = (m>>7)&127, w = m&127;
        int mc = (b_<<12) | ((h>>1)<<6) | (w>>1);
        float gt = g_gate[mc];
        float2 p0=upk(acc[i][0]), p1=upk(acc[i][1]), p2=upk(acc[i][2]), p3=upk(acc[i][3]);
        float4 u0 = make_float4(p0.x,p0.y,p1.x,p1.y);
        float4 u1 = make_float4(p2.x,p2.y,p3.x,p3.y);
        float4 qc0 = *(const float4*)&g_proj[(size_t)mc*NP + 64 + tx*4];
        float4 qc1 = *(const float4*)&g_proj[(size_t)mc*NP + 64 + 32 + tx*4];
        float4 q0, q1, o0, o1;
        q0.x = rstd*(u0.x - mean*dv0.x) + cv0.x;
        q0.y = rstd*(u0.y - mean*dv0.y) + cv0.y;
        q0.z = rstd*(u0.z - mean*dv0.z) + cv0.z;
        q0.w = rstd*(u0.w - mean*dv0.w) + cv0.w;
        q1.x = rstd*(u1.x - mean*dv1.x) + cv1.x;
        q1.y = rstd*(u1.y - mean*dv1.y) + cv1.y;
        q1.z = rstd*(u1.z - mean*dv1.z) + cv1.z;
        q1.w = rstd*(u1.w - mean*dv1.w) + cv1.w;
        o0.x = q0.x*gt + qc0.x*(1.f-gt);
        o0.y = q0.y*gt + qc0.y*(1.f-gt);
        o0.z = q0.z*gt + qc0.z*(1.f-gt);
        o0.w = q0.w*gt + qc0.w*(1.f-gt);
        o1.x = q1.x*gt + qc1.x*(1.f-gt);
        o1.y = q1.y*gt + qc1.y*(1.f-gt);
        o1.z = q1.z*gt + qc1.z*(1.f-gt);
        o1.w = q1.w*gt + qc1.w*(1.f-gt);
        *(float4*)&g_query[(size_t)m*EE + tx*4]      = o0;
        *(float4*)&g_query[(size_t)m*EE + 32 + tx*4] = o1;
    }
}

// ================= local attention =================
#define SK_STRIDE 68
#define ATT_SMEM_BYTES ((6800 + 25600 + 4096 + 64*28) * 4)
__global__ void __launch_bounds__(256) attn_kernel(float* __restrict__ out)
{
    extern __shared__ __align__(16) float sm[];
    float* sk = sm;                       // [5][20][68]
    float* sv = sm + 6800;                // [5][20][256]
    float* sq = sm + 6800 + 25600;        // [64][64]
    float* satt = sq + 4096;              // [64][28]

    int j0 = blockIdx.x * 16;
    int i  = blockIdx.y;
    int b  = blockIdx.z;
    int t = threadIdx.x;

    for (int idx = t; idx < 1600; idx += 256){
        int c4 = idx & 15, cc = (idx>>4) % 20, r = idx/320;
        int ci = i - 2 + r, cj = j0 - 2 + cc;
        float4 v = make_float4(0.f,0.f,0.f,0.f);
        if (ci>=0 && ci<HC && cj>=0 && cj<WC)
            v = *(const float4*)&g_proj[(size_t)((b*HC+ci)*WC + cj)*NP + c4*4];
        *(float4*)&sk[(r*20+cc)*SK_STRIDE + c4*4] = v;
    }
    for (int idx = t; idx < 6400; idx += 256){
        int c4 = idx & 63, cc = (idx>>6) % 20, r = idx/1280;
        int ci = i - 2 + r, cj = j0 - 2 + cc;
        float4 v = make_float4(0.f,0.f,0.f,0.f);
        if (ci>=0 && ci<HC && cj>=0 && cj<WC)
            v = *(const float4*)&g_proj[(size_t)((b*HC+ci)*WC + cj)*NP + 128 + c4*4];
        *(float4*)&sv[(r*20+cc)*256 + c4*4] = v;
    }
    for (int idx = t; idx < 1024; idx += 256){
        int c4 = idx & 15, fp = idx >> 4;
        int cp = fp>>2, q = fp&3, di = q>>1, dj = q&1;
        int h = 2*i + di, w = 2*(j0+cp) + dj;
        *(float4*)&sq[fp*64 + c4*4] =
            *(const float4*)&g_query[(((size_t)(b*HF+h)*WF + w)<<6) + c4*4];
    }
    __syncthreads();

    int wd = t>>5, l = t&31;
    int pr = l/5, pc = l - pr*5;
    for (int fi=0; fi<8; fi++){
        int fp = wd*8 + fi;
        int cp = fp>>2;
        float s = -1e30f;
        if (l < 25){
            s = 0.f;
            const float* kk = &sk[(pr*20 + cp + pc)*SK_STRIDE];
            const float* qq = &sq[fp*64];
            #pragma unroll
            for (int c4=0;c4<16;c4++){
                float4 qa = *(const float4*)(qq + c4*4);
                float4 ka = *(const float4*)(kk + c4*4);
                s += qa.x*ka.x + qa.y*ka.y + qa.z*ka.z + qa.w*ka.w;
            }
        }
        float mx = s;
        #pragma unroll
        for (int o=16;o;o>>=1) mx = fmaxf(mx, __shfl_xor_sync(0xffffffffu,mx,o));
        float e = (l<25) ? __expf(s - mx) : 0.f;
        float ssum = e;
        #pragma unroll
        for (int o=16;o;o>>=1) ssum += __shfl_xor_sync(0xffffffffu,ssum,o);
        if (l<25) satt[fp*28 + l] = e / ssum;
    }
    __syncthreads();

    int cp = t>>4, l16 = t&15;
    for (int cg=0; cg<4; cg++){
        int c = cg*64 + l16*4;
        ull acc[4][2];
        #pragma unroll
        for (int q=0;q<4;q++){ acc[q][0]=pk2(0.f,0.f); acc[q][1]=pk2(0.f,0.f); }
        #pragma unroll
        for (int p=0;p<25;p++){
            int ppr = p/5, ppc = p - ppr*5;
            const ull* vp = (const ull*)&sv[(ppr*20 + cp + ppc)*256 + c];
            ull v01 = vp[0], v23 = vp[1];
            #pragma unroll
            for (int q=0;q<4;q++){
                float a = satt[(cp*4+q)*28 + p];
                ull aP = pk2(a,a);
                ffma2(acc[q][0], aP, v01);
                ffma2(acc[q][1], aP, v23);
            }
        }
        #pragma unroll
        for (int q=0;q<4;q++){
            int di=q>>1, dj=q&1;
            int h = 2*i+di, w = 2*(j0+cp)+dj;
            float2 u0=upk(acc[q][0]), u1=upk(acc[q][1]);
            float4 o = make_float4(u0.x,u0.y,u1.x,u1.y);
            *(float4*)&out[(((size_t)(b*HF+h)*WF + w)<<8) + c] = o;
        }
    }
}

// ================= launch =================
extern "C" void kernel_launch(void* const* d_in, const int* in_sizes, int n_in,
                              void* d_out, int out_size)
{
    (void)in_sizes; (void)n_in; (void)out_size;
    const float* fine   = (const float*)d_in[0];
    const float* coarse = (const float*)d_in[1];
    const float* ln_f_g = (const float*)d_in[2];
    const float* ln_f_b = (const float*)d_in[3];
    const float* ln_c_g = (const float*)d_in[4];
    const float* ln_c_b = (const float*)d_in[5];
    const float* w_gate = (const float*)d_in[6];
    const float* b_gate = (const float*)d_in[7];
    const float* w_qf   = (const float*)d_in[8];
    const float* b_qf   = (const float*)d_in[9];
    const float* w_qc   = (const float*)d_in[10];
    const float* b_qc   = (const float*)d_in[11];
    const float* w_k    = (const float*)d_in[12];
    const float* b_k    = (const float*)d_in[13];
    const float* w_v    = (const float*)d_in[14];
    const float* b_v    = (const float*)d_in[15];
    float* out = (float*)d_out;

    ln_coarse_gate<<<NCOARSE, 128>>>(coarse, ln_c_g, ln_c_b, w_gate, b_gate);   // 1
    pack_w<<<CC, NP>>>(w_k, w_qc, w_v, b_k, b_qc, b_v);                          // 2
    fine_stats<<<NFINE/8, 256>>>(fine);                                          // 3
    proj_gemm<<<dim3(NP/128, NCOARSE/128), 256>>>();                             // 4  <- profiled slot
    fold_qf<<<EE, 256>>>(w_qf, b_qf, ln_f_g, ln_f_b);                            // 5
    query_gemm<<<NFINE/256, 256>>>(fine);                                        // 6
    cudaFuncSetAttribute(attn_kernel, cudaFuncAttributeMaxDynamicSharedMemorySize, ATT_SMEM_BYTES);
    attn_kernel<<<dim3(WC/16, HC, BB), 256, ATT_SMEM_BYTES>>>(out);              // 7
}

// round 9
// speedup vs baseline: 1.5092x; 1.0755x over previous
#include <cuda_runtime.h>
#include <cuda_bf16.h>
#include <cstdint>
#include <cstddef>

typedef unsigned long long ull;

__device__ __forceinline__ void ffma2(ull& d, ull a, ull b){
    asm("fma.rn.f32x2 %0, %1, %2, %0;" : "+l"(d) : "l"(a), "l"(b));
}
__device__ __forceinline__ ull pk2(float x, float y){
    ull r; asm("mov.b64 %0, {%1, %2};" : "=l"(r) : "f"(x), "f"(y)); return r;
}
__device__ __forceinline__ float2 upk(ull a){
    float2 r; asm("mov.b64 {%0, %1}, %2;" : "=f"(r.x), "=f"(r.y) : "l"(a)); return r;
}

#define LDSM4(r, addr) asm volatile( \
    "ldmatrix.sync.aligned.m8n8.x4.shared.b16 {%0,%1,%2,%3}, [%4];" \
    : "=r"((r)[0]),"=r"((r)[1]),"=r"((r)[2]),"=r"((r)[3]) : "r"(addr))

#define MMA16816(c, a, b) asm volatile( \
    "mma.sync.aligned.m16n8k16.row.col.f32.bf16.bf16.f32 " \
    "{%0,%1,%2,%3}, {%4,%5,%6,%7}, {%8,%9}, {%0,%1,%2,%3};" \
    : "+f"((c)[0]),"+f"((c)[1]),"+f"((c)[2]),"+f"((c)[3]) \
    : "r"((a)[0]),"r"((a)[1]),"r"((a)[2]),"r"((a)[3]), "r"((b)[0]),"r"((b)[1]))

#define CP16(dst, src) asm volatile( \
    "cp.async.cg.shared.global [%0], [%1], 16;" :: "r"(dst), "l"(src))

// ---------------- fixed shapes ----------------
#define BB 4
#define HF 128
#define WF 128
#define CF 256
#define HC 64
#define WC 64
#define CC 512
#define EE 64
#define FF 256
#define NP 384
#define NCOARSE (BB*HC*WC)   // 16384
#define NFINE   (BB*HF*WF)   // 65536

// ---------------- scratch ----------------
__device__ __nv_bfloat16 g_cnh[(size_t)NCOARSE*CC];  // LN(coarse) hi  [m][k]
__device__ __nv_bfloat16 g_cnl[(size_t)NCOARSE*CC];  // LN(coarse) lo
__device__ __nv_bfloat16 g_wth[(size_t)NP*CC];       // W^T hi  [n][k]
__device__ __nv_bfloat16 g_wtl[(size_t)NP*CC];       // W^T lo
__device__ float g_gate[NCOARSE];
__device__ float g_proj[(size_t)NCOARSE*NP];   // fused k|qc|v
__device__ float g_query[(size_t)NFINE*EE];
__device__ float g_mean[NFINE];
__device__ float g_rstd[NFINE];
__device__ float g_wfold[(size_t)CF*EE];
__device__ float g_dvec[EE];
__device__ float g_cvec[EE];
__device__ float g_bcat[NP];

// ================= kernel 1: LN(coarse) + gate, emit bf16 hi/lo =================
__global__ void __launch_bounds__(128) ln_coarse_gate(
    const float* __restrict__ x, const float* __restrict__ g, const float* __restrict__ b,
    const float* __restrict__ wg, const float* __restrict__ bg)
{
    int row = blockIdx.x; int t = threadIdx.x;
    const float4* xr = (const float4*)(x + (size_t)row*CC);
    float4 v = xr[t];
    float s  = v.x+v.y+v.z+v.w;
    float sq = v.x*v.x+v.y*v.y+v.z*v.z+v.w*v.w;
    #pragma unroll
    for (int o=16;o;o>>=1){ s += __shfl_xor_sync(0xffffffffu,s,o); sq += __shfl_xor_sync(0xffffffffu,sq,o); }
    __shared__ float red[8];
    int wid = t>>5, l = t&31;
    if (l==0){ red[wid]=s; red[4+wid]=sq; }
    __syncthreads();
    s  = red[0]+red[1]+red[2]+red[3];
    sq = red[4]+red[5]+red[6]+red[7];
    float mean = s*(1.f/512.f);
    float var  = sq*(1.f/512.f) - mean*mean;
    float rstd = rsqrtf(var + 1e-3f);
    float4 gv = ((const float4*)g)[t];
    float4 bv = ((const float4*)b)[t];
    float4 o;
    o.x = (v.x-mean)*rstd*gv.x + bv.x;
    o.y = (v.y-mean)*rstd*gv.y + bv.y;
    o.z = (v.z-mean)*rstd*gv.z + bv.z;
    o.w = (v.w-mean)*rstd*gv.w + bv.w;
    __nv_bfloat16 hx = __float2bfloat16_rn(o.x), hy = __float2bfloat16_rn(o.y);
    __nv_bfloat16 hz = __float2bfloat16_rn(o.z), hw = __float2bfloat16_rn(o.w);
    __nv_bfloat16 lx = __float2bfloat16_rn(o.x - __bfloat162float(hx));
    __nv_bfloat16 ly = __float2bfloat16_rn(o.y - __bfloat162float(hy));
    __nv_bfloat16 lz = __float2bfloat16_rn(o.z - __bfloat162float(hz));
    __nv_bfloat16 lw = __float2bfloat16_rn(o.w - __bfloat162float(hw));
    size_t off = (size_t)row*CC + t*4;
    __nv_bfloat162 h01; h01.x=hx; h01.y=hy;
    __nv_bfloat162 h23; h23.x=hz; h23.y=hw;
    __nv_bfloat162 l01; l01.x=lx; l01.y=ly;
    __nv_bfloat162 l23; l23.x=lz; l23.y=lw;
    uint2 uh, ulo;
    uh.x = *(unsigned*)&h01; uh.y = *(unsigned*)&h23;
    ulo.x = *(unsigned*)&l01; ulo.y = *(unsigned*)&l23;
    *(uint2*)&g_cnh[off] = uh;
    *(uint2*)&g_cnl[off] = ulo;

    float4 wv = ((const float4*)wg)[t];
    float gd = o.x*wv.x + o.y*wv.y + o.z*wv.z + o.w*wv.w;
    #pragma unroll
    for (int oo=16;oo;oo>>=1) gd += __shfl_xor_sync(0xffffffffu,gd,oo);
    __syncthreads();
    if (l==0) red[wid]=gd;
    __syncthreads();
    if (t==0){
        float tot = red[0]+red[1]+red[2]+red[3] + bg[0];
        g_gate[row] = 1.f/(1.f+__expf(-tot));
    }
}

// ================= kernel 2: fine LN stats =================
__global__ void __launch_bounds__(256) fine_stats(const float* __restrict__ x)
{
    int w = threadIdx.x>>5, l = threadIdx.x&31;
    int row = blockIdx.x*8 + w;
    const float4* xr = (const float4*)(x + (size_t)row*CF);
    float4 a = xr[l], c = xr[l+32];
    float s  = a.x+a.y+a.z+a.w + c.x+c.y+c.z+c.w;
    float sq = a.x*a.x+a.y*a.y+a.z*a.z+a.w*a.w + c.x*c.x+c.y*c.y+c.z*c.z+c.w*c.w;
    #pragma unroll
    for (int o=16;o;o>>=1){ s += __shfl_xor_sync(0xffffffffu,s,o); sq += __shfl_xor_sync(0xffffffffu,sq,o); }
    if (l==0){
        float m = s*(1.f/256.f);
        g_mean[row] = m;
        g_rstd[row] = rsqrtf(sq*(1.f/256.f) - m*m + 1e-3f);
    }
}

// ================= pack weights: W^T hi/lo bf16 + bias =================
__global__ void __launch_bounds__(384) pack_w(
    const float* __restrict__ wk, const float* __restrict__ wqc, const float* __restrict__ wv,
    const float* __restrict__ bk, const float* __restrict__ bqc, const float* __restrict__ bv)
{
    int k = blockIdx.x; int n = threadIdx.x;
    float v;
    if (n < 64)       v = wk [k*64  + n];
    else if (n < 128) v = wqc[k*64  + (n-64)];
    else              v = wv [k*256 + (n-128)];
    __nv_bfloat16 hi = __float2bfloat16_rn(v);
    __nv_bfloat16 lo = __float2bfloat16_rn(v - __bfloat162float(hi));
    g_wth[(size_t)n*CC + k] = hi;
    g_wtl[(size_t)n*CC + k] = lo;
    if (k == 0){
        float bvv = (n<64) ? bk[n] : (n<128) ? bqc[n-64] : bv[n-128];
        g_bcat[n] = bvv;
    }
}

// ================= fold LN(fine) params into w_qf =================
__global__ void __launch_bounds__(256) fold_qf(
    const float* __restrict__ wqf, const float* __restrict__ bqf,
    const float* __restrict__ g, const float* __restrict__ bb)
{
    int n = blockIdx.x; int t = threadIdx.x;
    float wv = wqf[t*EE + n];
    float wf = g[t]*wv;
    g_wfold[t*EE + n] = wf;
    float cv = bb[t]*wv;
    #pragma unroll
    for (int o=16;o;o>>=1){ wf += __shfl_xor_sync(0xffffffffu,wf,o); cv += __shfl_xor_sync(0xffffffffu,cv,o); }
    __shared__ float sd[8], sc[8];
    int wid = t>>5, l = t&31;
    if (l==0){ sd[wid]=wf; sc[wid]=cv; }
    __syncthreads();
    if (t==0){
        float dd=0.f, cc=0.f;
        #pragma unroll
        for (int i=0;i<8;i++){ dd+=sd[i]; cc+=sc[i]; }
        g_dvec[n]=dd; g_cvec[n]=cc + bqf[n];
    }
}

// ================= projection GEMM via mma.sync bf16 (hi/lo split), cp.async double-buffered =================
// BM=128 BN=128 BK=32, 8 warps (4m x 2n), warp tile m32 x n64.
// Smem rows padded to 40 bf16 (80B). Per buffer: 4 arrays x 10240B = 40960B; 2 buffers = 81920B dynamic.
#define SROW 40
#define ARR 10240
#define PBUF 40960
#define PROJ_SMEM 81920
__global__ void __launch_bounds__(256) proj_gemm()
{
    extern __shared__ __align__(16) char smraw[];
    uint32_t sb = (uint32_t)__cvta_generic_to_shared(smraw);
    int t = threadIdx.x;
    int n0 = blockIdx.x*128, m0 = blockIdx.y*128;
    int w = t>>5, l = t&31;
    int wm = w>>1, wn = w&1;
    int m0w = wm*32, n0w = wn*64;

    // staging: thread -> (row sr, 16-elem half skh)
    int sr = t>>1, skh = (t&1)*16;
    const __nv_bfloat16* gAh = g_cnh + (size_t)(m0+sr)*CC + skh;
    const __nv_bfloat16* gAl = g_cnl + (size_t)(m0+sr)*CC + skh;
    const __nv_bfloat16* gBh = g_wth + (size_t)(n0+sr)*CC + skh;
    const __nv_bfloat16* gBl = g_wtl + (size_t)(n0+sr)*CC + skh;
    uint32_t doff = (uint32_t)(sr*SROW + skh)*2;   // byte offset within one array

    float acc[2][8][4];
    #pragma unroll
    for (int mt=0;mt<2;mt++)
        #pragma unroll
        for (int nt=0;nt<8;nt++)
            #pragma unroll
            for (int i=0;i<4;i++) acc[mt][nt][i]=0.f;

    // prefetch chunk 0 into buffer 0
    {
        uint32_t d = sb + doff;
        CP16(d,            gAh);    CP16(d+16,            gAh+8);
        CP16(d+ARR,        gAl);    CP16(d+ARR+16,        gAl+8);
        CP16(d+2*ARR,      gBh);    CP16(d+2*ARR+16,      gBh+8);
        CP16(d+3*ARR,      gBl);    CP16(d+3*ARR+16,      gBl+8);
        asm volatile("cp.async.commit_group;" ::: "memory");
    }

    for (int c=0; c<16; c++){
        asm volatile("cp.async.wait_group 0;" ::: "memory");
        __syncthreads();
        if (c+1<16){
            int s = (c+1)&1;
            uint32_t d = sb + s*PBUF + doff;
            int koff = (c+1)*32;
            CP16(d,            gAh+koff);    CP16(d+16,            gAh+koff+8);
            CP16(d+ARR,        gAl+koff);    CP16(d+ARR+16,        gAl+koff+8);
            CP16(d+2*ARR,      gBh+koff);    CP16(d+2*ARR+16,      gBh+koff+8);
            CP16(d+3*ARR,      gBl+koff);    CP16(d+3*ARR+16,      gBl+koff+8);
            asm volatile("cp.async.commit_group;" ::: "memory");
        }
        uint32_t bAh = sb + (c&1)*PBUF;
        uint32_t bAl = bAh + ARR;
        uint32_t bBh = bAh + 2*ARR;
        uint32_t bBl = bAh + 3*ARR;

        #pragma unroll
        for (int ks=0; ks<2; ks++){
            int k0 = ks*16;
            uint32_t aoff = ((m0w + (l&15))*SROW + k0 + (l>>4)*8)*2;
            uint32_t ah[2][4], al[2][4];
            LDSM4(ah[0], bAh + aoff);
            LDSM4(ah[1], bAh + aoff + 16*SROW*2);
            LDSM4(al[0], bAl + aoff);
            LDSM4(al[1], bAl + aoff + 16*SROW*2);
            uint32_t boff = ((n0w + (l>>4)*8 + (l&7))*SROW + k0 + ((l>>3)&1)*8)*2;
            uint32_t bh[8][2];
            #pragma unroll
            for (int np=0; np<4; np++){
                uint32_t r4[4];
                LDSM4(r4, bBh + boff + np*16*SROW*2);
                bh[np*2][0]=r4[0]; bh[np*2][1]=r4[1];
                bh[np*2+1][0]=r4[2]; bh[np*2+1][1]=r4[3];
            }
            #pragma unroll
            for (int mt=0; mt<2; mt++)
                #pragma unroll
                for (int nt=0; nt<8; nt++)
                    MMA16816(acc[mt][nt], ah[mt], bh[nt]);
            #pragma unroll
            for (int mt=0; mt<2; mt++)
                #pragma unroll
                for (int nt=0; nt<8; nt++)
                    MMA16816(acc[mt][nt], al[mt], bh[nt]);
            #pragma unroll
            for (int np=0; np<4; np++){
                uint32_t r4[4];
                LDSM4(r4, bBl + boff + np*16*SROW*2);
                bh[np*2][0]=r4[0]; bh[np*2][1]=r4[1];
                bh[np*2+1][0]=r4[2]; bh[np*2+1][1]=r4[3];
            }
            #pragma unroll
            for (int mt=0; mt<2; mt++)
                #pragma unroll
                for (int nt=0; nt<8; nt++)
                    MMA16816(acc[mt][nt], ah[mt], bh[nt]);
        }
        __syncthreads();
    }

    int g = l>>2, q = l&3;
    #pragma unroll
    for (int mt=0; mt<2; mt++){
        int row0 = m0 + m0w + mt*16 + g;
        #pragma unroll
        for (int nt=0; nt<8; nt++){
            int col = n0 + n0w + nt*8 + q*2;
            float2 b2 = *(const float2*)&g_bcat[col];
            *(float2*)&g_proj[(size_t)row0*NP + col] =
                make_float2(acc[mt][nt][0]+b2.x, acc[mt][nt][1]+b2.y);
            *(float2*)&g_proj[(size_t)(row0+8)*NP + col] =
                make_float2(acc[mt][nt][2]+b2.x, acc[mt][nt][3]+b2.y);
        }
    }
}

// ================= query GEMM with folded LN + gate blend (CUDA cores) =================
__global__ void __launch_bounds__(256) query_gemm(const float* __restrict__ fine)
{
    __shared__ __align__(16) float As[16][256];
    __shared__ __align__(16) float Bs[16][64];
    int m0 = blockIdx.x*256;
    int t = threadIdx.x;
    int kB = t>>4, n4 = (t&15)*4;
    int ty = t>>3, tx = t&7;

    const float* Aload = fine + (size_t)(m0+t)*CF;
    const float* Wload = g_wfold + (size_t)kB*EE + n4;

    ull acc[8][4];
    #pragma unroll
    for (int i=0;i<8;i++)
        #pragma unroll
        for (int j=0;j<4;j++) acc[i][j]=pk2(0.f,0.f);

    const int KB = CF/16;  // 16
    float4 ra0 = *(const float4*)(Aload);
    float4 ra1 = *(const float4*)(Aload+4);
    float4 ra2 = *(const float4*)(Aload+8);
    float4 ra3 = *(const float4*)(Aload+12);
    float4 rb  = *(const float4*)(Wload);
    for (int kb=0; kb<KB; kb++){
        As[ 0][t]=ra0.x; As[ 1][t]=ra0.y; As[ 2][t]=ra0.z; As[ 3][t]=ra0.w;
        As[ 4][t]=ra1.x; As[ 5][t]=ra1.y; As[ 6][t]=ra1.z; As[ 7][t]=ra1.w;
        As[ 8][t]=ra2.x; As[ 9][t]=ra2.y; As[10][t]=ra2.z; As[11][t]=ra2.w;
        As[12][t]=ra3.x; As[13][t]=ra3.y; As[14][t]=ra3.z; As[15][t]=ra3.w;
        *(float4*)&Bs[kB][n4] = rb;
        __syncthreads();
        if (kb+1<KB){
            const float* ap = Aload + (kb+1)*16;
            ra0 = *(const float4*)(ap);
            ra1 = *(const float4*)(ap+4);
            ra2 = *(const float4*)(ap+8);
            ra3 = *(const float4*)(ap+12);
            rb  = *(const float4*)(Wload + (size_t)(kb+1)*16*EE);
        }
        #pragma unroll
        for (int k=0;k<16;k++){
            ulonglong2 A01 = *(const ulonglong2*)&As[k][ty*8];
            ulonglong2 A23 = *(const ulonglong2*)&As[k][ty*8+4];
            ulonglong2 B0  = *(const ulonglong2*)&Bs[k][tx*4];
            ulonglong2 B1  = *(const ulonglong2*)&Bs[k][32+tx*4];
            float2 f0=upk(A01.x), f1=upk(A01.y), f2=upk(A23.x), f3=upk(A23.y);
            ull AP0=pk2(f0.x,f0.x), AP1=pk2(f0.y,f0.y), AP2=pk2(f1.x,f1.x), AP3=pk2(f1.y,f1.y);
            ull AP4=pk2(f2.x,f2.x), AP5=pk2(f2.y,f2.y), AP6=pk2(f3.x,f3.x), AP7=pk2(f3.y,f3.y);
            ffma2(acc[0][0],AP0,B0.x); ffma2(acc[0][1],AP0,B0.y); ffma2(acc[0][2],AP0,B1.x); ffma2(acc[0][3],AP0,B1.y);
            ffma2(acc[1][0],AP1,B0.x); ffma2(acc[1][1],AP1,B0.y); ffma2(acc[1][2],AP1,B1.x); ffma2(acc[1][3],AP1,B1.y);
            ffma2(acc[2][0],AP2,B0.x); ffma2(acc[2][1],AP2,B0.y); ffma2(acc[2][2],AP2,B1.x); ffma2(acc[2][3],AP2,B1.y);
            ffma2(acc[3][0],AP3,B0.x); ffma2(acc[3][1],AP3,B0.y); ffma2(acc[3][2],AP3,B1.x); ffma2(acc[3][3],AP3,B1.y);
            ffma2(acc[4][0],AP4,B0.x); ffma2(acc[4][1],AP4,B0.y); ffma2(acc[4][2],AP4,B1.x); ffma2(acc[4][3],AP4,B1.y);
            ffma2(acc[5][0],AP5,B0.x); ffma2(acc[5][1],AP5,B0.y); ffma2(acc[5][2],AP5,B1.x); ffma2(acc[5][3],AP5,B1.y);
            ffma2(acc[6][0],AP6,B0.x); ffma2(acc[6][1],AP6,B0.y); ffma2(acc[6][2],AP6,B1.x); ffma2(acc[6][3],AP6,B1.y);
            ffma2(acc[7][0],AP7,B0.x); ffma2(acc[7][1],AP7,B0.y); ffma2(acc[7][2],AP7,B1.x); ffma2(acc[7][3],AP7,B1.y);
        }
        __syncthreads();
    }

    float4 dv0 = *(const float4*)&g_dvec[tx*4];
    float4 cv0 = *(const float4*)&g_cvec[tx*4];
    float4 dv1 = *(const float4*)&g_dvec[32+tx*4];
    float4 cv1 = *(const float4*)&g_cvec[32+tx*4];
    #pragma unroll
    for (int i=0;i<8;i++){
        int m = m0 + ty*8 + i;
        float mean = g_mean[m], rstd = g_rstd[m];
        int b_ = m>>14, h = (m>>7)&127, w = m&127;
        int mc = (b_<<12) | ((h>>1)<<6) | (w>>1);
        float gt = g_gate[mc];
        float2 p0=upk(acc[i][0]), p1=upk(acc[i][1]), p2=upk(acc[i][2]), p3=upk(acc[i][3]);
        float4 u0 = make_float4(p0.x,p0.y,p1.x,p1.y);
        float4 u1 = make_float4(p2.x,p2.y,p3.x,p3.y);
        float4 qc0 = *(const float4*)&g_proj[(size_t)mc*NP + 64 + tx*4];
        float4 qc1 = *(const float4*)&g_proj[(size_t)mc*NP + 64 + 32 + tx*4];
        float4 q0, q1, o0, o1;
        q0.x = rstd*(u0.x - mean*dv0.x) + cv0.x;
        q0.y = rstd*(u0.y - mean*dv0.y) + cv0.y;
        q0.z = rstd*(u0.z - mean*dv0.z) + cv0.z;
        q0.w = rstd*(u0.w - mean*dv0.w) + cv0.w;
        q1.x = rstd*(u1.x - mean*dv1.x) + cv1.x;
        q1.y = rstd*(u1.y - mean*dv1.y) + cv1.y;
        q1.z = rstd*(u1.z - mean*dv1.z) + cv1.z;
        q1.w = rstd*(u1.w - mean*dv1.w) + cv1.w;
        o0.x = q0.x*gt + qc0.x*(1.f-gt);
        o0.y = q0.y*gt + qc0.y*(1.f-gt);
        o0.z = q0.z*gt + qc0.z*(1.f-gt);
        o0.w = q0.w*gt + qc0.w*(1.f-gt);
        o1.x = q1.x*gt + qc1.x*(1.f-gt);
        o1.y = q1.y*gt + qc1.y*(1.f-gt);
        o1.z = q1.z*gt + qc1.z*(1.f-gt);
        o1.w = q1.w*gt + qc1.w*(1.f-gt);
        *(float4*)&g_query[(size_t)m*EE + tx*4]      = o0;
        *(float4*)&g_query[(size_t)m*EE + 32 + tx*4] = o1;
    }
}

// ================= local attention =================
#define SK_STRIDE 68
#define ATT_SMEM_BYTES ((6800 + 25600 + 4096 + 64*28) * 4)
__global__ void __launch_bounds__(256) attn_kernel(float* __restrict__ out)
{
    extern __shared__ __align__(16) float sm[];
    float* sk = sm;                       // [5][20][68]
    float* sv = sm + 6800;                // [5][20][256]
    float* sq = sm + 6800 + 25600;        // [64][64]
    float* satt = sq + 4096;              // [64][28]

    int j0 = blockIdx.x * 16;
    int i  = blockIdx.y;
    int b  = blockIdx.z;
    int t = threadIdx.x;

    for (int idx = t; idx < 1600; idx += 256){
        int c4 = idx & 15, cc = (idx>>4) % 20, r = idx/320;
        int ci = i - 2 + r, cj = j0 - 2 + cc;
        float4 v = make_float4(0.f,0.f,0.f,0.f);
        if (ci>=0 && ci<HC && cj>=0 && cj<WC)
            v = *(const float4*)&g_proj[(size_t)((b*HC+ci)*WC + cj)*NP + c4*4];
        *(float4*)&sk[(r*20+cc)*SK_STRIDE + c4*4] = v;
    }
    for (int idx = t; idx < 6400; idx += 256){
        int c4 = idx & 63, cc = (idx>>6) % 20, r = idx/1280;
        int ci = i - 2 + r, cj = j0 - 2 + cc;
        float4 v = make_float4(0.f,0.f,0.f,0.f);
        if (ci>=0 && ci<HC && cj>=0 && cj<WC)
            v = *(const float4*)&g_proj[(size_t)((b*HC+ci)*WC + cj)*NP + 128 + c4*4];
        *(float4*)&sv[(r*20+cc)*256 + c4*4] = v;
    }
    for (int idx = t; idx < 1024; idx += 256){
        int c4 = idx & 15, fp = idx >> 4;
        int cp = fp>>2, q = fp&3, di = q>>1, dj = q&1;
        int h = 2*i + di, w = 2*(j0+cp) + dj;
        *(float4*)&sq[fp*64 + c4*4] =
            *(const float4*)&g_query[(((size_t)(b*HF+h)*WF + w)<<6) + c4*4];
    }
    __syncthreads();

    int wd = t>>5, l = t&31;
    int pr = l/5, pc = l - pr*5;
    for (int fi=0; fi<8; fi++){
        int fp = wd*8 + fi;
        int cp = fp>>2;
        float s = -1e30f;
        if (l < 25){
            s = 0.f;
            const float* kk = &sk[(pr*20 + cp + pc)*SK_STRIDE];
            const float* qq = &sq[fp*64];
            #pragma unroll
            for (int c4=0;c4<16;c4++){
                float4 qa = *(const float4*)(qq + c4*4);
                float4 ka = *(const float4*)(kk + c4*4);
                s += qa.x*ka.x + qa.y*ka.y + qa.z*ka.z + qa.w*ka.w;
            }
        }
        float mx = s;
        #pragma unroll
        for (int o=16;o;o>>=1) mx = fmaxf(mx, __shfl_xor_sync(0xffffffffu,mx,o));
        float e = (l<25) ? __expf(s - mx) : 0.f;
        float ssum = e;
        #pragma unroll
        for (int o=16;o;o>>=1) ssum += __shfl_xor_sync(0xffffffffu,ssum,o);
        if (l<25) satt[fp*28 + l] = e / ssum;
    }
    __syncthreads();

    int cp = t>>4, l16 = t&15;
    for (int cg=0; cg<4; cg++){
        int c = cg*64 + l16*4;
        ull acc[4][2];
        #pragma unroll
        for (int q=0;q<4;q++){ acc[q][0]=pk2(0.f,0.f); acc[q][1]=pk2(0.f,0.f); }
        #pragma unroll
        for (int p=0;p<25;p++){
            int ppr = p/5, ppc = p - ppr*5;
            const ull* vp = (const ull*)&sv[(ppr*20 + cp + ppc)*256 + c];
            ull v01 = vp[0], v23 = vp[1];
            #pragma unroll
            for (int q=0;q<4;q++){
                float a = satt[(cp*4+q)*28 + p];
                ull aP = pk2(a,a);
                ffma2(acc[q][0], aP, v01);
                ffma2(acc[q][1], aP, v23);
            }
        }
        #pragma unroll
        for (int q=0;q<4;q++){
            int di=q>>1, dj=q&1;
            int h = 2*i+di, w = 2*(j0+cp)+dj;
            float2 u0=upk(acc[q][0]), u1=upk(acc[q][1]);
            float4 o = make_float4(u0.x,u0.y,u1.x,u1.y);
            *(float4*)&out[(((size_t)(b*HF+h)*WF + w)<<8) + c] = o;
        }
    }
}

// ================= launch =================
extern "C" void kernel_launch(void* const* d_in, const int* in_sizes, int n_in,
                              void* d_out, int out_size)
{
    (void)in_sizes; (void)n_in; (void)out_size;
    const float* fine   = (const float*)d_in[0];
    const float* coarse = (const float*)d_in[1];
    const float* ln_f_g = (const float*)d_in[2];
    const float* ln_f_b = (const float*)d_in[3];
    const float* ln_c_g = (const float*)d_in[4];
    const float* ln_c_b = (const float*)d_in[5];
    const float* w_gate = (const float*)d_in[6];
    const float* b_gate = (const float*)d_in[7];
    const float* w_qf   = (const float*)d_in[8];
    const float* b_qf   = (const float*)d_in[9];
    const float* w_qc   = (const float*)d_in[10];
    const float* b_qc   = (const float*)d_in[11];
    const float* w_k    = (const float*)d_in[12];
    const float* b_k    = (const float*)d_in[13];
    const float* w_v    = (const float*)d_in[14];
    const float* b_v    = (const float*)d_in[15];
    float* out = (float*)d_out;

    ln_coarse_gate<<<NCOARSE, 128>>>(coarse, ln_c_g, ln_c_b, w_gate, b_gate);   // 1
    pack_w<<<CC, NP>>>(w_k, w_qc, w_v, b_k, b_qc, b_v);                          // 2
    fine_stats<<<NFINE/8, 256>>>(fine);                                          // 3
    cudaFuncSetAttribute(proj_gemm, cudaFuncAttributeMaxDynamicSharedMemorySize, PROJ_SMEM);
    proj_gemm<<<dim3(NP/128, NCOARSE/128), 256, PROJ_SMEM>>>();                  // 4  <- profiled slot
    fold_qf<<<EE, 256>>>(w_qf, b_qf, ln_f_g, ln_f_b);                            // 5
    query_gemm<<<NFINE/256, 256>>>(fine);                                        // 6
    cudaFuncSetAttribute(attn_kernel, cudaFuncAttributeMaxDynamicSharedMemorySize, ATT_SMEM_BYTES);
    attn_kernel<<<dim3(WC/16, HC, BB), 256, ATT_SMEM_BYTES>>>(out);              // 7
}

// round 10
// speedup vs baseline: 1.5788x; 1.0462x over previous
#include <cuda_runtime.h>
#include <cuda_bf16.h>
#include <cstdint>
#include <cstddef>

typedef unsigned long long ull;

__device__ __forceinline__ void ffma2(ull& d, ull a, ull b){
    asm("fma.rn.f32x2 %0, %1, %2, %0;" : "+l"(d) : "l"(a), "l"(b));
}
__device__ __forceinline__ ull pk2(float x, float y){
    ull r; asm("mov.b64 %0, {%1, %2};" : "=l"(r) : "f"(x), "f"(y)); return r;
}
__device__ __forceinline__ float2 upk(ull a){
    float2 r; asm("mov.b64 {%0, %1}, %2;" : "=f"(r.x), "=f"(r.y) : "l"(a)); return r;
}

#define LDSM4(r, addr) asm volatile( \
    "ldmatrix.sync.aligned.m8n8.x4.shared.b16 {%0,%1,%2,%3}, [%4];" \
    : "=r"((r)[0]),"=r"((r)[1]),"=r"((r)[2]),"=r"((r)[3]) : "r"(addr))

#define MMA16816(c, a, b) asm volatile( \
    "mma.sync.aligned.m16n8k16.row.col.f32.bf16.bf16.f32 " \
    "{%0,%1,%2,%3}, {%4,%5,%6,%7}, {%8,%9}, {%0,%1,%2,%3};" \
    : "+f"((c)[0]),"+f"((c)[1]),"+f"((c)[2]),"+f"((c)[3]) \
    : "r"((a)[0]),"r"((a)[1]),"r"((a)[2]),"r"((a)[3]), "r"((b)[0]),"r"((b)[1]))

#define CP16(dst, src) asm volatile( \
    "cp.async.cg.shared.global [%0], [%1], 16;" :: "r"(dst), "l"(src))

// ---------------- fixed shapes ----------------
#define BB 4
#define HF 128
#define WF 128
#define CF 256
#define HC 64
#define WC 64
#define CC 512
#define EE 64
#define FF 256
#define NP 384
#define NCOARSE (BB*HC*WC)   // 16384
#define NFINE   (BB*HF*WF)   // 65536

// ---------------- scratch ----------------
__device__ __nv_bfloat16 g_cnh[(size_t)NCOARSE*CC];  // LN(coarse) hi  [m][k]
__device__ __nv_bfloat16 g_cnl[(size_t)NCOARSE*CC];  // LN(coarse) lo
__device__ __nv_bfloat16 g_wth[(size_t)NP*CC];       // W^T hi  [n][k]
__device__ __nv_bfloat16 g_wtl[(size_t)NP*CC];       // W^T lo
__device__ float g_gate[NCOARSE];
__device__ float g_proj[(size_t)NCOARSE*NP];   // fused k|qc|v
__device__ float g_query[(size_t)NFINE*EE];
__device__ float g_mean[NFINE];
__device__ float g_rstd[NFINE];
__device__ float g_wfold[(size_t)CF*EE];
__device__ float g_dvec[EE];
__device__ float g_cvec[EE];
__device__ float g_bcat[NP];

// ================= kernel 1: LN(coarse) + gate, emit bf16 hi/lo =================
__global__ void __launch_bounds__(128) ln_coarse_gate(
    const float* __restrict__ x, const float* __restrict__ g, const float* __restrict__ b,
    const float* __restrict__ wg, const float* __restrict__ bg)
{
    int row = blockIdx.x; int t = threadIdx.x;
    const float4* xr = (const float4*)(x + (size_t)row*CC);
    float4 v = xr[t];
    float s  = v.x+v.y+v.z+v.w;
    float sq = v.x*v.x+v.y*v.y+v.z*v.z+v.w*v.w;
    #pragma unroll
    for (int o=16;o;o>>=1){ s += __shfl_xor_sync(0xffffffffu,s,o); sq += __shfl_xor_sync(0xffffffffu,sq,o); }
    __shared__ float red[8];
    int wid = t>>5, l = t&31;
    if (l==0){ red[wid]=s; red[4+wid]=sq; }
    __syncthreads();
    s  = red[0]+red[1]+red[2]+red[3];
    sq = red[4]+red[5]+red[6]+red[7];
    float mean = s*(1.f/512.f);
    float var  = sq*(1.f/512.f) - mean*mean;
    float rstd = rsqrtf(var + 1e-3f);
    float4 gv = ((const float4*)g)[t];
    float4 bv = ((const float4*)b)[t];
    float4 o;
    o.x = (v.x-mean)*rstd*gv.x + bv.x;
    o.y = (v.y-mean)*rstd*gv.y + bv.y;
    o.z = (v.z-mean)*rstd*gv.z + bv.z;
    o.w = (v.w-mean)*rstd*gv.w + bv.w;
    __nv_bfloat16 hx = __float2bfloat16_rn(o.x), hy = __float2bfloat16_rn(o.y);
    __nv_bfloat16 hz = __float2bfloat16_rn(o.z), hw = __float2bfloat16_rn(o.w);
    __nv_bfloat16 lx = __float2bfloat16_rn(o.x - __bfloat162float(hx));
    __nv_bfloat16 ly = __float2bfloat16_rn(o.y - __bfloat162float(hy));
    __nv_bfloat16 lz = __float2bfloat16_rn(o.z - __bfloat162float(hz));
    __nv_bfloat16 lw = __float2bfloat16_rn(o.w - __bfloat162float(hw));
    size_t off = (size_t)row*CC + t*4;
    __nv_bfloat162 h01; h01.x=hx; h01.y=hy;
    __nv_bfloat162 h23; h23.x=hz; h23.y=hw;
    __nv_bfloat162 l01; l01.x=lx; l01.y=ly;
    __nv_bfloat162 l23; l23.x=lz; l23.y=lw;
    uint2 uh, ulo;
    uh.x = *(unsigned*)&h01; uh.y = *(unsigned*)&h23;
    ulo.x = *(unsigned*)&l01; ulo.y = *(unsigned*)&l23;
    *(uint2*)&g_cnh[off] = uh;
    *(uint2*)&g_cnl[off] = ulo;

    float4 wv = ((const float4*)wg)[t];
    float gd = o.x*wv.x + o.y*wv.y + o.z*wv.z + o.w*wv.w;
    #pragma unroll
    for (int oo=16;oo;oo>>=1) gd += __shfl_xor_sync(0xffffffffu,gd,oo);
    __syncthreads();
    if (l==0) red[wid]=gd;
    __syncthreads();
    if (t==0){
        float tot = red[0]+red[1]+red[2]+red[3] + bg[0];
        g_gate[row] = 1.f/(1.f+__expf(-tot));
    }
}

// ================= kernel 2: fine LN stats =================
__global__ void __launch_bounds__(256) fine_stats(const float* __restrict__ x)
{
    int w = threadIdx.x>>5, l = threadIdx.x&31;
    int row = blockIdx.x*8 + w;
    const float4* xr = (const float4*)(x + (size_t)row*CF);
    float4 a = xr[l], c = xr[l+32];
    float s  = a.x+a.y+a.z+a.w + c.x+c.y+c.z+c.w;
    float sq = a.x*a.x+a.y*a.y+a.z*a.z+a.w*a.w + c.x*c.x+c.y*c.y+c.z*c.z+c.w*c.w;
    #pragma unroll
    for (int o=16;o;o>>=1){ s += __shfl_xor_sync(0xffffffffu,s,o); sq += __shfl_xor_sync(0xffffffffu,sq,o); }
    if (l==0){
        float m = s*(1.f/256.f);
        g_mean[row] = m;
        g_rstd[row] = rsqrtf(sq*(1.f/256.f) - m*m + 1e-3f);
    }
}

// ================= pack weights: W^T hi/lo bf16 + bias =================
__global__ void __launch_bounds__(384) pack_w(
    const float* __restrict__ wk, const float* __restrict__ wqc, const float* __restrict__ wv,
    const float* __restrict__ bk, const float* __restrict__ bqc, const float* __restrict__ bv)
{
    int k = blockIdx.x; int n = threadIdx.x;
    float v;
    if (n < 64)       v = wk [k*64  + n];
    else if (n < 128) v = wqc[k*64  + (n-64)];
    else              v = wv [k*256 + (n-128)];
    __nv_bfloat16 hi = __float2bfloat16_rn(v);
    __nv_bfloat16 lo = __float2bfloat16_rn(v - __bfloat162float(hi));
    g_wth[(size_t)n*CC + k] = hi;
    g_wtl[(size_t)n*CC + k] = lo;
    if (k == 0){
        float bvv = (n<64) ? bk[n] : (n<128) ? bqc[n-64] : bv[n-128];
        g_bcat[n] = bvv;
    }
}

// ================= fold LN(fine) params into w_qf =================
__global__ void __launch_bounds__(256) fold_qf(
    const float* __restrict__ wqf, const float* __restrict__ bqf,
    const float* __restrict__ g, const float* __restrict__ bb)
{
    int n = blockIdx.x; int t = threadIdx.x;
    float wv = wqf[t*EE + n];
    float wf = g[t]*wv;
    g_wfold[t*EE + n] = wf;
    float cv = bb[t]*wv;
    #pragma unroll
    for (int o=16;o;o>>=1){ wf += __shfl_xor_sync(0xffffffffu,wf,o); cv += __shfl_xor_sync(0xffffffffu,cv,o); }
    __shared__ float sd[8], sc[8];
    int wid = t>>5, l = t&31;
    if (l==0){ sd[wid]=wf; sc[wid]=cv; }
    __syncthreads();
    if (t==0){
        float dd=0.f, cc=0.f;
        #pragma unroll
        for (int i=0;i<8;i++){ dd+=sd[i]; cc+=sc[i]; }
        g_dvec[n]=dd; g_cvec[n]=cc + bqf[n];
    }
}

// ================= projection GEMM via mma.sync bf16 (hi/lo split), cp.async double-buffered =================
// BM=128 BN=128 BK=32, 8 warps (4m x 2n), warp tile m32 x n64.
// Smem rows padded to 40 bf16 (80B). Per buffer: 4 arrays x 10240B = 40960B; 2 buffers = 81920B dynamic.
// __launch_bounds__(256,2): cap regs at 128 so 2 CTAs co-reside per SM (cross-CTA latency hiding).
#define SROW 40
#define ARR 10240
#define PBUF 40960
#define PROJ_SMEM 81920
__global__ void __launch_bounds__(256,2) proj_gemm()
{
    extern __shared__ __align__(16) char smraw[];
    uint32_t sb = (uint32_t)__cvta_generic_to_shared(smraw);
    int t = threadIdx.x;
    int n0 = blockIdx.x*128, m0 = blockIdx.y*128;
    int w = t>>5, l = t&31;
    int wm = w>>1, wn = w&1;
    int m0w = wm*32, n0w = wn*64;

    // staging: thread -> (row sr, 16-elem half skh)
    int sr = t>>1, skh = (t&1)*16;
    const __nv_bfloat16* gAh = g_cnh + (size_t)(m0+sr)*CC + skh;
    const __nv_bfloat16* gAl = g_cnl + (size_t)(m0+sr)*CC + skh;
    const __nv_bfloat16* gBh = g_wth + (size_t)(n0+sr)*CC + skh;
    const __nv_bfloat16* gBl = g_wtl + (size_t)(n0+sr)*CC + skh;
    uint32_t doff = (uint32_t)(sr*SROW + skh)*2;   // byte offset within one array

    float acc[2][8][4];
    #pragma unroll
    for (int mt=0;mt<2;mt++)
        #pragma unroll
        for (int nt=0;nt<8;nt++)
            #pragma unroll
            for (int i=0;i<4;i++) acc[mt][nt][i]=0.f;

    // prefetch chunk 0 into buffer 0
    {
        uint32_t d = sb + doff;
        CP16(d,            gAh);    CP16(d+16,            gAh+8);
        CP16(d+ARR,        gAl);    CP16(d+ARR+16,        gAl+8);
        CP16(d+2*ARR,      gBh);    CP16(d+2*ARR+16,      gBh+8);
        CP16(d+3*ARR,      gBl);    CP16(d+3*ARR+16,      gBl+8);
        asm volatile("cp.async.commit_group;" ::: "memory");
    }

    for (int c=0; c<16; c++){
        asm volatile("cp.async.wait_group 0;" ::: "memory");
        __syncthreads();
        if (c+1<16){
            int s = (c+1)&1;
            uint32_t d = sb + s*PBUF + doff;
            int koff = (c+1)*32;
            CP16(d,            gAh+koff);    CP16(d+16,            gAh+koff+8);
            CP16(d+ARR,        gAl+koff);    CP16(d+ARR+16,        gAl+koff+8);
            CP16(d+2*ARR,      gBh+koff);    CP16(d+2*ARR+16,      gBh+koff+8);
            CP16(d+3*ARR,      gBl+koff);    CP16(d+3*ARR+16,      gBl+koff+8);
            asm volatile("cp.async.commit_group;" ::: "memory");
        }
        uint32_t bAh = sb + (c&1)*PBUF;
        uint32_t bAl = bAh + ARR;
        uint32_t bBh = bAh + 2*ARR;
        uint32_t bBl = bAh + 3*ARR;

        #pragma unroll
        for (int ks=0; ks<2; ks++){
            int k0 = ks*16;
            uint32_t aoff = ((m0w + (l&15))*SROW + k0 + (l>>4)*8)*2;
            uint32_t ah[2][4], al[2][4];
            LDSM4(ah[0], bAh + aoff);
            LDSM4(ah[1], bAh + aoff + 16*SROW*2);
            LDSM4(al[0], bAl + aoff);
            LDSM4(al[1], bAl + aoff + 16*SROW*2);
            uint32_t boff = ((n0w + (l>>4)*8 + (l&7))*SROW + k0 + ((l>>3)&1)*8)*2;
            uint32_t bh[8][2];
            #pragma unroll
            for (int np=0; np<4; np++){
                uint32_t r4[4];
                LDSM4(r4, bBh + boff + np*16*SROW*2);
                bh[np*2][0]=r4[0]; bh[np*2][1]=r4[1];
                bh[np*2+1][0]=r4[2]; bh[np*2+1][1]=r4[3];
            }
            #pragma unroll
            for (int mt=0; mt<2; mt++)
                #pragma unroll
                for (int nt=0; nt<8; nt++)
                    MMA16816(acc[mt][nt], ah[mt], bh[nt]);
            #pragma unroll
            for (int mt=0; mt<2; mt++)
                #pragma unroll
                for (int nt=0; nt<8; nt++)
                    MMA16816(acc[mt][nt], al[mt], bh[nt]);
            #pragma unroll
            for (int np=0; np<4; np++){
                uint32_t r4[4];
                LDSM4(r4, bBl + boff + np*16*SROW*2);
                bh[np*2][0]=r4[0]; bh[np*2][1]=r4[1];
                bh[np*2+1][0]=r4[2]; bh[np*2+1][1]=r4[3];
            }
            #pragma unroll
            for (int mt=0; mt<2; mt++)
                #pragma unroll
                for (int nt=0; nt<8; nt++)
                    MMA16816(acc[mt][nt], ah[mt], bh[nt]);
        }
        __syncthreads();
    }

    int g = l>>2, q = l&3;
    #pragma unroll
    for (int mt=0; mt<2; mt++){
        int row0 = m0 + m0w + mt*16 + g;
        #pragma unroll
        for (int nt=0; nt<8; nt++){
            int col = n0 + n0w + nt*8 + q*2;
            float2 b2 = *(const float2*)&g_bcat[col];
            *(float2*)&g_proj[(size_t)row0*NP + col] =
                make_float2(acc[mt][nt][0]+b2.x, acc[mt][nt][1]+b2.y);
            *(float2*)&g_proj[(size_t)(row0+8)*NP + col] =
                make_float2(acc[mt][nt][2]+b2.x, acc[mt][nt][3]+b2.y);
        }
    }
}

// ================= query GEMM with folded LN + gate blend (CUDA cores) =================
__global__ void __launch_bounds__(256) query_gemm(const float* __restrict__ fine)
{
    __shared__ __align__(16) float As[16][256];
    __shared__ __align__(16) float Bs[16][64];
    int m0 = blockIdx.x*256;
    int t = threadIdx.x;
    int kB = t>>4, n4 = (t&15)*4;
    int ty = t>>3, tx = t&7;

    const float* Aload = fine + (size_t)(m0+t)*CF;
    const float* Wload = g_wfold + (size_t)kB*EE + n4;

    ull acc[8][4];
    #pragma unroll
    for (int i=0;i<8;i++)
        #pragma unroll
        for (int j=0;j<4;j++) acc[i][j]=pk2(0.f,0.f);

    const int KB = CF/16;  // 16
    float4 ra0 = *(const float4*)(Aload);
    float4 ra1 = *(const float4*)(Aload+4);
    float4 ra2 = *(const float4*)(Aload+8);
    float4 ra3 = *(const float4*)(Aload+12);
    float4 rb  = *(const float4*)(Wload);
    for (int kb=0; kb<KB; kb++){
        As[ 0][t]=ra0.x; As[ 1][t]=ra0.y; As[ 2][t]=ra0.z; As[ 3][t]=ra0.w;
        As[ 4][t]=ra1.x; As[ 5][t]=ra1.y; As[ 6][t]=ra1.z; As[ 7][t]=ra1.w;
        As[ 8][t]=ra2.x; As[ 9][t]=ra2.y; As[10][t]=ra2.z; As[11][t]=ra2.w;
        As[12][t]=ra3.x; As[13][t]=ra3.y; As[14][t]=ra3.z; As[15][t]=ra3.w;
        *(float4*)&Bs[kB][n4] = rb;
        __syncthreads();
        if (kb+1<KB){
            const float* ap = Aload + (kb+1)*16;
            ra0 = *(const float4*)(ap);
            ra1 = *(const float4*)(ap+4);
            ra2 = *(const float4*)(ap+8);
            ra3 = *(const float4*)(ap+12);
            rb  = *(const float4*)(Wload + (size_t)(kb+1)*16*EE);
        }
        #pragma unroll
        for (int k=0;k<16;k++){
            ulonglong2 A01 = *(const ulonglong2*)&As[k][ty*8];
            ulonglong2 A23 = *(const ulonglong2*)&As[k][ty*8+4];
            ulonglong2 B0  = *(const ulonglong2*)&Bs[k][tx*4];
            ulonglong2 B1  = *(const ulonglong2*)&Bs[k][32+tx*4];
            float2 f0=upk(A01.x), f1=upk(A01.y), f2=upk(A23.x), f3=upk(A23.y);
            ull AP0=pk2(f0.x,f0.x), AP1=pk2(f0.y,f0.y), AP2=pk2(f1.x,f1.x), AP3=pk2(f1.y,f1.y);
            ull AP4=pk2(f2.x,f2.x), AP5=pk2(f2.y,f2.y), AP6=pk2(f3.x,f3.x), AP7=pk2(f3.y,f3.y);
            ffma2(acc[0][0],AP0,B0.x); ffma2(acc[0][1],AP0,B0.y); ffma2(acc[0][2],AP0,B1.x); ffma2(acc[0][3],AP0,B1.y);
            ffma2(acc[1][0],AP1,B0.x); ffma2(acc[1][1],AP1,B0.y); ffma2(acc[1][2],AP1,B1.x); ffma2(acc[1][3],AP1,B1.y);
            ffma2(acc[2][0],AP2,B0.x); ffma2(acc[2][1],AP2,B0.y); ffma2(acc[2][2],AP2,B1.x); ffma2(acc[2][3],AP2,B1.y);
            ffma2(acc[3][0],AP3,B0.x); ffma2(acc[3][1],AP3,B0.y); ffma2(acc[3][2],AP3,B1.x); ffma2(acc[3][3],AP3,B1.y);
            ffma2(acc[4][0],AP4,B0.x); ffma2(acc[4][1],AP4,B0.y); ffma2(acc[4][2],AP4,B1.x); ffma2(acc[4][3],AP4,B1.y);
            ffma2(acc[5][0],AP5,B0.x); ffma2(acc[5][1],AP5,B0.y); ffma2(acc[5][2],AP5,B1.x); ffma2(acc[5][3],AP5,B1.y);
            ffma2(acc[6][0],AP6,B0.x); ffma2(acc[6][1],AP6,B0.y); ffma2(acc[6][2],AP6,B1.x); ffma2(acc[6][3],AP6,B1.y);
            ffma2(acc[7][0],AP7,B0.x); ffma2(acc[7][1],AP7,B0.y); ffma2(acc[7][2],AP7,B1.x); ffma2(acc[7][3],AP7,B1.y);
        }
        __syncthreads();
    }

    float4 dv0 = *(const float4*)&g_dvec[tx*4];
    float4 cv0 = *(const float4*)&g_cvec[tx*4];
    float4 dv1 = *(const float4*)&g_dvec[32+tx*4];
    float4 cv1 = *(const float4*)&g_cvec[32+tx*4];
    #pragma unroll
    for (int i=0;i<8;i++){
        int m = m0 + ty*8 + i;
        float mean = g_mean[m], rstd = g_rstd[m];
        int b_ = m>>14, h = (m>>7)&127, w = m&127;
        int mc = (b_<<12) | ((h>>1)<<6) | (w>>1);
        float gt = g_gate[mc];
        float2 p0=upk(acc[i][0]), p1=upk(acc[i][1]), p2=upk(acc[i][2]), p3=upk(acc[i][3]);
        float4 u0 = make_float4(p0.x,p0.y,p1.x,p1.y);
        float4 u1 = make_float4(p2.x,p2.y,p3.x,p3.y);
        float4 qc0 = *(const float4*)&g_proj[(size_t)mc*NP + 64 + tx*4];
        float4 qc1 = *(const float4*)&g_proj[(size_t)mc*NP + 64 + 32 + tx*4];
        float4 q0, q1, o0, o1;
        q0.x = rstd*(u0.x - mean*dv0.x) + cv0.x;
        q0.y = rstd*(u0.y - mean*dv0.y) + cv0.y;
        q0.z = rstd*(u0.z - mean*dv0.z) + cv0.z;
        q0.w = rstd*(u0.w - mean*dv0.w) + cv0.w;
        q1.x = rstd*(u1.x - mean*dv1.x) + cv1.x;
        q1.y = rstd*(u1.y - mean*dv1.y) + cv1.y;
        q1.z = rstd*(u1.z - mean*dv1.z) + cv1.z;
        q1.w = rstd*(u1.w - mean*dv1.w) + cv1.w;
        o0.x = q0.x*gt + qc0.x*(1.f-gt);
        o0.y = q0.y*gt + qc0.y*(1.f-gt);
        o0.z = q0.z*gt + qc0.z*(1.f-gt);
        o0.w = q0.w*gt + qc0.w*(1.f-gt);
        o1.x = q1.x*gt + qc1.x*(1.f-gt);
        o1.y = q1.y*gt + qc1.y*(1.f-gt);
        o1.z = q1.z*gt + qc1.z*(1.f-gt);
        o1.w = q1.w*gt + qc1.w*(1.f-gt);
        *(float4*)&g_query[(size_t)m*EE + tx*4]      = o0;
        *(float4*)&g_query[(size_t)m*EE + 32 + tx*4] = o1;
    }
}

// ================= local attention =================
#define SK_STRIDE 68
#define ATT_SMEM_BYTES ((6800 + 25600 + 4096 + 64*28) * 4)
__global__ void __launch_bounds__(256) attn_kernel(float* __restrict__ out)
{
    extern __shared__ __align__(16) float sm[];
    float* sk = sm;                       // [5][20][68]
    float* sv = sm + 6800;                // [5][20][256]
    float* sq = sm + 6800 + 25600;        // [64][64]
    float* satt = sq + 4096;              // [64][28]

    int j0 = blockIdx.x * 16;
    int i  = blockIdx.y;
    int b  = blockIdx.z;
    int t = threadIdx.x;

    for (int idx = t; idx < 1600; idx += 256){
        int c4 = idx & 15, cc = (idx>>4) % 20, r = idx/320;
        int ci = i - 2 + r, cj = j0 - 2 + cc;
        float4 v = make_float4(0.f,0.f,0.f,0.f);
        if (ci>=0 && ci<HC && cj>=0 && cj<WC)
            v = *(const float4*)&g_proj[(size_t)((b*HC+ci)*WC + cj)*NP + c4*4];
        *(float4*)&sk[(r*20+cc)*SK_STRIDE + c4*4] = v;
    }
    for (int idx = t; idx < 6400; idx += 256){
        int c4 = idx & 63, cc = (idx>>6) % 20, r = idx/1280;
        int ci = i - 2 + r, cj = j0 - 2 + cc;
        float4 v = make_float4(0.f,0.f,0.f,0.f);
        if (ci>=0 && ci<HC && cj>=0 && cj<WC)
            v = *(const float4*)&g_proj[(size_t)((b*HC+ci)*WC + cj)*NP + 128 + c4*4];
        *(float4*)&sv[(r*20+cc)*256 + c4*4] = v;
    }
    for (int idx = t; idx < 1024; idx += 256){
        int c4 = idx & 15, fp = idx >> 4;
        int cp = fp>>2, q = fp&3, di = q>>1, dj = q&1;
        int h = 2*i + di, w = 2*(j0+cp) + dj;
        *(float4*)&sq[fp*64 + c4*4] =
            *(const float4*)&g_query[(((size_t)(b*HF+h)*WF + w)<<6) + c4*4];
    }
    __syncthreads();

    int wd = t>>5, l = t&31;
    int pr = l/5, pc = l - pr*5;
    for (int fi=0; fi<8; fi++){
        int fp = wd*8 + fi;
        int cp = fp>>2;
        float s = -1e30f;
        if (l < 25){
            s = 0.f;
            const float* kk = &sk[(pr*20 + cp + pc)*SK_STRIDE];
            const float* qq = &sq[fp*64];
            #pragma unroll
            for (int c4=0;c4<16;c4++){
                float4 qa = *(const float4*)(qq + c4*4);
                float4 ka = *(const float4*)(kk + c4*4);
                s += qa.x*ka.x + qa.y*ka.y + qa.z*ka.z + qa.w*ka.w;
            }
        }
        float mx = s;
        #pragma unroll
        for (int o=16;o;o>>=1) mx = fmaxf(mx, __shfl_xor_sync(0xffffffffu,mx,o));
        float e = (l<25) ? __expf(s - mx) : 0.f;
        float ssum = e;
        #pragma unroll
        for (int o=16;o;o>>=1) ssum += __shfl_xor_sync(0xffffffffu,ssum,o);
        if (l<25) satt[fp*28 + l] = e / ssum;
    }
    __syncthreads();

    int cp = t>>4, l16 = t&15;
    for (int cg=0; cg<4; cg++){
        int c = cg*64 + l16*4;
        ull acc[4][2];
        #pragma unroll
        for (int q=0;q<4;q++){ acc[q][0]=pk2(0.f,0.f); acc[q][1]=pk2(0.f,0.f); }
        #pragma unroll
        for (int p=0;p<25;p++){
            int ppr = p/5, ppc = p - ppr*5;
            const ull* vp = (const ull*)&sv[(ppr*20 + cp + ppc)*256 + c];
            ull v01 = vp[0], v23 = vp[1];
            #pragma unroll
            for (int q=0;q<4;q++){
                float a = satt[(cp*4+q)*28 + p];
                ull aP = pk2(a,a);
                ffma2(acc[q][0], aP, v01);
                ffma2(acc[q][1], aP, v23);
            }
        }
        #pragma unroll
        for (int q=0;q<4;q++){
            int di=q>>1, dj=q&1;
            int h = 2*i+di, w = 2*(j0+cp)+dj;
            float2 u0=upk(acc[q][0]), u1=upk(acc[q][1]);
            float4 o = make_float4(u0.x,u0.y,u1.x,u1.y);
            *(float4*)&out[(((size_t)(b*HF+h)*WF + w)<<8) + c] = o;
        }
    }
}

// ================= launch =================
extern "C" void kernel_launch(void* const* d_in, const int* in_sizes, int n_in,
                              void* d_out, int out_size)
{
    (void)in_sizes; (void)n_in; (void)out_size;
    const float* fine   = (const float*)d_in[0];
    const float* coarse = (const float*)d_in[1];
    const float* ln_f_g = (const float*)d_in[2];
    const float* ln_f_b = (const float*)d_in[3];
    const float* ln_c_g = (const float*)d_in[4];
    const float* ln_c_b = (const float*)d_in[5];
    const float* w_gate = (const float*)d_in[6];
    const float* b_gate = (const float*)d_in[7];
    const float* w_qf   = (const float*)d_in[8];
    const float* b_qf   = (const float*)d_in[9];
    const float* w_qc   = (const float*)d_in[10];
    const float* b_qc   = (const float*)d_in[11];
    const float* w_k    = (const float*)d_in[12];
    const float* b_k    = (const float*)d_in[13];
    const float* w_v    = (const float*)d_in[14];
    const float* b_v    = (const float*)d_in[15];
    float* out = (float*)d_out;

    ln_coarse_gate<<<NCOARSE, 128>>>(coarse, ln_c_g, ln_c_b, w_gate, b_gate);   // 1
    pack_w<<<CC, NP>>>(w_k, w_qc, w_v, b_k, b_qc, b_v);                          // 2
    fine_stats<<<NFINE/8, 256>>>(fine);                                          // 3
    cudaFuncSetAttribute(proj_gemm, cudaFuncAttributeMaxDynamicSharedMemorySize, PROJ_SMEM);
    proj_gemm<<<dim3(NP/128, NCOARSE/128), 256, PROJ_SMEM>>>();                  // 4  <- profiled slot
    fold_qf<<<EE, 256>>>(w_qf, b_qf, ln_f_g, ln_f_b);                            // 5
    query_gemm<<<NFINE/256, 256>>>(fine);                                        // 6
    cudaFuncSetAttribute(attn_kernel, cudaFuncAttributeMaxDynamicSharedMemorySize, ATT_SMEM_BYTES);
    attn_kernel<<<dim3(WC/16, HC, BB), 256, ATT_SMEM_BYTES>>>(out);              // 7
}

// round 11
// speedup vs baseline: 1.5999x; 1.0133x over previous
#include <cuda_runtime.h>
#include <cuda_bf16.h>
#include <cstdint>
#include <cstddef>

typedef unsigned long long ull;

__device__ __forceinline__ void ffma2(ull& d, ull a, ull b){
    asm("fma.rn.f32x2 %0, %1, %2, %0;" : "+l"(d) : "l"(a), "l"(b));
}
__device__ __forceinline__ ull pk2(float x, float y){
    ull r; asm("mov.b64 %0, {%1, %2};" : "=l"(r) : "f"(x), "f"(y)); return r;
}
__device__ __forceinline__ float2 upk(ull a){
    float2 r; asm("mov.b64 {%0, %1}, %2;" : "=f"(r.x), "=f"(r.y) : "l"(a)); return r;
}

#define LDSM4(r, addr) asm volatile( \
    "ldmatrix.sync.aligned.m8n8.x4.shared.b16 {%0,%1,%2,%3}, [%4];" \
    : "=r"((r)[0]),"=r"((r)[1]),"=r"((r)[2]),"=r"((r)[3]) : "r"(addr))

#define MMA16816(c, a, b) asm volatile( \
    "mma.sync.aligned.m16n8k16.row.col.f32.bf16.bf16.f32 " \
    "{%0,%1,%2,%3}, {%4,%5,%6,%7}, {%8,%9}, {%0,%1,%2,%3};" \
    : "+f"((c)[0]),"+f"((c)[1]),"+f"((c)[2]),"+f"((c)[3]) \
    : "r"((a)[0]),"r"((a)[1]),"r"((a)[2]),"r"((a)[3]), "r"((b)[0]),"r"((b)[1]))

#define CP16(dst, src) asm volatile( \
    "cp.async.cg.shared.global [%0], [%1], 16;" :: "r"(dst), "l"(src))

// ---------------- fixed shapes ----------------
#define BB 4
#define HF 128
#define WF 128
#define CF 256
#define HC 64
#define WC 64
#define CC 512
#define EE 64
#define FF 256
#define NP 384
#define NCOARSE (BB*HC*WC)   // 16384
#define NFINE   (BB*HF*WF)   // 65536

// ---------------- scratch ----------------
__device__ __nv_bfloat16 g_cnh[(size_t)NCOARSE*CC];  // LN(coarse) hi  [m][k]
__device__ __nv_bfloat16 g_cnl[(size_t)NCOARSE*CC];  // LN(coarse) lo
__device__ __nv_bfloat16 g_wth[(size_t)NP*CC];       // W^T hi  [n][k]
__device__ __nv_bfloat16 g_wtl[(size_t)NP*CC];       // W^T lo
__device__ float g_gate[NCOARSE];
__device__ float g_proj[(size_t)NCOARSE*NP];   // fused k|qc|v
__device__ float g_query[(size_t)NFINE*EE];
__device__ float g_mean[NFINE];
__device__ float g_rstd[NFINE];
__device__ float g_wfold[(size_t)CF*EE];
__device__ float g_dvec[EE];
__device__ float g_cvec[EE];
__device__ float g_bcat[NP];

// ================= kernel 1: LN(coarse) + gate, emit bf16 hi/lo =================
__global__ void __launch_bounds__(128) ln_coarse_gate(
    const float* __restrict__ x, const float* __restrict__ g, const float* __restrict__ b,
    const float* __restrict__ wg, const float* __restrict__ bg)
{
    int row = blockIdx.x; int t = threadIdx.x;
    const float4* xr = (const float4*)(x + (size_t)row*CC);
    float4 v = xr[t];
    float s  = v.x+v.y+v.z+v.w;
    float sq = v.x*v.x+v.y*v.y+v.z*v.z+v.w*v.w;
    #pragma unroll
    for (int o=16;o;o>>=1){ s += __shfl_xor_sync(0xffffffffu,s,o); sq += __shfl_xor_sync(0xffffffffu,sq,o); }
    __shared__ float red[8];
    int wid = t>>5, l = t&31;
    if (l==0){ red[wid]=s; red[4+wid]=sq; }
    __syncthreads();
    s  = red[0]+red[1]+red[2]+red[3];
    sq = red[4]+red[5]+red[6]+red[7];
    float mean = s*(1.f/512.f);
    float var  = sq*(1.f/512.f) - mean*mean;
    float rstd = rsqrtf(var + 1e-3f);
    float4 gv = ((const float4*)g)[t];
    float4 bv = ((const float4*)b)[t];
    float4 o;
    o.x = (v.x-mean)*rstd*gv.x + bv.x;
    o.y = (v.y-mean)*rstd*gv.y + bv.y;
    o.z = (v.z-mean)*rstd*gv.z + bv.z;
    o.w = (v.w-mean)*rstd*gv.w + bv.w;
    __nv_bfloat16 hx = __float2bfloat16_rn(o.x), hy = __float2bfloat16_rn(o.y);
    __nv_bfloat16 hz = __float2bfloat16_rn(o.z), hw = __float2bfloat16_rn(o.w);
    __nv_bfloat16 lx = __float2bfloat16_rn(o.x - __bfloat162float(hx));
    __nv_bfloat16 ly = __float2bfloat16_rn(o.y - __bfloat162float(hy));
    __nv_bfloat16 lz = __float2bfloat16_rn(o.z - __bfloat162float(hz));
    __nv_bfloat16 lw = __float2bfloat16_rn(o.w - __bfloat162float(hw));
    size_t off = (size_t)row*CC + t*4;
    __nv_bfloat162 h01; h01.x=hx; h01.y=hy;
    __nv_bfloat162 h23; h23.x=hz; h23.y=hw;
    __nv_bfloat162 l01; l01.x=lx; l01.y=ly;
    __nv_bfloat162 l23; l23.x=lz; l23.y=lw;
    uint2 uh, ulo;
    uh.x = *(unsigned*)&h01; uh.y = *(unsigned*)&h23;
    ulo.x = *(unsigned*)&l01; ulo.y = *(unsigned*)&l23;
    *(uint2*)&g_cnh[off] = uh;
    *(uint2*)&g_cnl[off] = ulo;

    float4 wv = ((const float4*)wg)[t];
    float gd = o.x*wv.x + o.y*wv.y + o.z*wv.z + o.w*wv.w;
    #pragma unroll
    for (int oo=16;oo;oo>>=1) gd += __shfl_xor_sync(0xffffffffu,gd,oo);
    __syncthreads();
    if (l==0) red[wid]=gd;
    __syncthreads();
    if (t==0){
        float tot = red[0]+red[1]+red[2]+red[3] + bg[0];
        g_gate[row] = 1.f/(1.f+__expf(-tot));
    }
}

// ================= kernel 2: fine LN stats =================
__global__ void __launch_bounds__(256) fine_stats(const float* __restrict__ x)
{
    int w = threadIdx.x>>5, l = threadIdx.x&31;
    int row = blockIdx.x*8 + w;
    const float4* xr = (const float4*)(x + (size_t)row*CF);
    float4 a = xr[l], c = xr[l+32];
    float s  = a.x+a.y+a.z+a.w + c.x+c.y+c.z+c.w;
    float sq = a.x*a.x+a.y*a.y+a.z*a.z+a.w*a.w + c.x*c.x+c.y*c.y+c.z*c.z+c.w*c.w;
    #pragma unroll
    for (int o=16;o;o>>=1){ s += __shfl_xor_sync(0xffffffffu,s,o); sq += __shfl_xor_sync(0xffffffffu,sq,o); }
    if (l==0){
        float m = s*(1.f/256.f);
        g_mean[row] = m;
        g_rstd[row] = rsqrtf(sq*(1.f/256.f) - m*m + 1e-3f);
    }
}

// ================= pack weights: W^T hi/lo bf16 + bias =================
__global__ void __launch_bounds__(384) pack_w(
    const float* __restrict__ wk, const float* __restrict__ wqc, const float* __restrict__ wv,
    const float* __restrict__ bk, const float* __restrict__ bqc, const float* __restrict__ bv)
{
    int k = blockIdx.x; int n = threadIdx.x;
    float v;
    if (n < 64)       v = wk [k*64  + n];
    else if (n < 128) v = wqc[k*64  + (n-64)];
    else              v = wv [k*256 + (n-128)];
    __nv_bfloat16 hi = __float2bfloat16_rn(v);
    __nv_bfloat16 lo = __float2bfloat16_rn(v - __bfloat162float(hi));
    g_wth[(size_t)n*CC + k] = hi;
    g_wtl[(size_t)n*CC + k] = lo;
    if (k == 0){
        float bvv = (n<64) ? bk[n] : (n<128) ? bqc[n-64] : bv[n-128];
        g_bcat[n] = bvv;
    }
}

// ================= fold LN(fine) params into w_qf =================
__global__ void __launch_bounds__(256) fold_qf(
    const float* __restrict__ wqf, const float* __restrict__ bqf,
    const float* __restrict__ g, const float* __restrict__ bb)
{
    int n = blockIdx.x; int t = threadIdx.x;
    float wv = wqf[t*EE + n];
    float wf = g[t]*wv;
    g_wfold[t*EE + n] = wf;
    float cv = bb[t]*wv;
    #pragma unroll
    for (int o=16;o;o>>=1){ wf += __shfl_xor_sync(0xffffffffu,wf,o); cv += __shfl_xor_sync(0xffffffffu,cv,o); }
    __shared__ float sd[8], sc[8];
    int wid = t>>5, l = t&31;
    if (l==0){ sd[wid]=wf; sc[wid]=cv; }
    __syncthreads();
    if (t==0){
        float dd=0.f, cc=0.f;
        #pragma unroll
        for (int i=0;i<8;i++){ dd+=sd[i]; cc+=sc[i]; }
        g_dvec[n]=dd; g_cvec[n]=cc + bqf[n];
    }
}

// ================= projection GEMM via mma.sync bf16 (hi/lo split), cp.async double-buffered =================
#define SROW 40
#define ARR 10240
#define PBUF 40960
#define PROJ_SMEM 81920
__global__ void __launch_bounds__(256,2) proj_gemm()
{
    extern __shared__ __align__(16) char smraw[];
    uint32_t sb = (uint32_t)__cvta_generic_to_shared(smraw);
    int t = threadIdx.x;
    int n0 = blockIdx.x*128, m0 = blockIdx.y*128;
    int w = t>>5, l = t&31;
    int wm = w>>1, wn = w&1;
    int m0w = wm*32, n0w = wn*64;

    int sr = t>>1, skh = (t&1)*16;
    const __nv_bfloat16* gAh = g_cnh + (size_t)(m0+sr)*CC + skh;
    const __nv_bfloat16* gAl = g_cnl + (size_t)(m0+sr)*CC + skh;
    const __nv_bfloat16* gBh = g_wth + (size_t)(n0+sr)*CC + skh;
    const __nv_bfloat16* gBl = g_wtl + (size_t)(n0+sr)*CC + skh;
    uint32_t doff = (uint32_t)(sr*SROW + skh)*2;

    float acc[2][8][4];
    #pragma unroll
    for (int mt=0;mt<2;mt++)
        #pragma unroll
        for (int nt=0;nt<8;nt++)
            #pragma unroll
            for (int i=0;i<4;i++) acc[mt][nt][i]=0.f;

    {
        uint32_t d = sb + doff;
        CP16(d,            gAh);    CP16(d+16,            gAh+8);
        CP16(d+ARR,        gAl);    CP16(d+ARR+16,        gAl+8);
        CP16(d+2*ARR,      gBh);    CP16(d+2*ARR+16,      gBh+8);
        CP16(d+3*ARR,      gBl);    CP16(d+3*ARR+16,      gBl+8);
        asm volatile("cp.async.commit_group;" ::: "memory");
    }

    for (int c=0; c<16; c++){
        asm volatile("cp.async.wait_group 0;" ::: "memory");
        __syncthreads();
        if (c+1<16){
            int s = (c+1)&1;
            uint32_t d = sb + s*PBUF + doff;
            int koff = (c+1)*32;
            CP16(d,            gAh+koff);    CP16(d+16,            gAh+koff+8);
            CP16(d+ARR,        gAl+koff);    CP16(d+ARR+16,        gAl+koff+8);
            CP16(d+2*ARR,      gBh+koff);    CP16(d+2*ARR+16,      gBh+koff+8);
            CP16(d+3*ARR,      gBl+koff);    CP16(d+3*ARR+16,      gBl+koff+8);
            asm volatile("cp.async.commit_group;" ::: "memory");
        }
        uint32_t bAh = sb + (c&1)*PBUF;
        uint32_t bAl = bAh + ARR;
        uint32_t bBh = bAh + 2*ARR;
        uint32_t bBl = bAh + 3*ARR;

        #pragma unroll
        for (int ks=0; ks<2; ks++){
            int k0 = ks*16;
            uint32_t aoff = ((m0w + (l&15))*SROW + k0 + (l>>4)*8)*2;
            uint32_t ah[2][4], al[2][4];
            LDSM4(ah[0], bAh + aoff);
            LDSM4(ah[1], bAh + aoff + 16*SROW*2);
            LDSM4(al[0], bAl + aoff);
            LDSM4(al[1], bAl + aoff + 16*SROW*2);
            uint32_t boff = ((n0w + (l>>4)*8 + (l&7))*SROW + k0 + ((l>>3)&1)*8)*2;
            uint32_t bh[8][2];
            #pragma unroll
            for (int np=0; np<4; np++){
                uint32_t r4[4];
                LDSM4(r4, bBh + boff + np*16*SROW*2);
                bh[np*2][0]=r4[0]; bh[np*2][1]=r4[1];
                bh[np*2+1][0]=r4[2]; bh[np*2+1][1]=r4[3];
            }
            #pragma unroll
            for (int mt=0; mt<2; mt++)
                #pragma unroll
                for (int nt=0; nt<8; nt++)
                    MMA16816(acc[mt][nt], ah[mt], bh[nt]);
            #pragma unroll
            for (int mt=0; mt<2; mt++)
                #pragma unroll
                for (int nt=0; nt<8; nt++)
                    MMA16816(acc[mt][nt], al[mt], bh[nt]);
            #pragma unroll
            for (int np=0; np<4; np++){
                uint32_t r4[4];
                LDSM4(r4, bBl + boff + np*16*SROW*2);
                bh[np*2][0]=r4[0]; bh[np*2][1]=r4[1];
                bh[np*2+1][0]=r4[2]; bh[np*2+1][1]=r4[3];
            }
            #pragma unroll
            for (int mt=0; mt<2; mt++)
                #pragma unroll
                for (int nt=0; nt<8; nt++)
                    MMA16816(acc[mt][nt], ah[mt], bh[nt]);
        }
        __syncthreads();
    }

    int g = l>>2, q = l&3;
    #pragma unroll
    for (int mt=0; mt<2; mt++){
        int row0 = m0 + m0w + mt*16 + g;
        #pragma unroll
        for (int nt=0; nt<8; nt++){
            int col = n0 + n0w + nt*8 + q*2;
            float2 b2 = *(const float2*)&g_bcat[col];
            *(float2*)&g_proj[(size_t)row0*NP + col] =
                make_float2(acc[mt][nt][0]+b2.x, acc[mt][nt][1]+b2.y);
            *(float2*)&g_proj[(size_t)(row0+8)*NP + col] =
                make_float2(acc[mt][nt][2]+b2.x, acc[mt][nt][3]+b2.y);
        }
    }
}

// ================= query GEMM with folded LN + gate blend (CUDA cores) =================
__global__ void __launch_bounds__(256) query_gemm(const float* __restrict__ fine)
{
    __shared__ __align__(16) float As[16][256];
    __shared__ __align__(16) float Bs[16][64];
    int m0 = blockIdx.x*256;
    int t = threadIdx.x;
    int kB = t>>4, n4 = (t&15)*4;
    int ty = t>>3, tx = t&7;

    const float* Aload = fine + (size_t)(m0+t)*CF;
    const float* Wload = g_wfold + (size_t)kB*EE + n4;

    ull acc[8][4];
    #pragma unroll
    for (int i=0;i<8;i++)
        #pragma unroll
        for (int j=0;j<4;j++) acc[i][j]=pk2(0.f,0.f);

    const int KB = CF/16;  // 16
    float4 ra0 = *(const float4*)(Aload);
    float4 ra1 = *(const float4*)(Aload+4);
    float4 ra2 = *(const float4*)(Aload+8);
    float4 ra3 = *(const float4*)(Aload+12);
    float4 rb  = *(const float4*)(Wload);
    for (int kb=0; kb<KB; kb++){
        As[ 0][t]=ra0.x; As[ 1][t]=ra0.y; As[ 2][t]=ra0.z; As[ 3][t]=ra0.w;
        As[ 4][t]=ra1.x; As[ 5][t]=ra1.y; As[ 6][t]=ra1.z; As[ 7][t]=ra1.w;
        As[ 8][t]=ra2.x; As[ 9][t]=ra2.y; As[10][t]=ra2.z; As[11][t]=ra2.w;
        As[12][t]=ra3.x; As[13][t]=ra3.y; As[14][t]=ra3.z; As[15][t]=ra3.w;
        *(float4*)&Bs[kB][n4] = rb;
        __syncthreads();
        if (kb+1<KB){
            const float* ap = Aload + (kb+1)*16;
            ra0 = *(const float4*)(ap);
            ra1 = *(const float4*)(ap+4);
            ra2 = *(const float4*)(ap+8);
            ra3 = *(const float4*)(ap+12);
            rb  = *(const float4*)(Wload + (size_t)(kb+1)*16*EE);
        }
        #pragma unroll
        for (int k=0;k<16;k++){
            ulonglong2 A01 = *(const ulonglong2*)&As[k][ty*8];
            ulonglong2 A23 = *(const ulonglong2*)&As[k][ty*8+4];
            ulonglong2 B0  = *(const ulonglong2*)&Bs[k][tx*4];
            ulonglong2 B1  = *(const ulonglong2*)&Bs[k][32+tx*4];
            float2 f0=upk(A01.x), f1=upk(A01.y), f2=upk(A23.x), f3=upk(A23.y);
            ull AP0=pk2(f0.x,f0.x), AP1=pk2(f0.y,f0.y), AP2=pk2(f1.x,f1.x), AP3=pk2(f1.y,f1.y);
            ull AP4=pk2(f2.x,f2.x), AP5=pk2(f2.y,f2.y), AP6=pk2(f3.x,f3.x), AP7=pk2(f3.y,f3.y);
            ffma2(acc[0][0],AP0,B0.x); ffma2(acc[0][1],AP0,B0.y); ffma2(acc[0][2],AP0,B1.x); ffma2(acc[0][3],AP0,B1.y);
            ffma2(acc[1][0],AP1,B0.x); ffma2(acc[1][1],AP1,B0.y); ffma2(acc[1][2],AP1,B1.x); ffma2(acc[1][3],AP1,B1.y);
            ffma2(acc[2][0],AP2,B0.x); ffma2(acc[2][1],AP2,B0.y); ffma2(acc[2][2],AP2,B1.x); ffma2(acc[2][3],AP2,B1.y);
            ffma2(acc[3][0],AP3,B0.x); ffma2(acc[3][1],AP3,B0.y); ffma2(acc[3][2],AP3,B1.x); ffma2(acc[3][3],AP3,B1.y);
            ffma2(acc[4][0],AP4,B0.x); ffma2(acc[4][1],AP4,B0.y); ffma2(acc[4][2],AP4,B1.x); ffma2(acc[4][3],AP4,B1.y);
            ffma2(acc[5][0],AP5,B0.x); ffma2(acc[5][1],AP5,B0.y); ffma2(acc[5][2],AP5,B1.x); ffma2(acc[5][3],AP5,B1.y);
            ffma2(acc[6][0],AP6,B0.x); ffma2(acc[6][1],AP6,B0.y); ffma2(acc[6][2],AP6,B1.x); ffma2(acc[6][3],AP6,B1.y);
            ffma2(acc[7][0],AP7,B0.x); ffma2(acc[7][1],AP7,B0.y); ffma2(acc[7][2],AP7,B1.x); ffma2(acc[7][3],AP7,B1.y);
        }
        __syncthreads();
    }

    float4 dv0 = *(const float4*)&g_dvec[tx*4];
    float4 cv0 = *(const float4*)&g_cvec[tx*4];
    float4 dv1 = *(const float4*)&g_dvec[32+tx*4];
    float4 cv1 = *(const float4*)&g_cvec[32+tx*4];
    #pragma unroll
    for (int i=0;i<8;i++){
        int m = m0 + ty*8 + i;
        float mean = g_mean[m], rstd = g_rstd[m];
        int b_ = m>>14, h = (m>>7)&127, w = m&127;
        int mc = (b_<<12) | ((h>>1)<<6) | (w>>1);
        float gt = g_gate[mc];
        float2 p0=upk(acc[i][0]), p1=upk(acc[i][1]), p2=upk(acc[i][2]), p3=upk(acc[i][3]);
        float4 u0 = make_float4(p0.x,p0.y,p1.x,p1.y);
        float4 u1 = make_float4(p2.x,p2.y,p3.x,p3.y);
        float4 qc0 = *(const float4*)&g_proj[(size_t)mc*NP + 64 + tx*4];
        float4 qc1 = *(const float4*)&g_proj[(size_t)mc*NP + 64 + 32 + tx*4];
        float4 q0, q1, o0, o1;
        q0.x = rstd*(u0.x - mean*dv0.x) + cv0.x;
        q0.y = rstd*(u0.y - mean*dv0.y) + cv0.y;
        q0.z = rstd*(u0.z - mean*dv0.z) + cv0.z;
        q0.w = rstd*(u0.w - mean*dv0.w) + cv0.w;
        q1.x = rstd*(u1.x - mean*dv1.x) + cv1.x;
        q1.y = rstd*(u1.y - mean*dv1.y) + cv1.y;
        q1.z = rstd*(u1.z - mean*dv1.z) + cv1.z;
        q1.w = rstd*(u1.w - mean*dv1.w) + cv1.w;
        o0.x = q0.x*gt + qc0.x*(1.f-gt);
        o0.y = q0.y*gt + qc0.y*(1.f-gt);
        o0.z = q0.z*gt + qc0.z*(1.f-gt);
        o0.w = q0.w*gt + qc0.w*(1.f-gt);
        o1.x = q1.x*gt + qc1.x*(1.f-gt);
        o1.y = q1.y*gt + qc1.y*(1.f-gt);
        o1.z = q1.z*gt + qc1.z*(1.f-gt);
        o1.w = q1.w*gt + qc1.w*(1.f-gt);
        *(float4*)&g_query[(size_t)m*EE + tx*4]      = o0;
        *(float4*)&g_query[(size_t)m*EE + 32 + tx*4] = o1;
    }
}

// ================= local attention: 16x2 coarse tile (halo 20x6) =================
#define SK_STRIDE 68
// sk 6*20*68=8160, sv 6*20*256=30720, sq 128*64=8192, satt 128*28=3584 -> 50656 floats = 202624 B
#define ATT_SMEM_BYTES ((8160 + 30720 + 8192 + 3584) * 4)
__global__ void __launch_bounds__(256) attn_kernel(float* __restrict__ out)
{
    extern __shared__ __align__(16) float sm[];
    float* sk = sm;                       // [6][20][68]
    float* sv = sm + 8160;                // [6][20][256]
    float* sq = sm + 8160 + 30720;        // [128][64]  fp = lr*64 + cp*4 + q
    float* satt = sq + 8192;              // [128][28]

    int j0 = blockIdx.x * 16;
    int i0 = blockIdx.y * 2;
    int b  = blockIdx.z;
    int t = threadIdx.x;

    // stage keys: 6 rows x 20 cols x 64ch = 1920 float4
    for (int idx = t; idx < 1920; idx += 256){
        int c4 = idx & 15, cc = (idx>>4) % 20, r = idx/320;
        int ci = i0 - 2 + r, cj = j0 - 2 + cc;
        float4 v = make_float4(0.f,0.f,0.f,0.f);
        if (ci>=0 && ci<HC && cj>=0 && cj<WC)
            v = *(const float4*)&g_proj[(size_t)((b*HC+ci)*WC + cj)*NP + c4*4];
        *(float4*)&sk[(r*20+cc)*SK_STRIDE + c4*4] = v;
    }
    // stage values: 6 x 20 x 256ch = 7680 float4
    for (int idx = t; idx < 7680; idx += 256){
        int c4 = idx & 63, cc = (idx>>6) % 20, r = idx/1280;
        int ci = i0 - 2 + r, cj = j0 - 2 + cc;
        float4 v = make_float4(0.f,0.f,0.f,0.f);
        if (ci>=0 && ci<HC && cj>=0 && cj<WC)
            v = *(const float4*)&g_proj[(size_t)((b*HC+ci)*WC + cj)*NP + 128 + c4*4];
        *(float4*)&sv[(r*20+cc)*256 + c4*4] = v;
    }
    // stage queries: 128 fine pixels x 16 float4
    for (int idx = t; idx < 2048; idx += 256){
        int c4 = idx & 15, fp = idx >> 4;
        int lr = fp>>6, rem = fp&63, cp = rem>>2, q = rem&3, di = q>>1, dj = q&1;
        int h = 2*(i0+lr) + di, w = 2*(j0+cp) + dj;
        *(float4*)&sq[fp*64 + c4*4] =
            *(const float4*)&g_query[(((size_t)(b*HF+h)*WF + w)<<6) + c4*4];
    }
    __syncthreads();

    // scores + softmax: warp per 16 fine pixels, lane per patch
    int wd = t>>5, l = t&31;
    int pr = l/5, pc = l - pr*5;
    for (int fi=0; fi<16; fi++){
        int fp = wd*16 + fi;
        int lr = fp>>6, cp = (fp>>2)&15;
        float s = -1e30f;
        if (l < 25){
            s = 0.f;
            const float* kk = &sk[((lr+pr)*20 + cp + pc)*SK_STRIDE];
            const float* qq = &sq[fp*64];
            #pragma unroll
            for (int c4=0;c4<16;c4++){
                float4 qa = *(const float4*)(qq + c4*4);
                float4 ka = *(const float4*)(kk + c4*4);
                s += qa.x*ka.x + qa.y*ka.y + qa.z*ka.z + qa.w*ka.w;
            }
        }
        float mx = s;
        #pragma unroll
        for (int o=16;o;o>>=1) mx = fmaxf(mx, __shfl_xor_sync(0xffffffffu,mx,o));
        float e = (l<25) ? __expf(s - mx) : 0.f;
        float ssum = e;
        #pragma unroll
        for (int o=16;o;o>>=1) ssum += __shfl_xor_sync(0xffffffffu,ssum,o);
        if (l<25) satt[fp*28 + l] = e / ssum;
    }
    __syncthreads();

    // value pass: 8 threads per coarse pixel (32 pixels), 8 channel groups of 32
    int cpl = t>>3, l8 = t&7;
    int lr = cpl>>4, cp = cpl&15;
    for (int cg=0; cg<8; cg++){
        int c = cg*32 + l8*4;
        ull acc[4][2];
        #pragma unroll
        for (int q=0;q<4;q++){ acc[q][0]=pk2(0.f,0.f); acc[q][1]=pk2(0.f,0.f); }
        #pragma unroll
        for (int p=0;p<25;p++){
            int ppr = p/5, ppc = p - ppr*5;
            const ull* vp = (const ull*)&sv[((lr+ppr)*20 + cp + ppc)*256 + c];
            ull v01 = vp[0], v23 = vp[1];
            #pragma unroll
            for (int q=0;q<4;q++){
                float a = satt[(lr*64 + cp*4 + q)*28 + p];
                ull aP = pk2(a,a);
                ffma2(acc[q][0], aP, v01);
                ffma2(acc[q][1], aP, v23);
            }
        }
        #pragma unroll
        for (int q=0;q<4;q++){
            int di=q>>1, dj=q&1;
            int h = 2*(i0+lr)+di, w = 2*(j0+cp)+dj;
            float2 u0=upk(acc[q][0]), u1=upk(acc[q][1]);
            float4 o = make_float4(u0.x,u0.y,u1.x,u1.y);
            *(float4*)&out[(((size_t)(b*HF+h)*WF + w)<<8) + c] = o;
        }
    }
}

// ================= launch =================
extern "C" void kernel_launch(void* const* d_in, const int* in_sizes, int n_in,
                              void* d_out, int out_size)
{
    (void)in_sizes; (void)n_in; (void)out_size;
    const float* fine   = (const float*)d_in[0];
    const float* coarse = (const float*)d_in[1];
    const float* ln_f_g = (const float*)d_in[2];
    const float* ln_f_b = (const float*)d_in[3];
    const float* ln_c_g = (const float*)d_in[4];
    const float* ln_c_b = (const float*)d_in[5];
    const float* w_gate = (const float*)d_in[6];
    const float* b_gate = (const float*)d_in[7];
    const float* w_qf   = (const float*)d_in[8];
    const float* b_qf   = (const float*)d_in[9];
    const float* w_qc   = (const float*)d_in[10];
    const float* b_qc   = (const float*)d_in[11];
    const float* w_k    = (const float*)d_in[12];
    const float* b_k    = (const float*)d_in[13];
    const float* w_v    = (const float*)d_in[14];
    const float* b_v    = (const float*)d_in[15];
    float* out = (float*)d_out;

    ln_coarse_gate<<<NCOARSE, 128>>>(coarse, ln_c_g, ln_c_b, w_gate, b_gate);   // 1
    pack_w<<<CC, NP>>>(w_k, w_qc, w_v, b_k, b_qc, b_v);                          // 2
    fine_stats<<<NFINE/8, 256>>>(fine);                                          // 3
    cudaFuncSetAttribute(proj_gemm, cudaFuncAttributeMaxDynamicSharedMemorySize, PROJ_SMEM);
    proj_gemm<<<dim3(NP/128, NCOARSE/128), 256, PROJ_SMEM>>>();                  // 4  <- profiled slot
    fold_qf<<<EE, 256>>>(w_qf, b_qf, ln_f_g, ln_f_b);                            // 5
    query_gemm<<<NFINE/256, 256>>>(fine);                                        // 6
    cudaFuncSetAttribute(attn_kernel, cudaFuncAttributeMaxDynamicSharedMemorySize, ATT_SMEM_BYTES);
    attn_kernel<<<dim3(WC/16, HC/2, BB), 256, ATT_SMEM_BYTES>>>(out);            // 7
}

// round 12
// speedup vs baseline: 1.7020x; 1.0638x over previous
#include <cuda_runtime.h>
#include <cuda_bf16.h>
#include <cstdint>
#include <cstddef>

typedef unsigned long long ull;

__device__ __forceinline__ void ffma2(ull& d, ull a, ull b){
    asm("fma.rn.f32x2 %0, %1, %2, %0;" : "+l"(d) : "l"(a), "l"(b));
}
__device__ __forceinline__ ull pk2(float x, float y){
    ull r; asm("mov.b64 %0, {%1, %2};" : "=l"(r) : "f"(x), "f"(y)); return r;
}
__device__ __forceinline__ float2 upk(ull a){
    float2 r; asm("mov.b64 {%0, %1}, %2;" : "=f"(r.x), "=f"(r.y) : "l"(a)); return r;
}

#define LDSM4(r, addr) asm volatile( \
    "ldmatrix.sync.aligned.m8n8.x4.shared.b16 {%0,%1,%2,%3}, [%4];" \
    : "=r"((r)[0]),"=r"((r)[1]),"=r"((r)[2]),"=r"((r)[3]) : "r"(addr))

#define MMA16816(c, a, b) asm volatile( \
    "mma.sync.aligned.m16n8k16.row.col.f32.bf16.bf16.f32 " \
    "{%0,%1,%2,%3}, {%4,%5,%6,%7}, {%8,%9}, {%0,%1,%2,%3};" \
    : "+f"((c)[0]),"+f"((c)[1]),"+f"((c)[2]),"+f"((c)[3]) \
    : "r"((a)[0]),"r"((a)[1]),"r"((a)[2]),"r"((a)[3]), "r"((b)[0]),"r"((b)[1]))

#define CP16(dst, src) asm volatile( \
    "cp.async.cg.shared.global [%0], [%1], 16;" :: "r"(dst), "l"(src))

// ---------------- fixed shapes ----------------
#define BB 4
#define HF 128
#define WF 128
#define CF 256
#define HC 64
#define WC 64
#define CC 512
#define EE 64
#define FF 256
#define NP 384
#define NCOARSE (BB*HC*WC)   // 16384
#define NFINE   (BB*HF*WF)   // 65536

// ---------------- scratch ----------------
__device__ __nv_bfloat16 g_cnh[(size_t)NCOARSE*CC];
__device__ __nv_bfloat16 g_cnl[(size_t)NCOARSE*CC];
__device__ __nv_bfloat16 g_wth[(size_t)NP*CC];
__device__ __nv_bfloat16 g_wtl[(size_t)NP*CC];
__device__ __nv_bfloat16 g_fh[(size_t)NFINE*CF];   // fine hi  [m][k]
__device__ __nv_bfloat16 g_fl[(size_t)NFINE*CF];   // fine lo
__device__ __nv_bfloat16 g_wqh[(size_t)EE*CF];     // W' hi [n][k]
__device__ __nv_bfloat16 g_wql[(size_t)EE*CF];     // W' lo
__device__ float g_gate[NCOARSE];
__device__ float g_proj[(size_t)NCOARSE*NP];
__device__ float g_query[(size_t)NFINE*EE];
__device__ float g_mean[NFINE];
__device__ float g_rstd[NFINE];
__device__ float g_dvec[EE];
__device__ float g_cvec[EE];
__device__ float g_bcat[NP];

__device__ __forceinline__ void split4(float4 v, uint2& hi, uint2& lo){
    __nv_bfloat16 hx=__float2bfloat16_rn(v.x), hy=__float2bfloat16_rn(v.y);
    __nv_bfloat16 hz=__float2bfloat16_rn(v.z), hw=__float2bfloat16_rn(v.w);
    __nv_bfloat16 lx=__float2bfloat16_rn(v.x-__bfloat162float(hx));
    __nv_bfloat16 ly=__float2bfloat16_rn(v.y-__bfloat162float(hy));
    __nv_bfloat16 lz=__float2bfloat16_rn(v.z-__bfloat162float(hz));
    __nv_bfloat16 lw=__float2bfloat16_rn(v.w-__bfloat162float(hw));
    __nv_bfloat162 h01; h01.x=hx; h01.y=hy;
    __nv_bfloat162 h23; h23.x=hz; h23.y=hw;
    __nv_bfloat162 l01; l01.x=lx; l01.y=ly;
    __nv_bfloat162 l23; l23.x=lz; l23.y=lw;
    hi.x=*(unsigned*)&h01; hi.y=*(unsigned*)&h23;
    lo.x=*(unsigned*)&l01; lo.y=*(unsigned*)&l23;
}

// ================= kernel 1: LN(coarse) + gate, emit bf16 hi/lo =================
__global__ void __launch_bounds__(128) ln_coarse_gate(
    const float* __restrict__ x, const float* __restrict__ g, const float* __restrict__ b,
    const float* __restrict__ wg, const float* __restrict__ bg)
{
    int row = blockIdx.x; int t = threadIdx.x;
    const float4* xr = (const float4*)(x + (size_t)row*CC);
    float4 v = xr[t];
    float s  = v.x+v.y+v.z+v.w;
    float sq = v.x*v.x+v.y*v.y+v.z*v.z+v.w*v.w;
    #pragma unroll
    for (int o=16;o;o>>=1){ s += __shfl_xor_sync(0xffffffffu,s,o); sq += __shfl_xor_sync(0xffffffffu,sq,o); }
    __shared__ float red[8];
    int wid = t>>5, l = t&31;
    if (l==0){ red[wid]=s; red[4+wid]=sq; }
    __syncthreads();
    s  = red[0]+red[1]+red[2]+red[3];
    sq = red[4]+red[5]+red[6]+red[7];
    float mean = s*(1.f/512.f);
    float var  = sq*(1.f/512.f) - mean*mean;
    float rstd = rsqrtf(var + 1e-3f);
    float4 gv = ((const float4*)g)[t];
    float4 bv = ((const float4*)b)[t];
    float4 o;
    o.x = (v.x-mean)*rstd*gv.x + bv.x;
    o.y = (v.y-mean)*rstd*gv.y + bv.y;
    o.z = (v.z-mean)*rstd*gv.z + bv.z;
    o.w = (v.w-mean)*rstd*gv.w + bv.w;
    uint2 uh, ulo;
    split4(o, uh, ulo);
    size_t off = (size_t)row*CC + t*4;
    *(uint2*)&g_cnh[off] = uh;
    *(uint2*)&g_cnl[off] = ulo;

    float4 wv = ((const float4*)wg)[t];
    float gd = o.x*wv.x + o.y*wv.y + o.z*wv.z + o.w*wv.w;
    #pragma unroll
    for (int oo=16;oo;oo>>=1) gd += __shfl_xor_sync(0xffffffffu,gd,oo);
    __syncthreads();
    if (l==0) red[wid]=gd;
    __syncthreads();
    if (t==0){
        float tot = red[0]+red[1]+red[2]+red[3] + bg[0];
        g_gate[row] = 1.f/(1.f+__expf(-tot));
    }
}

// ================= kernel 2: fine LN stats + bf16 hi/lo emit =================
__global__ void __launch_bounds__(256) fine_stats(const float* __restrict__ x)
{
    int w = threadIdx.x>>5, l = threadIdx.x&31;
    int row = blockIdx.x*8 + w;
    const float4* xr = (const float4*)(x + (size_t)row*CF);
    float4 a = xr[l], c = xr[l+32];
    float s  = a.x+a.y+a.z+a.w + c.x+c.y+c.z+c.w;
    float sq = a.x*a.x+a.y*a.y+a.z*a.z+a.w*a.w + c.x*c.x+c.y*c.y+c.z*c.z+c.w*c.w;
    #pragma unroll
    for (int o=16;o;o>>=1){ s += __shfl_xor_sync(0xffffffffu,s,o); sq += __shfl_xor_sync(0xffffffffu,sq,o); }
    if (l==0){
        float m = s*(1.f/256.f);
        g_mean[row] = m;
        g_rstd[row] = rsqrtf(sq*(1.f/256.f) - m*m + 1e-3f);
    }
    uint2 ah, al, ch, cl;
    split4(a, ah, al);
    split4(c, ch, cl);
    size_t off = (size_t)row*CF + l*4;
    *(uint2*)&g_fh[off]       = ah;
    *(uint2*)&g_fl[off]       = al;
    *(uint2*)&g_fh[off + 128] = ch;
    *(uint2*)&g_fl[off + 128] = cl;
}

// ================= pack weights: W^T hi/lo bf16 + bias =================
__global__ void __launch_bounds__(384) pack_w(
    const float* __restrict__ wk, const float* __restrict__ wqc, const float* __restrict__ wv,
    const float* __restrict__ bk, const float* __restrict__ bqc, const float* __restrict__ bv)
{
    int k = blockIdx.x; int n = threadIdx.x;
    float v;
    if (n < 64)       v = wk [k*64  + n];
    else if (n < 128) v = wqc[k*64  + (n-64)];
    else              v = wv [k*256 + (n-128)];
    __nv_bfloat16 hi = __float2bfloat16_rn(v);
    __nv_bfloat16 lo = __float2bfloat16_rn(v - __bfloat162float(hi));
    g_wth[(size_t)n*CC + k] = hi;
    g_wtl[(size_t)n*CC + k] = lo;
    if (k == 0){
        float bvv = (n<64) ? bk[n] : (n<128) ? bqc[n-64] : bv[n-128];
        g_bcat[n] = bvv;
    }
}

// ================= fold LN(fine) params into w_qf (bf16 hi/lo [n][k]) =================
__global__ void __launch_bounds__(256) fold_qf(
    const float* __restrict__ wqf, const float* __restrict__ bqf,
    const float* __restrict__ g, const float* __restrict__ bb)
{
    int n = blockIdx.x; int t = threadIdx.x;
    float wv = wqf[t*EE + n];
    float wf = g[t]*wv;
    __nv_bfloat16 hi = __float2bfloat16_rn(wf);
    __nv_bfloat16 lo = __float2bfloat16_rn(wf - __bfloat162float(hi));
    g_wqh[(size_t)n*CF + t] = hi;
    g_wql[(size_t)n*CF + t] = lo;
    float cv = bb[t]*wv;
    float wfs = wf;
    #pragma unroll
    for (int o=16;o;o>>=1){ wfs += __shfl_xor_sync(0xffffffffu,wfs,o); cv += __shfl_xor_sync(0xffffffffu,cv,o); }
    __shared__ float sd[8], sc[8];
    int wid = t>>5, l = t&31;
    if (l==0){ sd[wid]=wfs; sc[wid]=cv; }
    __syncthreads();
    if (t==0){
        float dd=0.f, cc=0.f;
        #pragma unroll
        for (int i=0;i<8;i++){ dd+=sd[i]; cc+=sc[i]; }
        g_dvec[n]=dd; g_cvec[n]=cc + bqf[n];
    }
}

// ================= projection GEMM via mma.sync bf16 (hi/lo split), cp.async double-buffered =================
#define SROW 40
#define ARR 10240
#define PBUF 40960
#define PROJ_SMEM 81920
__global__ void __launch_bounds__(256,2) proj_gemm()
{
    extern __shared__ __align__(16) char smraw[];
    uint32_t sb = (uint32_t)__cvta_generic_to_shared(smraw);
    int t = threadIdx.x;
    int n0 = blockIdx.x*128, m0 = blockIdx.y*128;
    int w = t>>5, l = t&31;
    int wm = w>>1, wn = w&1;
    int m0w = wm*32, n0w = wn*64;

    int sr = t>>1, skh = (t&1)*16;
    const __nv_bfloat16* gAh = g_cnh + (size_t)(m0+sr)*CC + skh;
    const __nv_bfloat16* gAl = g_cnl + (size_t)(m0+sr)*CC + skh;
    const __nv_bfloat16* gBh = g_wth + (size_t)(n0+sr)*CC + skh;
    const __nv_bfloat16* gBl = g_wtl + (size_t)(n0+sr)*CC + skh;
    uint32_t doff = (uint32_t)(sr*SROW + skh)*2;

    float acc[2][8][4];
    #pragma unroll
    for (int mt=0;mt<2;mt++)
        #pragma unroll
        for (int nt=0;nt<8;nt++)
            #pragma unroll
            for (int i=0;i<4;i++) acc[mt][nt][i]=0.f;

    {
        uint32_t d = sb + doff;
        CP16(d,            gAh);    CP16(d+16,            gAh+8);
        CP16(d+ARR,        gAl);    CP16(d+ARR+16,        gAl+8);
        CP16(d+2*ARR,      gBh);    CP16(d+2*ARR+16,      gBh+8);
        CP16(d+3*ARR,      gBl);    CP16(d+3*ARR+16,      gBl+8);
        asm volatile("cp.async.commit_group;" ::: "memory");
    }

    for (int c=0; c<16; c++){
        asm volatile("cp.async.wait_group 0;" ::: "memory");
        __syncthreads();
        if (c+1<16){
            int s = (c+1)&1;
            uint32_t d = sb + s*PBUF + doff;
            int koff = (c+1)*32;
            CP16(d,            gAh+koff);    CP16(d+16,            gAh+koff+8);
            CP16(d+ARR,        gAl+koff);    CP16(d+ARR+16,        gAl+koff+8);
            CP16(d+2*ARR,      gBh+koff);    CP16(d+2*ARR+16,      gBh+koff+8);
            CP16(d+3*ARR,      gBl+koff);    CP16(d+3*ARR+16,      gBl+koff+8);
            asm volatile("cp.async.commit_group;" ::: "memory");
        }
        uint32_t bAh = sb + (c&1)*PBUF;
        uint32_t bAl = bAh + ARR;
        uint32_t bBh = bAh + 2*ARR;
        uint32_t bBl = bAh + 3*ARR;

        #pragma unroll
        for (int ks=0; ks<2; ks++){
            int k0 = ks*16;
            uint32_t aoff = ((m0w + (l&15))*SROW + k0 + (l>>4)*8)*2;
            uint32_t ah[2][4], al[2][4];
            LDSM4(ah[0], bAh + aoff);
            LDSM4(ah[1], bAh + aoff + 16*SROW*2);
            LDSM4(al[0], bAl + aoff);
            LDSM4(al[1], bAl + aoff + 16*SROW*2);
            uint32_t boff = ((n0w + (l>>4)*8 + (l&7))*SROW + k0 + ((l>>3)&1)*8)*2;
            uint32_t bh[8][2];
            #pragma unroll
            for (int np=0; np<4; np++){
                uint32_t r4[4];
                LDSM4(r4, bBh + boff + np*16*SROW*2);
                bh[np*2][0]=r4[0]; bh[np*2][1]=r4[1];
                bh[np*2+1][0]=r4[2]; bh[np*2+1][1]=r4[3];
            }
            #pragma unroll
            for (int mt=0; mt<2; mt++)
                #pragma unroll
                for (int nt=0; nt<8; nt++)
                    MMA16816(acc[mt][nt], ah[mt], bh[nt]);
            #pragma unroll
            for (int mt=0; mt<2; mt++)
                #pragma unroll
                for (int nt=0; nt<8; nt++)
                    MMA16816(acc[mt][nt], al[mt], bh[nt]);
            #pragma unroll
            for (int np=0; np<4; np++){
                uint32_t r4[4];
                LDSM4(r4, bBl + boff + np*16*SROW*2);
                bh[np*2][0]=r4[0]; bh[np*2][1]=r4[1];
                bh[np*2+1][0]=r4[2]; bh[np*2+1][1]=r4[3];
            }
            #pragma unroll
            for (int mt=0; mt<2; mt++)
                #pragma unroll
                for (int nt=0; nt<8; nt++)
                    MMA16816(acc[mt][nt], ah[mt], bh[nt]);
        }
        __syncthreads();
    }

    int g = l>>2, q = l&3;
    #pragma unroll
    for (int mt=0; mt<2; mt++){
        int row0 = m0 + m0w + mt*16 + g;
        #pragma unroll
        for (int nt=0; nt<8; nt++){
            int col = n0 + n0w + nt*8 + q*2;
            float2 b2 = *(const float2*)&g_bcat[col];
            *(float2*)&g_proj[(size_t)row0*NP + col] =
                make_float2(acc[mt][nt][0]+b2.x, acc[mt][nt][1]+b2.y);
            *(float2*)&g_proj[(size_t)(row0+8)*NP + col] =
                make_float2(acc[mt][nt][2]+b2.x, acc[mt][nt][3]+b2.y);
        }
    }
}

// ================= query GEMM via mma.sync (hi/lo) + folded LN + gate blend =================
// BM=128 BN=64 BK=32; 8 warps (4m x 2n), warp tile m32 x n32.
// Per buffer: Ah 10240 | Al 10240 | Bh 5120 | Bl 5120 = 30720B; x2 = 61440B dynamic.
#define QROW 40
#define QAH 0
#define QAL 10240
#define QBH 20480
#define QBL 25600
#define QBUF 30720
#define QUERY_SMEM 61440
__global__ void __launch_bounds__(256,2) query_gemm()
{
    extern __shared__ __align__(16) char smq[];
    uint32_t sb = (uint32_t)__cvta_generic_to_shared(smq);
    int t = threadIdx.x;
    int m0 = blockIdx.x*128;
    int w = t>>5, l = t&31;
    int wm = w>>1, wn = w&1;
    int m0w = wm*32, n0w = wn*32;

    // A staging: 128 rows, 2 thr/row, 16 elems each
    int sr = t>>1, skh = (t&1)*16;
    const __nv_bfloat16* gAh = g_fh + (size_t)(m0+sr)*CF + skh;
    const __nv_bfloat16* gAl = g_fl + (size_t)(m0+sr)*CF + skh;
    uint32_t doffA = (uint32_t)(sr*QROW + skh)*2;
    // B staging: 64 rows, 4 thr/row, 8 elems each
    int sbr = t>>2, sq8 = (t&3)*8;
    const __nv_bfloat16* gBh = g_wqh + (size_t)sbr*CF + sq8;
    const __nv_bfloat16* gBl = g_wql + (size_t)sbr*CF + sq8;
    uint32_t doffB = (uint32_t)(sbr*QROW + sq8)*2;

    float acc[2][4][4];
    #pragma unroll
    for (int mt=0;mt<2;mt++)
        #pragma unroll
        for (int nt=0;nt<4;nt++)
            #pragma unroll
            for (int i=0;i<4;i++) acc[mt][nt][i]=0.f;

    {
        uint32_t dA = sb + doffA, dB = sb + doffB;
        CP16(dA+QAH, gAh);  CP16(dA+QAH+16, gAh+8);
        CP16(dA+QAL, gAl);  CP16(dA+QAL+16, gAl+8);
        CP16(dB+QBH, gBh);
        CP16(dB+QBL, gBl);
        asm volatile("cp.async.commit_group;" ::: "memory");
    }

    const int KB = CF/32;  // 8
    for (int c=0; c<KB; c++){
        asm volatile("cp.async.wait_group 0;" ::: "memory");
        __syncthreads();
        if (c+1<KB){
            int s = (c+1)&1;
            uint32_t dA = sb + s*QBUF + doffA, dB = sb + s*QBUF + doffB;
            int koff = (c+1)*32;
            CP16(dA+QAH, gAh+koff);  CP16(dA+QAH+16, gAh+koff+8);
            CP16(dA+QAL, gAl+koff);  CP16(dA+QAL+16, gAl+koff+8);
            CP16(dB+QBH, gBh+koff);
            CP16(dB+QBL, gBl+koff);
            asm volatile("cp.async.commit_group;" ::: "memory");
        }
        uint32_t bAh = sb + (c&1)*QBUF + QAH;
        uint32_t bAl = sb + (c&1)*QBUF + QAL;
        uint32_t bBh = sb + (c&1)*QBUF + QBH;
        uint32_t bBl = sb + (c&1)*QBUF + QBL;

        #pragma unroll
        for (int ks=0; ks<2; ks++){
            int k0 = ks*16;
            uint32_t aoff = ((m0w + (l&15))*QROW + k0 + (l>>4)*8)*2;
            uint32_t ah[2][4], al[2][4];
            LDSM4(ah[0], bAh + aoff);
            LDSM4(ah[1], bAh + aoff + 16*QROW*2);
            LDSM4(al[0], bAl + aoff);
            LDSM4(al[1], bAl + aoff + 16*QROW*2);
            uint32_t boff = ((n0w + (l>>4)*8 + (l&7))*QROW + k0 + ((l>>3)&1)*8)*2;
            uint32_t bh[4][2];
            #pragma unroll
            for (int np=0; np<2; np++){
                uint32_t r4[4];
                LDSM4(r4, bBh + boff + np*16*QROW*2);
                bh[np*2][0]=r4[0]; bh[np*2][1]=r4[1];
                bh[np*2+1][0]=r4[2]; bh[np*2+1][1]=r4[3];
            }
            #pragma unroll
            for (int mt=0; mt<2; mt++)
                #pragma unroll
                for (int nt=0; nt<4; nt++)
                    MMA16816(acc[mt][nt], ah[mt], bh[nt]);
            #pragma unroll
            for (int mt=0; mt<2; mt++)
                #pragma unroll
                for (int nt=0; nt<4; nt++)
                    MMA16816(acc[mt][nt], al[mt], bh[nt]);
            #pragma unroll
            for (int np=0; np<2; np++){
                uint32_t r4[4];
                LDSM4(r4, bBl + boff + np*16*QROW*2);
                bh[np*2][0]=r4[0]; bh[np*2][1]=r4[1];
                bh[np*2+1][0]=r4[2]; bh[np*2+1][1]=r4[3];
            }
            #pragma unroll
            for (int mt=0; mt<2; mt++)
                #pragma unroll
                for (int nt=0; nt<4; nt++)
                    MMA16816(acc[mt][nt], ah[mt], bh[nt]);
        }
        __syncthreads();
    }

    // epilogue: folded LN + gate blend
    int g = l>>2, q = l&3;
    #pragma unroll
    for (int mt=0; mt<2; mt++){
        #pragma unroll
        for (int rr=0; rr<2; rr++){
            int m = m0 + m0w + mt*16 + rr*8 + g;
            float mean = g_mean[m], rstd = g_rstd[m];
            int b_ = m>>14, h = (m>>7)&127, wI = m&127;
            int mc = (b_<<12) | ((h>>1)<<6) | (wI>>1);
            float gt = g_gate[mc];
            #pragma unroll
            for (int nt=0; nt<4; nt++){
                int col = n0w + nt*8 + q*2;
                float ux = acc[mt][nt][rr*2+0];
                float uy = acc[mt][nt][rr*2+1];
                float2 dv = *(const float2*)&g_dvec[col];
                float2 cv = *(const float2*)&g_cvec[col];
                float2 qc = *(const float2*)&g_proj[(size_t)mc*NP + 64 + col];
                float2 qv, o;
                qv.x = rstd*(ux - mean*dv.x) + cv.x;
                qv.y = rstd*(uy - mean*dv.y) + cv.y;
                o.x = qv.x*gt + qc.x*(1.f-gt);
                o.y = qv.y*gt + qc.y*(1.f-gt);
                *(float2*)&g_query[(size_t)m*EE + col] = o;
            }
        }
    }
}

// ================= local attention: 16x2 coarse tile (halo 20x6) =================
#define SK_STRIDE 68
#define ATT_SMEM_BYTES ((8160 + 30720 + 8192 + 3584) * 4)
__global__ void __launch_bounds__(256) attn_kernel(float* __restrict__ out)
{
    extern __shared__ __align__(16) float sm[];
    float* sk = sm;                       // [6][20][68]
    float* sv = sm + 8160;                // [6][20][256]
    float* sq = sm + 8160 + 30720;        // [128][64]
    float* satt = sq + 8192;              // [128][28]

    int j0 = blockIdx.x * 16;
    int i0 = blockIdx.y * 2;
    int b  = blockIdx.z;
    int t = threadIdx.x;

    for (int idx = t; idx < 1920; idx += 256){
        int c4 = idx & 15, cc = (idx>>4) % 20, r = idx/320;
        int ci = i0 - 2 + r, cj = j0 - 2 + cc;
        float4 v = make_float4(0.f,0.f,0.f,0.f);
        if (ci>=0 && ci<HC && cj>=0 && cj<WC)
            v = *(const float4*)&g_proj[(size_t)((b*HC+ci)*WC + cj)*NP + c4*4];
        *(float4*)&sk[(r*20+cc)*SK_STRIDE + c4*4] = v;
    }
    for (int idx = t; idx < 7680; idx += 256){
        int c4 = idx & 63, cc = (idx>>6) % 20, r = idx/1280;
        int ci = i0 - 2 + r, cj = j0 - 2 + cc;
        float4 v = make_float4(0.f,0.f,0.f,0.f);
        if (ci>=0 && ci<HC && cj>=0 && cj<WC)
            v = *(const float4*)&g_proj[(size_t)((b*HC+ci)*WC + cj)*NP + 128 + c4*4];
        *(float4*)&sv[(r*20+cc)*256 + c4*4] = v;
    }
    for (int idx = t; idx < 2048; idx += 256){
        int c4 = idx & 15, fp = idx >> 4;
        int lr = fp>>6, rem = fp&63, cp = rem>>2, q = rem&3, di = q>>1, dj = q&1;
        int h = 2*(i0+lr) + di, w = 2*(j0+cp) + dj;
        *(float4*)&sq[fp*64 + c4*4] =
            *(const float4*)&g_query[(((size_t)(b*HF+h)*WF + w)<<6) + c4*4];
    }
    __syncthreads();

    int wd = t>>5, l = t&31;
    int pr = l/5, pc = l - pr*5;
    for (int fi=0; fi<16; fi++){
        int fp = wd*16 + fi;
        int lr = fp>>6, cp = (fp>>2)&15;
        float s = -1e30f;
        if (l < 25){
            s = 0.f;
            const float* kk = &sk[((lr+pr)*20 + cp + pc)*SK_STRIDE];
            const float* qq = &sq[fp*64];
            #pragma unroll
            for (int c4=0;c4<16;c4++){
                float4 qa = *(const float4*)(qq + c4*4);
                float4 ka = *(const float4*)(kk + c4*4);
                s += qa.x*ka.x + qa.y*ka.y + qa.z*ka.z + qa.w*ka.w;
            }
        }
        float mx = s;
        #pragma unroll
        for (int o=16;o;o>>=1) mx = fmaxf(mx, __shfl_xor_sync(0xffffffffu,mx,o));
        float e = (l<25) ? __expf(s - mx) : 0.f;
        float ssum = e;
        #pragma unroll
        for (int o=16;o;o>>=1) ssum += __shfl_xor_sync(0xffffffffu,ssum,o);
        if (l<25) satt[fp*28 + l] = e / ssum;
    }
    __syncthreads();

    int cpl = t>>3, l8 = t&7;
    int lr = cpl>>4, cp = cpl&15;
    for (int cg=0; cg<8; cg++){
        int c = cg*32 + l8*4;
        ull acc[4][2];
        #pragma unroll
        for (int q=0;q<4;q++){ acc[q][0]=pk2(0.f,0.f); acc[q][1]=pk2(0.f,0.f); }
        #pragma unroll
        for (int p=0;p<25;p++){
            int ppr = p/5, ppc = p - ppr*5;
            const ull* vp = (const ull*)&sv[((lr+ppr)*20 + cp + ppc)*256 + c];
            ull v01 = vp[0], v23 = vp[1];
            #pragma unroll
            for (int q=0;q<4;q++){
                float a = satt[(lr*64 + cp*4 + q)*28 + p];
                ull aP = pk2(a,a);
                ffma2(acc[q][0], aP, v01);
                ffma2(acc[q][1], aP, v23);
            }
        }
        #pragma unroll
        for (int q=0;q<4;q++){
            int di=q>>1, dj=q&1;
            int h = 2*(i0+lr)+di, w = 2*(j0+cp)+dj;
            float2 u0=upk(acc[q][0]), u1=upk(acc[q][1]);
            float4 o = make_float4(u0.x,u0.y,u1.x,u1.y);
            *(float4*)&out[(((size_t)(b*HF+h)*WF + w)<<8) + c] = o;
        }
    }
}

// ================= launch =================
extern "C" void kernel_launch(void* const* d_in, const int* in_sizes, int n_in,
                              void* d_out, int out_size)
{
    (void)in_sizes; (void)n_in; (void)out_size;
    const float* fine   = (const float*)d_in[0];
    const float* coarse = (const float*)d_in[1];
    const float* ln_f_g = (const float*)d_in[2];
    const float* ln_f_b = (const float*)d_in[3];
    const float* ln_c_g = (const float*)d_in[4];
    const float* ln_c_b = (const float*)d_in[5];
    const float* w_gate = (const float*)d_in[6];
    const float* b_gate = (const float*)d_in[7];
    const float* w_qf   = (const float*)d_in[8];
    const float* b_qf   = (const float*)d_in[9];
    const float* w_qc   = (const float*)d_in[10];
    const float* b_qc   = (const float*)d_in[11];
    const float* w_k    = (const float*)d_in[12];
    const float* b_k    = (const float*)d_in[13];
    const float* w_v    = (const float*)d_in[14];
    const float* b_v    = (const float*)d_in[15];
    float* out = (float*)d_out;

    ln_coarse_gate<<<NCOARSE, 128>>>(coarse, ln_c_g, ln_c_b, w_gate, b_gate);   // 1
    pack_w<<<CC, NP>>>(w_k, w_qc, w_v, b_k, b_qc, b_v);                          // 2
    fine_stats<<<NFINE/8, 256>>>(fine);                                          // 3
    cudaFuncSetAttribute(proj_gemm, cudaFuncAttributeMaxDynamicSharedMemorySize, PROJ_SMEM);
    proj_gemm<<<dim3(NP/128, NCOARSE/128), 256, PROJ_SMEM>>>();                  // 4  <- profiled slot
    fold_qf<<<EE, 256>>>(w_qf, b_qf, ln_f_g, ln_f_b);                            // 5
    cudaFuncSetAttribute(query_gemm, cudaFuncAttributeMaxDynamicSharedMemorySize, QUERY_SMEM);
    query_gemm<<<NFINE/128, 256, QUERY_SMEM>>>();                                // 6
    cudaFuncSetAttribute(attn_kernel, cudaFuncAttributeMaxDynamicSharedMemorySize, ATT_SMEM_BYTES);
    attn_kernel<<<dim3(WC/16, HC/2, BB), 256, ATT_SMEM_BYTES>>>(out);            // 7
}